// round 2
// baseline (speedup 1.0000x reference)
#include <cuda_runtime.h>
#include <math.h>

#define NNDIM 512
#define DDIM  128
#define MROWS (NNDIM*NNDIM)   // 262144 rows of (i,j)

// Scratch (device globals; allocation is forbidden). All stored [c][row], c-major.
__device__ float g_left [(size_t)DDIM*MROWS];
__device__ float g_right[(size_t)DDIM*MROWS];
__device__ float g_gate [(size_t)DDIM*MROWS];
__device__ float g_p    [(size_t)DDIM*MROWS];

__device__ __forceinline__ float sigmoidf_(float x) { return 1.0f / (1.0f + expf(-x)); }

// ---------------------------------------------------------------------------
// Kernel 1: LN1 + projections + gating.
// grid (2048 row-tiles, 6 col-tiles of 64), block 256.
// col-tiles 0..3 -> left/right (dual GEMM vs W_lr & W_gate), 4..5 -> g (W_og).
// Outputs written transposed: left/right/g as [c][row].
// ---------------------------------------------------------------------------
extern "C" __global__ void __launch_bounds__(256)
proj_kernel(const float* __restrict__ Z, const float* __restrict__ mask,
            const float* __restrict__ g1v, const float* __restrict__ b1v,
            const float* __restrict__ Wlr, const float* __restrict__ blr,
            const float* __restrict__ Wg,  const float* __restrict__ bg,
            const float* __restrict__ Wog, const float* __restrict__ bog)
{
    extern __shared__ float sm[];
    float* As  = sm;                 // [128 c][129] normalized Z, transposed
    float* Bs1 = As  + 128*129;      // [128 k][64]
    float* Bs2 = Bs1 + 128*64;       // [128 k][64]
    float* mus = Bs2 + 128*64;       // 128
    float* rss = mus + 128;          // 128
    float* msk = rss + 128;          // 128
    float* g1s = msk + 128;          // 128
    float* b1s = g1s + 128;          // 128
    float* Cs  = Bs1;                // reuse for epilogue staging [64 oc][129]

    const int t     = threadIdx.x;
    const int rbase = blockIdx.x * 128;
    const int ct    = blockIdx.y;     // 0..5
    const bool dual = (ct < 4);

    // Load Z tile transposed into smem (coalesced gmem, conflict-free smem)
    for (int idx = t; idx < 128*128; idx += 256) {
        int r = idx >> 7, c = idx & 127;
        As[c*129 + r] = Z[(size_t)(rbase + r)*128 + c];
    }
    if (t < 128) { msk[t] = mask[rbase + t]; g1s[t] = g1v[t]; b1s[t] = b1v[t]; }

    // Load weight column tiles (full K=128 in smem)
    if (dual) {
        int cb = ct * 64;
        for (int idx = t; idx < 128*64; idx += 256) {
            int k = idx >> 6, oc = idx & 63;
            Bs1[k*64 + oc] = Wlr[k*256 + cb + oc];
            Bs2[k*64 + oc] = Wg [k*256 + cb + oc];
        }
    } else {
        int cb = (ct - 4) * 64;
        for (int idx = t; idx < 128*64; idx += 256) {
            int k = idx >> 6, oc = idx & 63;
            Bs1[k*64 + oc] = Wog[k*128 + cb + oc];
        }
    }
    __syncthreads();

    // LayerNorm stats: 2 threads per row
    {
        int r = t >> 1, h = t & 1;
        float s = 0.f, s2 = 0.f;
        #pragma unroll 8
        for (int c = h*64; c < h*64 + 64; ++c) {
            float v = As[c*129 + r];
            s += v; s2 += v*v;
        }
        s  += __shfl_xor_sync(0xffffffffu, s,  1);
        s2 += __shfl_xor_sync(0xffffffffu, s2, 1);
        if (h == 0) {
            float mu  = s * (1.f/128.f);
            float var = s2 * (1.f/128.f) - mu*mu;
            mus[r] = mu;
            rss[r] = rsqrtf(var + 1e-5f);
        }
    }
    __syncthreads();
    // Normalize in place
    for (int idx = t; idx < 128*128; idx += 256) {
        int r = idx >> 7, c = idx & 127;
        float v = As[c*129 + r];
        As[c*129 + r] = (v - mus[r]) * rss[r] * g1s[c] + b1s[c];
    }
    __syncthreads();

    // GEMM: 128 rows x 64 cols, thread = 8 rows x 4 cols (x2 matrices if dual)
    const int tr = t & 15;    // row group: r = tr + 16*ii
    const int tc = t >> 4;    // col group: oc = tc*4 + jj
    float acc1[8][4], acc2[8][4];
    #pragma unroll
    for (int ii = 0; ii < 8; ++ii)
        #pragma unroll
        for (int jj = 0; jj < 4; ++jj) { acc1[ii][jj] = 0.f; acc2[ii][jj] = 0.f; }

    if (dual) {
        #pragma unroll 4
        for (int k = 0; k < 128; ++k) {
            float a[8], b1[4], b2[4];
            #pragma unroll
            for (int ii = 0; ii < 8; ++ii) a[ii] = As[k*129 + tr + 16*ii];
            #pragma unroll
            for (int jj = 0; jj < 4; ++jj) { b1[jj] = Bs1[k*64 + tc*4 + jj]; b2[jj] = Bs2[k*64 + tc*4 + jj]; }
            #pragma unroll
            for (int ii = 0; ii < 8; ++ii)
                #pragma unroll
                for (int jj = 0; jj < 4; ++jj) {
                    acc1[ii][jj] += a[ii]*b1[jj];
                    acc2[ii][jj] += a[ii]*b2[jj];
                }
        }
    } else {
        #pragma unroll 4
        for (int k = 0; k < 128; ++k) {
            float a[8], b1[4];
            #pragma unroll
            for (int ii = 0; ii < 8; ++ii) a[ii] = As[k*129 + tr + 16*ii];
            #pragma unroll
            for (int jj = 0; jj < 4; ++jj) b1[jj] = Bs1[k*64 + tc*4 + jj];
            #pragma unroll
            for (int ii = 0; ii < 8; ++ii)
                #pragma unroll
                for (int jj = 0; jj < 4; ++jj)
                    acc1[ii][jj] += a[ii]*b1[jj];
        }
    }

    __syncthreads();   // done reading Bs; safe to reuse as staging

    const int ocbase = ct * 64;
    #pragma unroll
    for (int ii = 0; ii < 8; ++ii) {
        int r = tr + 16*ii;
        float mv = msk[r];
        #pragma unroll
        for (int jj = 0; jj < 4; ++jj) {
            int oc  = tc*4 + jj;
            int ocg = ocbase + oc;
            float v;
            if (dual) {
                float lrv = acc1[ii][jj] + __ldg(&blr[ocg]);
                float gtv = acc2[ii][jj] + __ldg(&bg[ocg]);
                v = lrv * mv * sigmoidf_(gtv);
            } else {
                v = sigmoidf_(acc1[ii][jj] + __ldg(&bog[ocg - 256]));
            }
            Cs[oc*129 + r] = v;
        }
    }
    __syncthreads();

    for (int idx = t; idx < 64*128; idx += 256) {
        int oc = idx >> 7, r = idx & 127;
        int ocg = ocbase + oc;
        float* dst = (ocg < 128) ? g_left : (ocg < 256 ? g_right : g_gate);
        int c = ocg & 127;
        dst[(size_t)c*MROWS + rbase + r] = Cs[oc*129 + r];
    }
}

// ---------------------------------------------------------------------------
// Kernel 2: p[c] = L_c @ R_c^T, 128 independent 512x512x512 NT SGEMMs.
// grid (jt=4, it=4, c=128), block 256, tile 128x128, BK=8, micro 8x8.
// ---------------------------------------------------------------------------
extern "C" __global__ void __launch_bounds__(256, 2)
einsum_kernel()
{
    __shared__ float As[8][128];
    __shared__ float Bs[8][128];

    const int t     = threadIdx.x;
    const int jbase = blockIdx.x * 128;
    const int ibase = blockIdx.y * 128;
    const int c     = blockIdx.z;

    const float* A = g_left  + (size_t)c*MROWS;   // [i][k] row-major 512x512
    const float* B = g_right + (size_t)c*MROWS;   // [j][k] row-major 512x512

    const int tx = t & 15;     // j = jbase + tx + 16*jj
    const int ty = t >> 4;     // i = ibase + ty*8 + ii
    const int lr_ = t >> 1;    // load row 0..127
    const int lh  = (t & 1) * 4;

    float acc[8][8];
    #pragma unroll
    for (int ii = 0; ii < 8; ++ii)
        #pragma unroll
        for (int jj = 0; jj < 8; ++jj) acc[ii][jj] = 0.f;

    for (int k0 = 0; k0 < 512; k0 += 8) {
        float4 av = *(const float4*)&A[(size_t)(ibase + lr_)*512 + k0 + lh];
        float4 bv = *(const float4*)&B[(size_t)(jbase + lr_)*512 + k0 + lh];
        __syncthreads();
        As[lh+0][lr_] = av.x; As[lh+1][lr_] = av.y; As[lh+2][lr_] = av.z; As[lh+3][lr_] = av.w;
        Bs[lh+0][lr_] = bv.x; Bs[lh+1][lr_] = bv.y; Bs[lh+2][lr_] = bv.z; Bs[lh+3][lr_] = bv.w;
        __syncthreads();
        #pragma unroll
        for (int k = 0; k < 8; ++k) {
            float a[8], b[8];
            #pragma unroll
            for (int ii = 0; ii < 8; ++ii) a[ii] = As[k][ty*8 + ii];
            #pragma unroll
            for (int jj = 0; jj < 8; ++jj) b[jj] = Bs[k][tx + 16*jj];
            #pragma unroll
            for (int ii = 0; ii < 8; ++ii)
                #pragma unroll
                for (int jj = 0; jj < 8; ++jj)
                    acc[ii][jj] += a[ii]*b[jj];
        }
    }

    float* P = g_p + (size_t)c*MROWS;
    #pragma unroll
    for (int ii = 0; ii < 8; ++ii) {
        int irow = ibase + ty*8 + ii;
        #pragma unroll
        for (int jj = 0; jj < 8; ++jj)
            P[(size_t)irow*512 + jbase + tx + 16*jj] = acc[ii][jj];
    }
}

// ---------------------------------------------------------------------------
// Kernel 3: LN2 over c, ab = pln @ W_op, out = Z + g*(ab + out_bias).
// grid 2048 (128 rows each), block 256.
// ---------------------------------------------------------------------------
extern "C" __global__ void __launch_bounds__(256)
final_kernel(const float* __restrict__ Z,
             const float* __restrict__ g2v, const float* __restrict__ b2v,
             const float* __restrict__ Wop, const float* __restrict__ obias,
             float* __restrict__ out)
{
    extern __shared__ float sm[];
    float* Ps  = sm;              // [128 c][129] p tile; reused as [128 r][129] out stage
    float* Ws  = Ps  + 128*129;   // [128 c][128 d]
    float* mus = Ws  + 128*128;
    float* rss = mus + 128;
    float* g2s = rss + 128;
    float* b2s = g2s + 128;
    float* obs = b2s + 128;

    const int t     = threadIdx.x;
    const int rbase = blockIdx.x * 128;

    for (int idx = t; idx < 128*128; idx += 256) {
        int c = idx >> 7, r = idx & 127;
        Ps[c*129 + r] = g_p[(size_t)c*MROWS + rbase + r];
        Ws[idx] = Wop[idx];
    }
    if (t < 128) { g2s[t] = g2v[t]; b2s[t] = b2v[t]; obs[t] = obias[t]; }
    __syncthreads();

    // LN over c, 2 threads per r
    {
        int r = t >> 1, h = t & 1;
        float s = 0.f, s2 = 0.f;
        #pragma unroll 8
        for (int c = h*64; c < h*64 + 64; ++c) {
            float v = Ps[c*129 + r];
            s += v; s2 += v*v;
        }
        s  += __shfl_xor_sync(0xffffffffu, s,  1);
        s2 += __shfl_xor_sync(0xffffffffu, s2, 1);
        if (h == 0) {
            float mu  = s * (1.f/128.f);
            float var = s2 * (1.f/128.f) - mu*mu;
            mus[r] = mu;
            rss[r] = rsqrtf(var + 1e-5f);
        }
    }
    __syncthreads();
    for (int idx = t; idx < 128*128; idx += 256) {
        int r = idx & 127, c = idx >> 7;
        float v = Ps[c*129 + r];
        Ps[c*129 + r] = (v - mus[r]) * rss[r] * g2s[c] + b2s[c];
    }
    __syncthreads();

    // GEMM: ab[r][d] = sum_c pln[c][r] * Wop[c][d]
    const int tx = t & 15;    // r = tx + 16*ii
    const int ty = t >> 4;    // d = ty*8 + dd
    float acc[8][8];
    #pragma unroll
    for (int ii = 0; ii < 8; ++ii)
        #pragma unroll
        for (int dd = 0; dd < 8; ++dd) acc[ii][dd] = 0.f;

    #pragma unroll 2
    for (int c = 0; c < 128; ++c) {
        float a[8], b[8];
        #pragma unroll
        for (int ii = 0; ii < 8; ++ii) a[ii] = Ps[c*129 + tx + 16*ii];
        #pragma unroll
        for (int dd = 0; dd < 8; ++dd) b[dd] = Ws[c*128 + ty*8 + dd];
        #pragma unroll
        for (int ii = 0; ii < 8; ++ii)
            #pragma unroll
            for (int dd = 0; dd < 8; ++dd)
                acc[ii][dd] += a[ii]*b[dd];
    }
    __syncthreads();   // done reading Ps; reuse as output stage

    #pragma unroll
    for (int ii = 0; ii < 8; ++ii) {
        int r = tx + 16*ii;
        #pragma unroll
        for (int dd = 0; dd < 8; ++dd) {
            int d = ty*8 + dd;
            float gv = g_gate[(size_t)d*MROWS + rbase + r];
            Ps[r*129 + d] = gv * (acc[ii][dd] + obs[d]);
        }
    }
    __syncthreads();

    for (int idx = t; idx < 128*128; idx += 256) {
        int r = idx >> 7, d = idx & 127;
        size_t gi = (size_t)(rbase + r)*128 + d;
        out[gi] = Z[gi] + Ps[r*129 + d];
    }
}

// ---------------------------------------------------------------------------
extern "C" void kernel_launch(void* const* d_in, const int* in_sizes, int n_in,
                              void* d_out, int out_size)
{
    const float* Zr   = (const float*)d_in[0];
    const float* mask = (const float*)d_in[1];
    const float* g1   = (const float*)d_in[2];
    const float* b1   = (const float*)d_in[3];
    const float* Wlr  = (const float*)d_in[4];
    const float* blr  = (const float*)d_in[5];
    const float* Wg   = (const float*)d_in[6];
    const float* bg   = (const float*)d_in[7];
    const float* Wog  = (const float*)d_in[8];
    const float* bog  = (const float*)d_in[9];
    const float* g2   = (const float*)d_in[10];
    const float* b2   = (const float*)d_in[11];
    const float* Wop  = (const float*)d_in[12];
    const float* ob   = (const float*)d_in[13];
    float* out = (float*)d_out;

    const size_t sm1 = (size_t)(128*129 + 2*128*64 + 5*128) * sizeof(float);  // ~134 KB
    const size_t sm3 = (size_t)(128*129 + 128*128 + 5*128) * sizeof(float);   // ~134 KB
    cudaFuncSetAttribute(proj_kernel,  cudaFuncAttributeMaxDynamicSharedMemorySize, (int)sm1);
    cudaFuncSetAttribute(final_kernel, cudaFuncAttributeMaxDynamicSharedMemorySize, (int)sm3);

    proj_kernel<<<dim3(2048, 6), 256, sm1>>>(Zr, mask, g1, b1, Wlr, blr, Wg, bg, Wog, bog);
    einsum_kernel<<<dim3(4, 4, 128), 256>>>();
    final_kernel<<<2048, 256, sm3>>>(Zr, g2, b2, Wop, ob, out);
}

// round 3
// speedup vs baseline: 2.1143x; 2.1143x over previous
#include <cuda_runtime.h>
#include <math.h>

#define NNDIM 512
#define DDIM  128
#define MROWS (NNDIM*NNDIM)   // 262144 rows of (i,j)

// Scratch (device globals). left/right/gate stored [c][row] c-major; p stored per-c [i][j].
__device__ float g_left [(size_t)DDIM*MROWS];
__device__ float g_right[(size_t)DDIM*MROWS];
__device__ float g_gate [(size_t)DDIM*MROWS];
__device__ float g_p    [(size_t)DDIM*MROWS];

__device__ __forceinline__ float sigmoidf_(float x) { return 1.0f / (1.0f + expf(-x)); }

__device__ __forceinline__ unsigned f2tf32(float x) {
    unsigned r; asm("cvt.rna.tf32.f32 %0, %1;" : "=r"(r) : "f"(x)); return r;
}

__device__ __forceinline__ void mma_tf32(float c[4],
    unsigned a0, unsigned a1, unsigned a2, unsigned a3, unsigned b0, unsigned b1)
{
    asm volatile(
        "mma.sync.aligned.m16n8k8.row.col.f32.tf32.tf32.f32 "
        "{%0,%1,%2,%3}, {%4,%5,%6,%7}, {%8,%9}, {%0,%1,%2,%3};"
        : "+f"(c[0]), "+f"(c[1]), "+f"(c[2]), "+f"(c[3])
        : "r"(a0), "r"(a1), "r"(a2), "r"(a3), "r"(b0), "r"(b1));
}

// ---------------------------------------------------------------------------
// Kernel 1: LN1 + projections + gating. 64-row tiles for 2 blocks/SM.
// grid (4096 row-tiles, 6 col-tiles of 64), block 256.
// Outputs written transposed: left/right/g as [c][row].
// ---------------------------------------------------------------------------
extern "C" __global__ void __launch_bounds__(256)
proj_kernel(const float* __restrict__ Z, const float* __restrict__ mask,
            const float* __restrict__ g1v, const float* __restrict__ b1v,
            const float* __restrict__ Wlr, const float* __restrict__ blr,
            const float* __restrict__ Wg,  const float* __restrict__ bg,
            const float* __restrict__ Wog, const float* __restrict__ bog)
{
    extern __shared__ float sm[];
    float* As  = sm;                 // [128 c][65] normalized Z, transposed (ld 65)
    float* Bs1 = As  + 128*65;       // [128 k][64]
    float* Bs2 = Bs1 + 128*64;       // [128 k][64]
    float* mus = Bs2 + 128*64;       // 64
    float* rss = mus + 64;           // 64
    float* msk = rss + 64;           // 64
    float* g1s = msk + 64;           // 128
    float* b1s = g1s + 128;          // 128
    float* Cs  = Bs1;                // reuse for epilogue staging [64 oc][64 r]

    const int t     = threadIdx.x;
    const int rbase = blockIdx.x * 64;
    const int ct    = blockIdx.y;     // 0..5
    const bool dual = (ct < 4);

    // Load Z tile transposed into smem
    for (int idx = t; idx < 64*128; idx += 256) {
        int r = idx >> 7, c = idx & 127;
        As[c*65 + r] = Z[(size_t)(rbase + r)*128 + c];
    }
    if (t < 64)  msk[t] = mask[rbase + t];
    if (t < 128) { g1s[t] = g1v[t]; b1s[t] = b1v[t]; }

    // Load weight column tiles (full K=128 in smem)
    if (dual) {
        int cb = ct * 64;
        for (int idx = t; idx < 128*64; idx += 256) {
            int k = idx >> 6, oc = idx & 63;
            Bs1[k*64 + oc] = Wlr[k*256 + cb + oc];
            Bs2[k*64 + oc] = Wg [k*256 + cb + oc];
        }
    } else {
        int cb = (ct - 4) * 64;
        for (int idx = t; idx < 128*64; idx += 256) {
            int k = idx >> 6, oc = idx & 63;
            Bs1[k*64 + oc] = Wog[k*128 + cb + oc];
        }
    }
    __syncthreads();

    // LayerNorm stats: 4 threads per row
    {
        int r = t >> 2, h = t & 3;
        float s = 0.f, s2 = 0.f;
        #pragma unroll 8
        for (int c = h*32; c < h*32 + 32; ++c) {
            float v = As[c*65 + r];
            s += v; s2 += v*v;
        }
        s  += __shfl_xor_sync(0xffffffffu, s,  1);
        s2 += __shfl_xor_sync(0xffffffffu, s2, 1);
        s  += __shfl_xor_sync(0xffffffffu, s,  2);
        s2 += __shfl_xor_sync(0xffffffffu, s2, 2);
        if (h == 0) {
            float mu  = s * (1.f/128.f);
            float var = s2 * (1.f/128.f) - mu*mu;
            mus[r] = mu;
            rss[r] = rsqrtf(var + 1e-5f);
        }
    }
    __syncthreads();
    // Normalize in place
    for (int idx = t; idx < 64*128; idx += 256) {
        int r = idx & 63, c = idx >> 6;
        float v = As[c*65 + r];
        As[c*65 + r] = (v - mus[r]) * rss[r] * g1s[c] + b1s[c];
    }
    __syncthreads();

    // GEMM: 64 rows x 64 cols, thread = 4 rows x 4 cols (x2 matrices if dual)
    const int tr = t & 15;    // row group: r = tr + 16*ii
    const int tc = t >> 4;    // col group: oc = tc*4 + jj
    float acc1[4][4], acc2[4][4];
    #pragma unroll
    for (int ii = 0; ii < 4; ++ii)
        #pragma unroll
        for (int jj = 0; jj < 4; ++jj) { acc1[ii][jj] = 0.f; acc2[ii][jj] = 0.f; }

    if (dual) {
        #pragma unroll 4
        for (int k = 0; k < 128; ++k) {
            float a[4], b1[4], b2[4];
            #pragma unroll
            for (int ii = 0; ii < 4; ++ii) a[ii] = As[k*65 + tr + 16*ii];
            #pragma unroll
            for (int jj = 0; jj < 4; ++jj) { b1[jj] = Bs1[k*64 + tc*4 + jj]; b2[jj] = Bs2[k*64 + tc*4 + jj]; }
            #pragma unroll
            for (int ii = 0; ii < 4; ++ii)
                #pragma unroll
                for (int jj = 0; jj < 4; ++jj) {
                    acc1[ii][jj] += a[ii]*b1[jj];
                    acc2[ii][jj] += a[ii]*b2[jj];
                }
        }
    } else {
        #pragma unroll 4
        for (int k = 0; k < 128; ++k) {
            float a[4], b1[4];
            #pragma unroll
            for (int ii = 0; ii < 4; ++ii) a[ii] = As[k*65 + tr + 16*ii];
            #pragma unroll
            for (int jj = 0; jj < 4; ++jj) b1[jj] = Bs1[k*64 + tc*4 + jj];
            #pragma unroll
            for (int ii = 0; ii < 4; ++ii)
                #pragma unroll
                for (int jj = 0; jj < 4; ++jj)
                    acc1[ii][jj] += a[ii]*b1[jj];
        }
    }

    __syncthreads();   // done reading Bs; safe to reuse as staging

    const int ocbase = ct * 64;
    #pragma unroll
    for (int ii = 0; ii < 4; ++ii) {
        int r = tr + 16*ii;
        float mv = msk[r];
        #pragma unroll
        for (int jj = 0; jj < 4; ++jj) {
            int oc  = tc*4 + jj;
            int ocg = ocbase + oc;
            float v;
            if (dual) {
                float lrv = acc1[ii][jj] + __ldg(&blr[ocg]);
                float gtv = acc2[ii][jj] + __ldg(&bg[ocg]);
                v = lrv * mv * sigmoidf_(gtv);
            } else {
                v = sigmoidf_(acc1[ii][jj] + __ldg(&bog[ocg - 256]));
            }
            Cs[oc*64 + r] = v;
        }
    }
    __syncthreads();

    for (int idx = t; idx < 64*64; idx += 256) {
        int oc = idx >> 6, r = idx & 63;
        int ocg = ocbase + oc;
        float* dst = (ocg < 128) ? g_left : (ocg < 256 ? g_right : g_gate);
        int c = ocg & 127;
        dst[(size_t)c*MROWS + rbase + r] = Cs[oc*64 + r];
    }
}

// ---------------------------------------------------------------------------
// Kernel 2: p[c] = L_c @ R_c^T via tf32 mma.sync (tensor cores).
// grid (jt=4, it=4, c=128), block 256 (8 warps as 4x2), tile 128x128, BK=16.
// smem holds pre-converted tf32 bits, [k][row] layout ld=136 (conflict-free).
// ---------------------------------------------------------------------------
#define EK 16
extern "C" __global__ void __launch_bounds__(256, 2)
einsum_kernel()
{
    __shared__ unsigned As[2][EK][136];   // A: [k][i]
    __shared__ unsigned Bs[2][EK][136];   // B: [k][j]

    const int t     = threadIdx.x;
    const int lane  = t & 31;
    const int w     = t >> 5;
    const int wm    = w & 3;          // 4 warps along i
    const int wn    = w >> 2;         // 2 warps along j
    const int jbase = blockIdx.x * 128;
    const int ibase = blockIdx.y * 128;
    const int c     = blockIdx.z;

    const float* A = g_left  + (size_t)c*MROWS;   // [i][k] 512x512
    const float* B = g_right + (size_t)c*MROWS;   // [j][k] 512x512

    const int lrow = t >> 1;          // load row 0..127
    const int lkb  = (t & 1) * 8;     // k sub-offset 0 or 8

    const float* Ap = A + (size_t)(ibase + lrow)*512 + lkb;
    const float* Bp = B + (size_t)(jbase + lrow)*512 + lkb;

    const int tig  = lane & 3;        // thread in group (k / col idx)
    const int grp  = lane >> 2;       // group id (row / n idx)

    float acc[2][8][4];
    #pragma unroll
    for (int mt = 0; mt < 2; ++mt)
        #pragma unroll
        for (int nt = 0; nt < 8; ++nt)
            #pragma unroll
            for (int q = 0; q < 4; ++q) acc[mt][nt][q] = 0.f;

    // preload chunk 0
    float4 av0 = *(const float4*)(Ap + 0);
    float4 av1 = *(const float4*)(Ap + 4);
    float4 bv0 = *(const float4*)(Bp + 0);
    float4 bv1 = *(const float4*)(Bp + 4);

    int buf = 0;
    {
        As[0][lkb+0][lrow] = f2tf32(av0.x); As[0][lkb+1][lrow] = f2tf32(av0.y);
        As[0][lkb+2][lrow] = f2tf32(av0.z); As[0][lkb+3][lrow] = f2tf32(av0.w);
        As[0][lkb+4][lrow] = f2tf32(av1.x); As[0][lkb+5][lrow] = f2tf32(av1.y);
        As[0][lkb+6][lrow] = f2tf32(av1.z); As[0][lkb+7][lrow] = f2tf32(av1.w);
        Bs[0][lkb+0][lrow] = f2tf32(bv0.x); Bs[0][lkb+1][lrow] = f2tf32(bv0.y);
        Bs[0][lkb+2][lrow] = f2tf32(bv0.z); Bs[0][lkb+3][lrow] = f2tf32(bv0.w);
        Bs[0][lkb+4][lrow] = f2tf32(bv1.x); Bs[0][lkb+5][lrow] = f2tf32(bv1.y);
        Bs[0][lkb+6][lrow] = f2tf32(bv1.z); Bs[0][lkb+7][lrow] = f2tf32(bv1.w);
    }
    __syncthreads();

    for (int k0 = 0; k0 < 512; k0 += EK) {
        const bool more = (k0 + EK) < 512;
        if (more) {
            av0 = *(const float4*)(Ap + k0 + EK);
            av1 = *(const float4*)(Ap + k0 + EK + 4);
            bv0 = *(const float4*)(Bp + k0 + EK);
            bv1 = *(const float4*)(Bp + k0 + EK + 4);
        }

        #pragma unroll
        for (int kk = 0; kk < EK/8; ++kk) {
            unsigned af[2][4], bf[8][2];
            #pragma unroll
            for (int mt = 0; mt < 2; ++mt) {
                int arow = wm*32 + mt*16 + grp;
                af[mt][0] = As[buf][kk*8 + tig    ][arow    ];
                af[mt][1] = As[buf][kk*8 + tig    ][arow + 8];
                af[mt][2] = As[buf][kk*8 + tig + 4][arow    ];
                af[mt][3] = As[buf][kk*8 + tig + 4][arow + 8];
            }
            #pragma unroll
            for (int nt = 0; nt < 8; ++nt) {
                int bcol = wn*64 + nt*8 + grp;
                bf[nt][0] = Bs[buf][kk*8 + tig    ][bcol];
                bf[nt][1] = Bs[buf][kk*8 + tig + 4][bcol];
            }
            #pragma unroll
            for (int mt = 0; mt < 2; ++mt)
                #pragma unroll
                for (int nt = 0; nt < 8; ++nt)
                    mma_tf32(acc[mt][nt], af[mt][0], af[mt][1], af[mt][2], af[mt][3],
                             bf[nt][0], bf[nt][1]);
        }

        if (more) {
            int nb = buf ^ 1;
            As[nb][lkb+0][lrow] = f2tf32(av0.x); As[nb][lkb+1][lrow] = f2tf32(av0.y);
            As[nb][lkb+2][lrow] = f2tf32(av0.z); As[nb][lkb+3][lrow] = f2tf32(av0.w);
            As[nb][lkb+4][lrow] = f2tf32(av1.x); As[nb][lkb+5][lrow] = f2tf32(av1.y);
            As[nb][lkb+6][lrow] = f2tf32(av1.z); As[nb][lkb+7][lrow] = f2tf32(av1.w);
            Bs[nb][lkb+0][lrow] = f2tf32(bv0.x); Bs[nb][lkb+1][lrow] = f2tf32(bv0.y);
            Bs[nb][lkb+2][lrow] = f2tf32(bv0.z); Bs[nb][lkb+3][lrow] = f2tf32(bv0.w);
            Bs[nb][lkb+4][lrow] = f2tf32(bv1.x); Bs[nb][lkb+5][lrow] = f2tf32(bv1.y);
            Bs[nb][lkb+6][lrow] = f2tf32(bv1.z); Bs[nb][lkb+7][lrow] = f2tf32(bv1.w);
            __syncthreads();
            buf ^= 1;
        }
    }

    // Write P (per-c plane, [i][j])
    float* P = g_p + (size_t)c*MROWS;
    #pragma unroll
    for (int mt = 0; mt < 2; ++mt) {
        int i0 = ibase + wm*32 + mt*16 + grp;
        #pragma unroll
        for (int nt = 0; nt < 8; ++nt) {
            int j0 = jbase + wn*64 + nt*8 + tig*2;
            float2 v01 = make_float2(acc[mt][nt][0], acc[mt][nt][1]);
            float2 v23 = make_float2(acc[mt][nt][2], acc[mt][nt][3]);
            *(float2*)&P[(size_t)i0*512 + j0]       = v01;
            *(float2*)&P[(size_t)(i0+8)*512 + j0]   = v23;
        }
    }
}

// ---------------------------------------------------------------------------
// Kernel 3: LN2 over c, ab = pln @ W_op, out = Z + g*(ab + out_bias).
// grid 2048 (128 rows each), block 256.
// ---------------------------------------------------------------------------
extern "C" __global__ void __launch_bounds__(256)
final_kernel(const float* __restrict__ Z,
             const float* __restrict__ g2v, const float* __restrict__ b2v,
             const float* __restrict__ Wop, const float* __restrict__ obias,
             float* __restrict__ out)
{
    extern __shared__ float sm[];
    float* Ps  = sm;              // [128 c][129] p tile; reused as [128 r][129] out stage
    float* Ws  = Ps  + 128*129;   // [128 c][128 d]
    float* mus = Ws  + 128*128;
    float* rss = mus + 128;
    float* g2s = rss + 128;
    float* b2s = g2s + 128;
    float* obs = b2s + 128;

    const int t     = threadIdx.x;
    const int rbase = blockIdx.x * 128;

    for (int idx = t; idx < 128*128; idx += 256) {
        int c = idx >> 7, r = idx & 127;
        Ps[c*129 + r] = g_p[(size_t)c*MROWS + rbase + r];
        Ws[idx] = Wop[idx];
    }
    if (t < 128) { g2s[t] = g2v[t]; b2s[t] = b2v[t]; obs[t] = obias[t]; }
    __syncthreads();

    // LN over c, 2 threads per r
    {
        int r = t >> 1, h = t & 1;
        float s = 0.f, s2 = 0.f;
        #pragma unroll 8
        for (int c = h*64; c < h*64 + 64; ++c) {
            float v = Ps[c*129 + r];
            s += v; s2 += v*v;
        }
        s  += __shfl_xor_sync(0xffffffffu, s,  1);
        s2 += __shfl_xor_sync(0xffffffffu, s2, 1);
        if (h == 0) {
            float mu  = s * (1.f/128.f);
            float var = s2 * (1.f/128.f) - mu*mu;
            mus[r] = mu;
            rss[r] = rsqrtf(var + 1e-5f);
        }
    }
    __syncthreads();
    for (int idx = t; idx < 128*128; idx += 256) {
        int r = idx & 127, c = idx >> 7;
        float v = Ps[c*129 + r];
        Ps[c*129 + r] = (v - mus[r]) * rss[r] * g2s[c] + b2s[c];
    }
    __syncthreads();

    // GEMM: ab[r][d] = sum_c pln[c][r] * Wop[c][d]
    const int tx = t & 15;    // r = tx + 16*ii
    const int ty = t >> 4;    // d = ty*8 + dd
    float acc[8][8];
    #pragma unroll
    for (int ii = 0; ii < 8; ++ii)
        #pragma unroll
        for (int dd = 0; dd < 8; ++dd) acc[ii][dd] = 0.f;

    #pragma unroll 2
    for (int c = 0; c < 128; ++c) {
        float a[8], b[8];
        #pragma unroll
        for (int ii = 0; ii < 8; ++ii) a[ii] = Ps[c*129 + tx + 16*ii];
        #pragma unroll
        for (int dd = 0; dd < 8; ++dd) b[dd] = Ws[c*128 + ty*8 + dd];
        #pragma unroll
        for (int ii = 0; ii < 8; ++ii)
            #pragma unroll
            for (int dd = 0; dd < 8; ++dd)
                acc[ii][dd] += a[ii]*b[dd];
    }
    __syncthreads();   // done reading Ps; reuse as output stage

    #pragma unroll
    for (int ii = 0; ii < 8; ++ii) {
        int r = tx + 16*ii;
        #pragma unroll
        for (int dd = 0; dd < 8; ++dd) {
            int d = ty*8 + dd;
            float gv = g_gate[(size_t)d*MROWS + rbase + r];
            Ps[r*129 + d] = gv * (acc[ii][dd] + obs[d]);
        }
    }
    __syncthreads();

    for (int idx = t; idx < 128*128; idx += 256) {
        int r = idx >> 7, d = idx & 127;
        size_t gi = (size_t)(rbase + r)*128 + d;
        out[gi] = Z[gi] + Ps[r*129 + d];
    }
}

// ---------------------------------------------------------------------------
extern "C" void kernel_launch(void* const* d_in, const int* in_sizes, int n_in,
                              void* d_out, int out_size)
{
    const float* Zr   = (const float*)d_in[0];
    const float* mask = (const float*)d_in[1];
    const float* g1   = (const float*)d_in[2];
    const float* b1   = (const float*)d_in[3];
    const float* Wlr  = (const float*)d_in[4];
    const float* blr  = (const float*)d_in[5];
    const float* Wg   = (const float*)d_in[6];
    const float* bg   = (const float*)d_in[7];
    const float* Wog  = (const float*)d_in[8];
    const float* bog  = (const float*)d_in[9];
    const float* g2   = (const float*)d_in[10];
    const float* b2   = (const float*)d_in[11];
    const float* Wop  = (const float*)d_in[12];
    const float* ob   = (const float*)d_in[13];
    float* out = (float*)d_out;

    const size_t sm1 = (size_t)(128*65 + 2*128*64 + 3*64 + 2*128) * sizeof(float);  // ~100 KB
    const size_t sm3 = (size_t)(128*129 + 128*128 + 5*128) * sizeof(float);         // ~134 KB
    cudaFuncSetAttribute(proj_kernel,  cudaFuncAttributeMaxDynamicSharedMemorySize, (int)sm1);
    cudaFuncSetAttribute(final_kernel, cudaFuncAttributeMaxDynamicSharedMemorySize, (int)sm3);

    proj_kernel<<<dim3(4096, 6), 256, sm1>>>(Zr, mask, g1, b1, Wlr, blr, Wg, bg, Wog, bog);
    einsum_kernel<<<dim3(4, 4, 128), 256>>>();
    final_kernel<<<2048, 256, sm3>>>(Zr, g2, b2, Wop, ob, out);
}

// round 4
// speedup vs baseline: 3.6704x; 1.7360x over previous
#include <cuda_runtime.h>
#include <math.h>

#define NNDIM 512
#define DDIM  128
#define MROWS (NNDIM*NNDIM)   // 262144 rows of (i,j)
#define PLD   136             // smem leading dim (conflict-free mma frag loads)

// Scratch (device globals). left/right/gate stored [c][row] c-major; p stored per-c [i][j].
__device__ float g_left [(size_t)DDIM*MROWS];
__device__ float g_right[(size_t)DDIM*MROWS];
__device__ float g_gate [(size_t)DDIM*MROWS];
__device__ float g_p    [(size_t)DDIM*MROWS];

__device__ __forceinline__ float sigmoidf_(float x) { return 1.0f / (1.0f + expf(-x)); }

__device__ __forceinline__ unsigned f2tf32(float x) {
    unsigned r; asm("cvt.rna.tf32.f32 %0, %1;" : "=r"(r) : "f"(x)); return r;
}

__device__ __forceinline__ void mma_tf32(float c[4],
    unsigned a0, unsigned a1, unsigned a2, unsigned a3, unsigned b0, unsigned b1)
{
    asm volatile(
        "mma.sync.aligned.m16n8k8.row.col.f32.tf32.tf32.f32 "
        "{%0,%1,%2,%3}, {%4,%5,%6,%7}, {%8,%9}, {%0,%1,%2,%3};"
        : "+f"(c[0]), "+f"(c[1]), "+f"(c[2]), "+f"(c[3])
        : "r"(a0), "r"(a1), "r"(a2), "r"(a3), "r"(b0), "r"(b1));
}

// ---------------------------------------------------------------------------
// Kernel 1: LN1 + projections + gating, tf32 tensor cores.
// grid (2048 row-tiles of 128, 3 col-tiles), block 512 (16 warps, 4x4).
// ct=0 -> left (Wlr/Wg cols 0..127), ct=1 -> right (cols 128..255), ct=2 -> og.
// Outputs written transposed: left/right/g as [c][row].
// ---------------------------------------------------------------------------
extern "C" __global__ void __launch_bounds__(512)
proj_kernel(const float* __restrict__ Z, const float* __restrict__ mask,
            const float* __restrict__ g1v, const float* __restrict__ b1v,
            const float* __restrict__ Wlr, const float* __restrict__ blr,
            const float* __restrict__ Wg,  const float* __restrict__ bg,
            const float* __restrict__ Wog, const float* __restrict__ bog)
{
    extern __shared__ unsigned smu[];
    unsigned* As = smu;               // [128 k=c][PLD] LN'd Z (tf32), [c][row]
    unsigned* W1 = As + 128*PLD;      // [128 k][PLD] weight 1 (tf32)
    unsigned* W2 = W1 + 128*PLD;      // [128 k][PLD] weight 2 (tf32, dual only)
    float* Asf = (float*)As;
    float* mus = (float*)(W2 + 128*PLD);
    float* rss = mus + 128;
    float* msk = rss + 128;
    float* g1s = msk + 128;
    float* b1s = g1s + 128;
    float* bb1 = b1s + 128;
    float* bb2 = bb1 + 128;
    float* Cs  = (float*)W1;          // epilogue staging [oc][129] (reuse W1)

    const int t     = threadIdx.x;
    const int rbase = blockIdx.x * 128;
    const int ct    = blockIdx.y;     // 0,1: lr dual; 2: og
    const bool dual = (ct < 2);

    // Load Z tile transposed into smem (as float for LN)
    for (int idx = t; idx < 128*128; idx += 512) {
        int r = idx >> 7, c = idx & 127;
        Asf[c*PLD + r] = Z[(size_t)(rbase + r)*128 + c];
    }
    if (t < 128) { msk[t] = mask[rbase + t]; g1s[t] = g1v[t]; b1s[t] = b1v[t]; }

    // Load weights (tf32) + biases
    if (dual) {
        int cb = ct * 128;
        for (int idx = t; idx < 128*128; idx += 512) {
            int k = idx >> 7, j = idx & 127;
            W1[k*PLD + j] = f2tf32(Wlr[k*256 + cb + j]);
            W2[k*PLD + j] = f2tf32(Wg [k*256 + cb + j]);
        }
        if (t < 128) { bb1[t] = blr[ct*128 + t]; bb2[t] = bg[ct*128 + t]; }
    } else {
        for (int idx = t; idx < 128*128; idx += 512) {
            int k = idx >> 7, j = idx & 127;
            W1[k*PLD + j] = f2tf32(Wog[k*128 + j]);
        }
        if (t < 128) bb1[t] = bog[t];
    }
    __syncthreads();

    // LayerNorm stats: 4 threads per row
    {
        int r = t >> 2, h = t & 3;
        float s = 0.f, s2 = 0.f;
        #pragma unroll 8
        for (int cc = 0; cc < 32; ++cc) {
            float v = Asf[(h*32 + cc)*PLD + r];
            s += v; s2 += v*v;
        }
        s  += __shfl_xor_sync(0xffffffffu, s,  1);
        s2 += __shfl_xor_sync(0xffffffffu, s2, 1);
        s  += __shfl_xor_sync(0xffffffffu, s,  2);
        s2 += __shfl_xor_sync(0xffffffffu, s2, 2);
        if (h == 0) {
            float mu  = s * (1.f/128.f);
            float var = s2 * (1.f/128.f) - mu*mu;
            mus[r] = mu;
            rss[r] = rsqrtf(var + 1e-5f);
        }
    }
    __syncthreads();
    // Normalize + convert to tf32 in place
    for (int idx = t; idx < 128*128; idx += 512) {
        int r = idx & 127, c = idx >> 7;
        float v = Asf[c*PLD + r];
        As[c*PLD + r] = f2tf32((v - mus[r]) * rss[r] * g1s[c] + b1s[c]);
    }
    __syncthreads();

    // Tensor-core GEMM: 128x128, K=128. 16 warps as 4(m) x 4(n), 32x32 per warp.
    const int lane = t & 31, w = t >> 5;
    const int wm = w & 3, wn = w >> 2;
    const int tig = lane & 3, grp = lane >> 2;

    float acc1[2][4][4], acc2[2][4][4];
    #pragma unroll
    for (int mt = 0; mt < 2; ++mt)
        #pragma unroll
        for (int nt = 0; nt < 4; ++nt)
            #pragma unroll
            for (int q = 0; q < 4; ++q) { acc1[mt][nt][q] = 0.f; acc2[mt][nt][q] = 0.f; }

    if (dual) {
        #pragma unroll
        for (int k0 = 0; k0 < 128; k0 += 8) {
            unsigned af[2][4];
            #pragma unroll
            for (int mt = 0; mt < 2; ++mt) {
                int ar = wm*32 + mt*16 + grp;
                af[mt][0] = As[(k0+tig  )*PLD + ar];
                af[mt][1] = As[(k0+tig  )*PLD + ar + 8];
                af[mt][2] = As[(k0+tig+4)*PLD + ar];
                af[mt][3] = As[(k0+tig+4)*PLD + ar + 8];
            }
            #pragma unroll
            for (int nt = 0; nt < 4; ++nt) {
                int bc = wn*32 + nt*8 + grp;
                unsigned b0 = W1[(k0+tig)*PLD + bc], b1 = W1[(k0+tig+4)*PLD + bc];
                mma_tf32(acc1[0][nt], af[0][0], af[0][1], af[0][2], af[0][3], b0, b1);
                mma_tf32(acc1[1][nt], af[1][0], af[1][1], af[1][2], af[1][3], b0, b1);
                unsigned c0 = W2[(k0+tig)*PLD + bc], c1 = W2[(k0+tig+4)*PLD + bc];
                mma_tf32(acc2[0][nt], af[0][0], af[0][1], af[0][2], af[0][3], c0, c1);
                mma_tf32(acc2[1][nt], af[1][0], af[1][1], af[1][2], af[1][3], c0, c1);
            }
        }
    } else {
        #pragma unroll
        for (int k0 = 0; k0 < 128; k0 += 8) {
            unsigned af[2][4];
            #pragma unroll
            for (int mt = 0; mt < 2; ++mt) {
                int ar = wm*32 + mt*16 + grp;
                af[mt][0] = As[(k0+tig  )*PLD + ar];
                af[mt][1] = As[(k0+tig  )*PLD + ar + 8];
                af[mt][2] = As[(k0+tig+4)*PLD + ar];
                af[mt][3] = As[(k0+tig+4)*PLD + ar + 8];
            }
            #pragma unroll
            for (int nt = 0; nt < 4; ++nt) {
                int bc = wn*32 + nt*8 + grp;
                unsigned b0 = W1[(k0+tig)*PLD + bc], b1 = W1[(k0+tig+4)*PLD + bc];
                mma_tf32(acc1[0][nt], af[0][0], af[0][1], af[0][2], af[0][3], b0, b1);
                mma_tf32(acc1[1][nt], af[1][0], af[1][1], af[1][2], af[1][3], b0, b1);
            }
        }
    }
    __syncthreads();   // done reading W1/As; W1 reused as staging

    // Epilogue: bias + mask*sigmoid gating (or sigmoid for og), stage [oc][129]
    #pragma unroll
    for (int mt = 0; mt < 2; ++mt) {
        #pragma unroll
        for (int nt = 0; nt < 4; ++nt) {
            #pragma unroll
            for (int q = 0; q < 4; ++q) {
                int r  = wm*32 + mt*16 + grp + ((q >= 2) ? 8 : 0);
                int oc = wn*32 + nt*8 + tig*2 + (q & 1);
                float v;
                if (dual) {
                    float lrv = acc1[mt][nt][q] + bb1[oc];
                    float gtv = acc2[mt][nt][q] + bb2[oc];
                    v = lrv * msk[r] * sigmoidf_(gtv);
                } else {
                    v = sigmoidf_(acc1[mt][nt][q] + bb1[oc]);
                }
                Cs[oc*129 + r] = v;
            }
        }
    }
    __syncthreads();

    float* dst = (ct == 0) ? g_left : (ct == 1 ? g_right : g_gate);
    for (int idx = t; idx < 128*128; idx += 512) {
        int oc = idx >> 7, r = idx & 127;
        dst[(size_t)oc*MROWS + rbase + r] = Cs[oc*129 + r];
    }
}

// ---------------------------------------------------------------------------
// Kernel 2: p[c] = L_c @ R_c^T via tf32 mma.sync (tensor cores).
// grid (jt=4, it=4, c=128), block 256 (8 warps as 4x2), tile 128x128, BK=16.
// ---------------------------------------------------------------------------
#define EK 16
extern "C" __global__ void __launch_bounds__(256, 2)
einsum_kernel()
{
    __shared__ unsigned As[2][EK][136];   // A: [k][i]
    __shared__ unsigned Bs[2][EK][136];   // B: [k][j]

    const int t     = threadIdx.x;
    const int lane  = t & 31;
    const int w     = t >> 5;
    const int wm    = w & 3;          // 4 warps along i
    const int wn    = w >> 2;         // 2 warps along j
    const int jbase = blockIdx.x * 128;
    const int ibase = blockIdx.y * 128;
    const int c     = blockIdx.z;

    const float* A = g_left  + (size_t)c*MROWS;   // [i][k] 512x512
    const float* B = g_right + (size_t)c*MROWS;   // [j][k] 512x512

    const int lrow = t >> 1;          // load row 0..127
    const int lkb  = (t & 1) * 8;     // k sub-offset 0 or 8

    const float* Ap = A + (size_t)(ibase + lrow)*512 + lkb;
    const float* Bp = B + (size_t)(jbase + lrow)*512 + lkb;

    const int tig  = lane & 3;
    const int grp  = lane >> 2;

    float acc[2][8][4];
    #pragma unroll
    for (int mt = 0; mt < 2; ++mt)
        #pragma unroll
        for (int nt = 0; nt < 8; ++nt)
            #pragma unroll
            for (int q = 0; q < 4; ++q) acc[mt][nt][q] = 0.f;

    float4 av0 = *(const float4*)(Ap + 0);
    float4 av1 = *(const float4*)(Ap + 4);
    float4 bv0 = *(const float4*)(Bp + 0);
    float4 bv1 = *(const float4*)(Bp + 4);

    int buf = 0;
    {
        As[0][lkb+0][lrow] = f2tf32(av0.x); As[0][lkb+1][lrow] = f2tf32(av0.y);
        As[0][lkb+2][lrow] = f2tf32(av0.z); As[0][lkb+3][lrow] = f2tf32(av0.w);
        As[0][lkb+4][lrow] = f2tf32(av1.x); As[0][lkb+5][lrow] = f2tf32(av1.y);
        As[0][lkb+6][lrow] = f2tf32(av1.z); As[0][lkb+7][lrow] = f2tf32(av1.w);
        Bs[0][lkb+0][lrow] = f2tf32(bv0.x); Bs[0][lkb+1][lrow] = f2tf32(bv0.y);
        Bs[0][lkb+2][lrow] = f2tf32(bv0.z); Bs[0][lkb+3][lrow] = f2tf32(bv0.w);
        Bs[0][lkb+4][lrow] = f2tf32(bv1.x); Bs[0][lkb+5][lrow] = f2tf32(bv1.y);
        Bs[0][lkb+6][lrow] = f2tf32(bv1.z); Bs[0][lkb+7][lrow] = f2tf32(bv1.w);
    }
    __syncthreads();

    for (int k0 = 0; k0 < 512; k0 += EK) {
        const bool more = (k0 + EK) < 512;
        if (more) {
            av0 = *(const float4*)(Ap + k0 + EK);
            av1 = *(const float4*)(Ap + k0 + EK + 4);
            bv0 = *(const float4*)(Bp + k0 + EK);
            bv1 = *(const float4*)(Bp + k0 + EK + 4);
        }

        #pragma unroll
        for (int kk = 0; kk < EK/8; ++kk) {
            unsigned af[2][4], bf[8][2];
            #pragma unroll
            for (int mt = 0; mt < 2; ++mt) {
                int arow = wm*32 + mt*16 + grp;
                af[mt][0] = As[buf][kk*8 + tig    ][arow    ];
                af[mt][1] = As[buf][kk*8 + tig    ][arow + 8];
                af[mt][2] = As[buf][kk*8 + tig + 4][arow    ];
                af[mt][3] = As[buf][kk*8 + tig + 4][arow + 8];
            }
            #pragma unroll
            for (int nt = 0; nt < 8; ++nt) {
                int bcol = wn*64 + nt*8 + grp;
                bf[nt][0] = Bs[buf][kk*8 + tig    ][bcol];
                bf[nt][1] = Bs[buf][kk*8 + tig + 4][bcol];
            }
            #pragma unroll
            for (int mt = 0; mt < 2; ++mt)
                #pragma unroll
                for (int nt = 0; nt < 8; ++nt)
                    mma_tf32(acc[mt][nt], af[mt][0], af[mt][1], af[mt][2], af[mt][3],
                             bf[nt][0], bf[nt][1]);
        }

        if (more) {
            int nb = buf ^ 1;
            As[nb][lkb+0][lrow] = f2tf32(av0.x); As[nb][lkb+1][lrow] = f2tf32(av0.y);
            As[nb][lkb+2][lrow] = f2tf32(av0.z); As[nb][lkb+3][lrow] = f2tf32(av0.w);
            As[nb][lkb+4][lrow] = f2tf32(av1.x); As[nb][lkb+5][lrow] = f2tf32(av1.y);
            As[nb][lkb+6][lrow] = f2tf32(av1.z); As[nb][lkb+7][lrow] = f2tf32(av1.w);
            Bs[nb][lkb+0][lrow] = f2tf32(bv0.x); Bs[nb][lkb+1][lrow] = f2tf32(bv0.y);
            Bs[nb][lkb+2][lrow] = f2tf32(bv0.z); Bs[nb][lkb+3][lrow] = f2tf32(bv0.w);
            Bs[nb][lkb+4][lrow] = f2tf32(bv1.x); Bs[nb][lkb+5][lrow] = f2tf32(bv1.y);
            Bs[nb][lkb+6][lrow] = f2tf32(bv1.z); Bs[nb][lkb+7][lrow] = f2tf32(bv1.w);
            __syncthreads();
            buf ^= 1;
        }
    }

    float* P = g_p + (size_t)c*MROWS;
    #pragma unroll
    for (int mt = 0; mt < 2; ++mt) {
        int i0 = ibase + wm*32 + mt*16 + grp;
        #pragma unroll
        for (int nt = 0; nt < 8; ++nt) {
            int j0 = jbase + wn*64 + nt*8 + tig*2;
            float2 v01 = make_float2(acc[mt][nt][0], acc[mt][nt][1]);
            float2 v23 = make_float2(acc[mt][nt][2], acc[mt][nt][3]);
            *(float2*)&P[(size_t)i0*512 + j0]       = v01;
            *(float2*)&P[(size_t)(i0+8)*512 + j0]   = v23;
        }
    }
}

// ---------------------------------------------------------------------------
// Kernel 3: LN2 over c, ab = pln @ W_op (tf32 mma), out = Z + g*(ab + bias).
// grid 2048 (128 rows each), block 512 (16 warps, 4x4).
// ---------------------------------------------------------------------------
extern "C" __global__ void __launch_bounds__(512)
final_kernel(const float* __restrict__ Z,
             const float* __restrict__ g2v, const float* __restrict__ b2v,
             const float* __restrict__ Wop, const float* __restrict__ obias,
             float* __restrict__ out)
{
    extern __shared__ unsigned smu[];
    unsigned* Ps = smu;               // [c=k][PLD] p tile -> tf32 after LN
    unsigned* Ws = Ps + 128*PLD;      // [c=k][PLD] W_op (tf32)
    float* Psf = (float*)Ps;
    float* mus = (float*)(Ws + 128*PLD);
    float* rss = mus + 128;
    float* g2s = rss + 128;
    float* b2s = g2s + 128;
    float* obs = b2s + 128;
    float* Sout = (float*)Ws;         // reuse after GEMM: [r][129]

    const int t     = threadIdx.x;
    const int rbase = blockIdx.x * 128;

    for (int idx = t; idx < 128*128; idx += 512) {
        int c = idx >> 7, r = idx & 127;
        Psf[c*PLD + r] = g_p[(size_t)c*MROWS + rbase + r];
        Ws[c*PLD + r]  = f2tf32(Wop[idx]);   // [c][d], d = r index here
    }
    if (t < 128) { g2s[t] = g2v[t]; b2s[t] = b2v[t]; obs[t] = obias[t]; }
    __syncthreads();

    // LN over c: 4 threads per row
    {
        int r = t >> 2, h = t & 3;
        float s = 0.f, s2 = 0.f;
        #pragma unroll 8
        for (int cc = 0; cc < 32; ++cc) {
            float v = Psf[(h*32 + cc)*PLD + r];
            s += v; s2 += v*v;
        }
        s  += __shfl_xor_sync(0xffffffffu, s,  1);
        s2 += __shfl_xor_sync(0xffffffffu, s2, 1);
        s  += __shfl_xor_sync(0xffffffffu, s,  2);
        s2 += __shfl_xor_sync(0xffffffffu, s2, 2);
        if (h == 0) {
            float mu  = s * (1.f/128.f);
            float var = s2 * (1.f/128.f) - mu*mu;
            mus[r] = mu;
            rss[r] = rsqrtf(var + 1e-5f);
        }
    }
    __syncthreads();
    for (int idx = t; idx < 128*128; idx += 512) {
        int r = idx & 127, c = idx >> 7;
        float v = Psf[c*PLD + r];
        Ps[c*PLD + r] = f2tf32((v - mus[r]) * rss[r] * g2s[c] + b2s[c]);
    }
    __syncthreads();

    // Tensor-core GEMM: M=128 (r), N=128 (d), K=128 (c)
    const int lane = t & 31, w = t >> 5;
    const int wm = w & 3, wn = w >> 2;
    const int tig = lane & 3, grp = lane >> 2;

    float acc[2][4][4];
    #pragma unroll
    for (int mt = 0; mt < 2; ++mt)
        #pragma unroll
        for (int nt = 0; nt < 4; ++nt)
            #pragma unroll
            for (int q = 0; q < 4; ++q) acc[mt][nt][q] = 0.f;

    #pragma unroll
    for (int k0 = 0; k0 < 128; k0 += 8) {
        unsigned af[2][4];
        #pragma unroll
        for (int mt = 0; mt < 2; ++mt) {
            int ar = wm*32 + mt*16 + grp;
            af[mt][0] = Ps[(k0+tig  )*PLD + ar];
            af[mt][1] = Ps[(k0+tig  )*PLD + ar + 8];
            af[mt][2] = Ps[(k0+tig+4)*PLD + ar];
            af[mt][3] = Ps[(k0+tig+4)*PLD + ar + 8];
        }
        #pragma unroll
        for (int nt = 0; nt < 4; ++nt) {
            int bc = wn*32 + nt*8 + grp;
            unsigned b0 = Ws[(k0+tig)*PLD + bc], b1 = Ws[(k0+tig+4)*PLD + bc];
            mma_tf32(acc[0][nt], af[0][0], af[0][1], af[0][2], af[0][3], b0, b1);
            mma_tf32(acc[1][nt], af[1][0], af[1][1], af[1][2], af[1][3], b0, b1);
        }
    }
    __syncthreads();   // done reading Ws; reuse as staging

    // Epilogue: gate + bias, stage [r][129]
    #pragma unroll
    for (int mt = 0; mt < 2; ++mt) {
        #pragma unroll
        for (int nt = 0; nt < 4; ++nt) {
            #pragma unroll
            for (int q = 0; q < 4; ++q) {
                int r = wm*32 + mt*16 + grp + ((q >= 2) ? 8 : 0);
                int d = wn*32 + nt*8 + tig*2 + (q & 1);
                float gv = g_gate[(size_t)d*MROWS + rbase + r];
                Sout[r*129 + d] = gv * (acc[mt][nt][q] + obs[d]);
            }
        }
    }
    __syncthreads();

    for (int idx = t; idx < 128*128; idx += 512) {
        int r = idx >> 7, d = idx & 127;
        size_t gi = (size_t)(rbase + r)*128 + d;
        out[gi] = Z[gi] + Sout[r*129 + d];
    }
}

// ---------------------------------------------------------------------------
extern "C" void kernel_launch(void* const* d_in, const int* in_sizes, int n_in,
                              void* d_out, int out_size)
{
    const float* Zr   = (const float*)d_in[0];
    const float* mask = (const float*)d_in[1];
    const float* g1   = (const float*)d_in[2];
    const float* b1   = (const float*)d_in[3];
    const float* Wlr  = (const float*)d_in[4];
    const float* blr  = (const float*)d_in[5];
    const float* Wg   = (const float*)d_in[6];
    const float* bg   = (const float*)d_in[7];
    const float* Wog  = (const float*)d_in[8];
    const float* bog  = (const float*)d_in[9];
    const float* g2   = (const float*)d_in[10];
    const float* b2   = (const float*)d_in[11];
    const float* Wop  = (const float*)d_in[12];
    const float* ob   = (const float*)d_in[13];
    float* out = (float*)d_out;

    const size_t sm1 = (size_t)(3*128*PLD + 7*128) * 4;   // 212,480 B
    const size_t sm3 = (size_t)(2*128*PLD + 5*128) * 4;   // 141,824 B
    cudaFuncSetAttribute(proj_kernel,  cudaFuncAttributeMaxDynamicSharedMemorySize, (int)sm1);
    cudaFuncSetAttribute(final_kernel, cudaFuncAttributeMaxDynamicSharedMemorySize, (int)sm3);

    proj_kernel<<<dim3(2048, 3), 512, sm1>>>(Zr, mask, g1, b1, Wlr, blr, Wg, bg, Wog, bog);
    einsum_kernel<<<dim3(4, 4, 128), 256>>>();
    final_kernel<<<2048, 512, sm3>>>(Zr, g2, b2, Wop, ob, out);
}

// round 5
// speedup vs baseline: 4.3770x; 1.1925x over previous
#include <cuda_runtime.h>
#include <math.h>

#define NNDIM 512
#define DDIM  128
#define MROWS (NNDIM*NNDIM)   // 262144 rows of (i,j)

// Scratch (device globals). left/right/gate stored [c][row] c-major; p per-c [i][j].
__device__ float    g_left [(size_t)DDIM*MROWS];
__device__ float    g_right[(size_t)DDIM*MROWS];
__device__ float    g_gate [(size_t)DDIM*MROWS];
__device__ float    g_p    [(size_t)DDIM*MROWS];
__device__ unsigned g_zln  [(size_t)DDIM*MROWS];   // LN1(Z) as tf32 bits, [c][row]

__device__ __forceinline__ float sigmoidf_(float x) { return 1.0f / (1.0f + expf(-x)); }

__device__ __forceinline__ unsigned f2tf32(float x) {
    unsigned r; asm("cvt.rna.tf32.f32 %0, %1;" : "=r"(r) : "f"(x)); return r;
}

__device__ __forceinline__ void mma_tf32(float c[4],
    unsigned a0, unsigned a1, unsigned a2, unsigned a3, unsigned b0, unsigned b1)
{
    asm volatile(
        "mma.sync.aligned.m16n8k8.row.col.f32.tf32.tf32.f32 "
        "{%0,%1,%2,%3}, {%4,%5,%6,%7}, {%8,%9}, {%0,%1,%2,%3};"
        : "+f"(c[0]), "+f"(c[1]), "+f"(c[2]), "+f"(c[3])
        : "r"(a0), "r"(a1), "r"(a2), "r"(a3), "r"(b0), "r"(b1));
}

__device__ __forceinline__ void cp16(void* smem_dst, const void* gsrc) {
    unsigned d = (unsigned)__cvta_generic_to_shared(smem_dst);
    asm volatile("cp.async.ca.shared.global [%0], [%1], 16;" :: "r"(d), "l"(gsrc));
}
__device__ __forceinline__ void cp_commit() { asm volatile("cp.async.commit_group;"); }
template<int N> __device__ __forceinline__ void cp_wait() {
    asm volatile("cp.async.wait_group %0;" :: "n"(N));
}

// ---------------------------------------------------------------------------
// Kernel 0: LN1(Z) -> g_zln (tf32 bits, transposed [c][row]). grid 2048 x 256.
// ---------------------------------------------------------------------------
extern "C" __global__ void __launch_bounds__(256)
ln1_kernel(const float* __restrict__ Z, const float* __restrict__ g1v,
           const float* __restrict__ b1v)
{
    extern __shared__ float sf[];
    float* sZ  = sf;                // [128 c][129 r]
    float* mus = sZ + 128*129;
    float* rss = mus + 128;
    float* g1s = rss + 128;
    float* b1s = g1s + 128;

    const int t = threadIdx.x;
    const int rbase = blockIdx.x * 128;

    for (int idx = t; idx < 128*128; idx += 256) {
        int r = idx >> 7, c = idx & 127;
        sZ[c*129 + r] = Z[(size_t)(rbase + r)*128 + c];
    }
    if (t < 128) { g1s[t] = g1v[t]; b1s[t] = b1v[t]; }
    __syncthreads();

    {
        int r = t >> 1, h = t & 1;
        float s = 0.f, s2 = 0.f;
        #pragma unroll 8
        for (int c = h*64; c < h*64 + 64; ++c) {
            float v = sZ[c*129 + r]; s += v; s2 += v*v;
        }
        s  += __shfl_xor_sync(0xffffffffu, s,  1);
        s2 += __shfl_xor_sync(0xffffffffu, s2, 1);
        if (h == 0) {
            float mu = s * (1.f/128.f);
            float var = s2 * (1.f/128.f) - mu*mu;
            mus[r] = mu; rss[r] = rsqrtf(var + 1e-5f);
        }
    }
    __syncthreads();

    for (int idx = t; idx < 128*128; idx += 256) {
        int c = idx >> 7, r = idx & 127;
        float v = (sZ[c*129 + r] - mus[r]) * rss[r] * g1s[c] + b1s[c];
        g_zln[(size_t)c*MROWS + rbase + r] = f2tf32(v);
    }
}

// ---------------------------------------------------------------------------
// Kernel 1: persistent projections + gating, tf32 tensor cores.
// 150 blocks x 512 thr: bx<60 -> left-dual, <120 -> right-dual, else og.
// Weights resident in smem; 64-row M-tiles double-buffered via cp.async.
// ---------------------------------------------------------------------------
extern "C" __global__ void __launch_bounds__(512)
proj_kernel(const float* __restrict__ mask,
            const float* __restrict__ Wlr, const float* __restrict__ blr,
            const float* __restrict__ Wg,  const float* __restrict__ bg,
            const float* __restrict__ Wog, const float* __restrict__ bog)
{
    extern __shared__ unsigned smu[];
    unsigned* W1 = smu;                 // [128 k][136 n]
    unsigned* W2 = W1 + 128*136;        // [128 k][136 n]
    unsigned* As = W2 + 128*136;        // [2][128 k][72 m]
    float* bb1 = (float*)(As + 2*128*72);
    float* bb2 = bb1 + 128;

    const int t = threadIdx.x, bx = blockIdx.x;
    int cg, ms, stride;
    if      (bx < 60)  { cg = 0; ms = bx;       stride = 60; }
    else if (bx < 120) { cg = 1; ms = bx - 60;  stride = 60; }
    else               { cg = 2; ms = bx - 120; stride = 30; }
    const bool dual = (cg < 2);

    if (dual) {
        int cb = cg * 128;
        for (int idx = t; idx < 128*128; idx += 512) {
            int k = idx >> 7, j = idx & 127;
            W1[k*136 + j] = f2tf32(Wlr[k*256 + cb + j]);
            W2[k*136 + j] = f2tf32(Wg [k*256 + cb + j]);
        }
        if (t < 128) { bb1[t] = blr[cg*128 + t]; bb2[t] = bg[cg*128 + t]; }
    } else {
        for (int idx = t; idx < 128*128; idx += 512) {
            int k = idx >> 7, j = idx & 127;
            W1[k*136 + j] = f2tf32(Wog[k*128 + j]);
        }
        if (t < 128) bb1[t] = bog[t];
    }

    const int lane = t & 31, w = t >> 5;
    const int wm = w & 1, wn = w >> 1;      // 2 m-warps x 8 n-warps
    const int tig = lane & 3, grp = lane >> 2;

    float* dst = (cg == 0) ? g_left : (cg == 1 ? g_right : g_gate);

    int tile = ms;
    // prefetch first tile into buf 0
    {
        int m0 = tile * 64;
        #pragma unroll
        for (int i = 0; i < 4; ++i) {
            int idx = t + 512*i;             // 0..2047
            int c = idx >> 4, seg = idx & 15;
            cp16(As + c*72 + seg*4, g_zln + (size_t)c*MROWS + m0 + seg*4);
        }
        cp_commit();
    }
    int buf = 0;

    for (; tile < 4096; tile += stride) {
        int nxt = tile + stride;
        if (nxt < 4096) {
            int m0 = nxt * 64;
            unsigned* db = As + (buf^1)*128*72;
            #pragma unroll
            for (int i = 0; i < 4; ++i) {
                int idx = t + 512*i;
                int c = idx >> 4, seg = idx & 15;
                cp16(db + c*72 + seg*4, g_zln + (size_t)c*MROWS + m0 + seg*4);
            }
            cp_commit();
            cp_wait<1>();
        } else {
            cp_wait<0>();
        }
        __syncthreads();

        const unsigned* A = As + buf*128*72;

        float acc1[2][2][4], acc2[2][2][4];
        #pragma unroll
        for (int mt = 0; mt < 2; ++mt)
            #pragma unroll
            for (int nt = 0; nt < 2; ++nt)
                #pragma unroll
                for (int q = 0; q < 4; ++q) { acc1[mt][nt][q] = 0.f; acc2[mt][nt][q] = 0.f; }

        if (dual) {
            #pragma unroll
            for (int k0 = 0; k0 < 128; k0 += 8) {
                unsigned af[2][4];
                #pragma unroll
                for (int mt = 0; mt < 2; ++mt) {
                    int ar = wm*32 + mt*16 + grp;
                    af[mt][0] = A[(k0+tig  )*72 + ar];
                    af[mt][1] = A[(k0+tig  )*72 + ar + 8];
                    af[mt][2] = A[(k0+tig+4)*72 + ar];
                    af[mt][3] = A[(k0+tig+4)*72 + ar + 8];
                }
                #pragma unroll
                for (int nt = 0; nt < 2; ++nt) {
                    int bc = wn*16 + nt*8 + grp;
                    unsigned b0 = W1[(k0+tig)*136 + bc], b1 = W1[(k0+tig+4)*136 + bc];
                    mma_tf32(acc1[0][nt], af[0][0], af[0][1], af[0][2], af[0][3], b0, b1);
                    mma_tf32(acc1[1][nt], af[1][0], af[1][1], af[1][2], af[1][3], b0, b1);
                    unsigned c0 = W2[(k0+tig)*136 + bc], c1 = W2[(k0+tig+4)*136 + bc];
                    mma_tf32(acc2[0][nt], af[0][0], af[0][1], af[0][2], af[0][3], c0, c1);
                    mma_tf32(acc2[1][nt], af[1][0], af[1][1], af[1][2], af[1][3], c0, c1);
                }
            }
        } else {
            #pragma unroll
            for (int k0 = 0; k0 < 128; k0 += 8) {
                unsigned af[2][4];
                #pragma unroll
                for (int mt = 0; mt < 2; ++mt) {
                    int ar = wm*32 + mt*16 + grp;
                    af[mt][0] = A[(k0+tig  )*72 + ar];
                    af[mt][1] = A[(k0+tig  )*72 + ar + 8];
                    af[mt][2] = A[(k0+tig+4)*72 + ar];
                    af[mt][3] = A[(k0+tig+4)*72 + ar + 8];
                }
                #pragma unroll
                for (int nt = 0; nt < 2; ++nt) {
                    int bc = wn*16 + nt*8 + grp;
                    unsigned b0 = W1[(k0+tig)*136 + bc], b1 = W1[(k0+tig+4)*136 + bc];
                    mma_tf32(acc1[0][nt], af[0][0], af[0][1], af[0][2], af[0][3], b0, b1);
                    mma_tf32(acc1[1][nt], af[1][0], af[1][1], af[1][2], af[1][3], b0, b1);
                }
            }
        }

        // Epilogue: bias + gating, direct sector-aligned global stores.
        const int rb = tile * 64;
        #pragma unroll
        for (int mt = 0; mt < 2; ++mt) {
            #pragma unroll
            for (int nt = 0; nt < 2; ++nt) {
                #pragma unroll
                for (int q = 0; q < 4; ++q) {
                    int r  = wm*32 + mt*16 + grp + ((q >= 2) ? 8 : 0);
                    int oc = wn*16 + nt*8 + tig*2 + (q & 1);
                    float v;
                    if (dual) {
                        float mv  = __ldg(&mask[rb + r]);
                        float lrv = acc1[mt][nt][q] + bb1[oc];
                        float gtv = acc2[mt][nt][q] + bb2[oc];
                        v = lrv * mv * sigmoidf_(gtv);
                    } else {
                        v = sigmoidf_(acc1[mt][nt][q] + bb1[oc]);
                    }
                    dst[(size_t)oc*MROWS + rb + r] = v;
                }
            }
        }
        __syncthreads();   // As[buf] free for next prefetch overwrite
        buf ^= 1;
    }
}

// ---------------------------------------------------------------------------
// Kernel 2: p[c] = L_c @ R_c^T via tf32 mma.sync (unchanged from R3).
// ---------------------------------------------------------------------------
#define EK 16
extern "C" __global__ void __launch_bounds__(256, 2)
einsum_kernel()
{
    __shared__ unsigned As[2][EK][136];
    __shared__ unsigned Bs[2][EK][136];

    const int t = threadIdx.x;
    const int lane = t & 31;
    const int w = t >> 5;
    const int wm = w & 3;
    const int wn = w >> 2;
    const int jbase = blockIdx.x * 128;
    const int ibase = blockIdx.y * 128;
    const int c = blockIdx.z;

    const float* A = g_left  + (size_t)c*MROWS;
    const float* B = g_right + (size_t)c*MROWS;

    const int lrow = t >> 1;
    const int lkb  = (t & 1) * 8;

    const float* Ap = A + (size_t)(ibase + lrow)*512 + lkb;
    const float* Bp = B + (size_t)(jbase + lrow)*512 + lkb;

    const int tig = lane & 3;
    const int grp = lane >> 2;

    float acc[2][8][4];
    #pragma unroll
    for (int mt = 0; mt < 2; ++mt)
        #pragma unroll
        for (int nt = 0; nt < 8; ++nt)
            #pragma unroll
            for (int q = 0; q < 4; ++q) acc[mt][nt][q] = 0.f;

    float4 av0 = *(const float4*)(Ap + 0);
    float4 av1 = *(const float4*)(Ap + 4);
    float4 bv0 = *(const float4*)(Bp + 0);
    float4 bv1 = *(const float4*)(Bp + 4);

    int buf = 0;
    {
        As[0][lkb+0][lrow] = f2tf32(av0.x); As[0][lkb+1][lrow] = f2tf32(av0.y);
        As[0][lkb+2][lrow] = f2tf32(av0.z); As[0][lkb+3][lrow] = f2tf32(av0.w);
        As[0][lkb+4][lrow] = f2tf32(av1.x); As[0][lkb+5][lrow] = f2tf32(av1.y);
        As[0][lkb+6][lrow] = f2tf32(av1.z); As[0][lkb+7][lrow] = f2tf32(av1.w);
        Bs[0][lkb+0][lrow] = f2tf32(bv0.x); Bs[0][lkb+1][lrow] = f2tf32(bv0.y);
        Bs[0][lkb+2][lrow] = f2tf32(bv0.z); Bs[0][lkb+3][lrow] = f2tf32(bv0.w);
        Bs[0][lkb+4][lrow] = f2tf32(bv1.x); Bs[0][lkb+5][lrow] = f2tf32(bv1.y);
        Bs[0][lkb+6][lrow] = f2tf32(bv1.z); Bs[0][lkb+7][lrow] = f2tf32(bv1.w);
    }
    __syncthreads();

    for (int k0 = 0; k0 < 512; k0 += EK) {
        const bool more = (k0 + EK) < 512;
        if (more) {
            av0 = *(const float4*)(Ap + k0 + EK);
            av1 = *(const float4*)(Ap + k0 + EK + 4);
            bv0 = *(const float4*)(Bp + k0 + EK);
            bv1 = *(const float4*)(Bp + k0 + EK + 4);
        }

        #pragma unroll
        for (int kk = 0; kk < EK/8; ++kk) {
            unsigned af[2][4], bf[8][2];
            #pragma unroll
            for (int mt = 0; mt < 2; ++mt) {
                int arow = wm*32 + mt*16 + grp;
                af[mt][0] = As[buf][kk*8 + tig    ][arow    ];
                af[mt][1] = As[buf][kk*8 + tig    ][arow + 8];
                af[mt][2] = As[buf][kk*8 + tig + 4][arow    ];
                af[mt][3] = As[buf][kk*8 + tig + 4][arow + 8];
            }
            #pragma unroll
            for (int nt = 0; nt < 8; ++nt) {
                int bcol = wn*64 + nt*8 + grp;
                bf[nt][0] = Bs[buf][kk*8 + tig    ][bcol];
                bf[nt][1] = Bs[buf][kk*8 + tig + 4][bcol];
            }
            #pragma unroll
            for (int mt = 0; mt < 2; ++mt)
                #pragma unroll
                for (int nt = 0; nt < 8; ++nt)
                    mma_tf32(acc[mt][nt], af[mt][0], af[mt][1], af[mt][2], af[mt][3],
                             bf[nt][0], bf[nt][1]);
        }

        if (more) {
            int nb = buf ^ 1;
            As[nb][lkb+0][lrow] = f2tf32(av0.x); As[nb][lkb+1][lrow] = f2tf32(av0.y);
            As[nb][lkb+2][lrow] = f2tf32(av0.z); As[nb][lkb+3][lrow] = f2tf32(av0.w);
            As[nb][lkb+4][lrow] = f2tf32(av1.x); As[nb][lkb+5][lrow] = f2tf32(av1.y);
            As[nb][lkb+6][lrow] = f2tf32(av1.z); As[nb][lkb+7][lrow] = f2tf32(av1.w);
            Bs[nb][lkb+0][lrow] = f2tf32(bv0.x); Bs[nb][lkb+1][lrow] = f2tf32(bv0.y);
            Bs[nb][lkb+2][lrow] = f2tf32(bv0.z); Bs[nb][lkb+3][lrow] = f2tf32(bv0.w);
            Bs[nb][lkb+4][lrow] = f2tf32(bv1.x); Bs[nb][lkb+5][lrow] = f2tf32(bv1.y);
            Bs[nb][lkb+6][lrow] = f2tf32(bv1.z); Bs[nb][lkb+7][lrow] = f2tf32(bv1.w);
            __syncthreads();
            buf ^= 1;
        }
    }

    float* P = g_p + (size_t)c*MROWS;
    #pragma unroll
    for (int mt = 0; mt < 2; ++mt) {
        int i0 = ibase + wm*32 + mt*16 + grp;
        #pragma unroll
        for (int nt = 0; nt < 8; ++nt) {
            int j0 = jbase + wn*64 + nt*8 + tig*2;
            float2 v01 = make_float2(acc[mt][nt][0], acc[mt][nt][1]);
            float2 v23 = make_float2(acc[mt][nt][2], acc[mt][nt][3]);
            *(float2*)&P[(size_t)i0*512 + j0]     = v01;
            *(float2*)&P[(size_t)(i0+8)*512 + j0] = v23;
        }
    }
}

// ---------------------------------------------------------------------------
// Kernel 3: persistent LN2 + (pln @ W_op) + gate + residual.
// 148 blocks x 512 thr; W_op resident; 128-row P tiles cp.async double-buffered.
// ---------------------------------------------------------------------------
extern "C" __global__ void __launch_bounds__(512)
final_kernel(const float* __restrict__ Z,
             const float* __restrict__ g2v, const float* __restrict__ b2v,
             const float* __restrict__ Wop, const float* __restrict__ obias,
             float* __restrict__ out)
{
    extern __shared__ unsigned smu[];
    unsigned* Ws = smu;                 // [128 c][136 d]
    unsigned* Ps = Ws + 128*136;        // [2][128 c][136 r]
    float* g2s = (float*)(Ps + 2*128*136);
    float* b2s = g2s + 128;
    float* obs = b2s + 128;
    float* mus = obs + 128;
    float* rss = mus + 128;

    const int t = threadIdx.x;
    for (int idx = t; idx < 128*128; idx += 512) {
        int c = idx >> 7, d = idx & 127;
        Ws[c*136 + d] = f2tf32(Wop[idx]);
    }
    if (t < 128) { g2s[t] = g2v[t]; b2s[t] = b2v[t]; obs[t] = obias[t]; }

    const int lane = t & 31, w = t >> 5;
    const int wm = w & 3, wn = w >> 2;
    const int tig = lane & 3, grp = lane >> 2;

    int tile = blockIdx.x;
    {
        int m0 = tile * 128;
        #pragma unroll
        for (int i = 0; i < 8; ++i) {
            int idx = t + 512*i;            // 0..4095
            int c = idx >> 5, seg = idx & 31;
            cp16(Ps + c*136 + seg*4, g_p + (size_t)c*MROWS + m0 + seg*4);
        }
        cp_commit();
    }
    int buf = 0;

    for (; tile < 2048; tile += 148) {
        int nxt = tile + 148;
        if (nxt < 2048) {
            int m0 = nxt * 128;
            unsigned* db = Ps + (buf^1)*128*136;
            #pragma unroll
            for (int i = 0; i < 8; ++i) {
                int idx = t + 512*i;
                int c = idx >> 5, seg = idx & 31;
                cp16(db + c*136 + seg*4, g_p + (size_t)c*MROWS + m0 + seg*4);
            }
            cp_commit();
            cp_wait<1>();
        } else {
            cp_wait<0>();
        }
        __syncthreads();

        unsigned* P = Ps + buf*128*136;
        float* Pf = (float*)P;

        // LN over c: 4 threads per row
        {
            int r = t >> 2, h = t & 3;
            float s = 0.f, s2 = 0.f;
            #pragma unroll 8
            for (int cc = 0; cc < 32; ++cc) {
                float v = Pf[(h*32 + cc)*136 + r]; s += v; s2 += v*v;
            }
            s  += __shfl_xor_sync(0xffffffffu, s,  1);
            s2 += __shfl_xor_sync(0xffffffffu, s2, 1);
            s  += __shfl_xor_sync(0xffffffffu, s,  2);
            s2 += __shfl_xor_sync(0xffffffffu, s2, 2);
            if (h == 0) {
                float mu = s * (1.f/128.f);
                float var = s2 * (1.f/128.f) - mu*mu;
                mus[r] = mu; rss[r] = rsqrtf(var + 1e-5f);
            }
        }
        __syncthreads();
        for (int idx = t; idx < 128*128; idx += 512) {
            int r = idx & 127, c = idx >> 7;
            P[c*136 + r] = f2tf32((Pf[c*136 + r] - mus[r]) * rss[r] * g2s[c] + b2s[c]);
        }
        __syncthreads();

        float acc[2][4][4];
        #pragma unroll
        for (int mt = 0; mt < 2; ++mt)
            #pragma unroll
            for (int nt = 0; nt < 4; ++nt)
                #pragma unroll
                for (int q = 0; q < 4; ++q) acc[mt][nt][q] = 0.f;

        #pragma unroll
        for (int k0 = 0; k0 < 128; k0 += 8) {
            unsigned af[2][4];
            #pragma unroll
            for (int mt = 0; mt < 2; ++mt) {
                int ar = wm*32 + mt*16 + grp;
                af[mt][0] = P[(k0+tig  )*136 + ar];
                af[mt][1] = P[(k0+tig  )*136 + ar + 8];
                af[mt][2] = P[(k0+tig+4)*136 + ar];
                af[mt][3] = P[(k0+tig+4)*136 + ar + 8];
            }
            #pragma unroll
            for (int nt = 0; nt < 4; ++nt) {
                int bc = wn*32 + nt*8 + grp;
                unsigned b0 = Ws[(k0+tig)*136 + bc], b1 = Ws[(k0+tig+4)*136 + bc];
                mma_tf32(acc[0][nt], af[0][0], af[0][1], af[0][2], af[0][3], b0, b1);
                mma_tf32(acc[1][nt], af[1][0], af[1][1], af[1][2], af[1][3], b0, b1);
            }
        }
        __syncthreads();   // all warps done reading P; reuse as staging

        float* Sout = Pf;
        const int rb = tile * 128;
        #pragma unroll
        for (int mt = 0; mt < 2; ++mt) {
            #pragma unroll
            for (int nt = 0; nt < 4; ++nt) {
                #pragma unroll
                for (int q = 0; q < 4; ++q) {
                    int r = wm*32 + mt*16 + grp + ((q >= 2) ? 8 : 0);
                    int d = wn*32 + nt*8 + tig*2 + (q & 1);
                    float gv = __ldg(&g_gate[(size_t)d*MROWS + rb + r]);
                    Sout[r*136 + d] = gv * (acc[mt][nt][q] + obs[d]);
                }
            }
        }
        __syncthreads();

        for (int idx = t; idx < 128*128; idx += 512) {
            int r = idx >> 7, d = idx & 127;
            size_t gi = (size_t)(rb + r)*128 + d;
            out[gi] = Z[gi] + Sout[r*136 + d];
        }
        __syncthreads();
        buf ^= 1;
    }
}

// ---------------------------------------------------------------------------
extern "C" void kernel_launch(void* const* d_in, const int* in_sizes, int n_in,
                              void* d_out, int out_size)
{
    const float* Zr   = (const float*)d_in[0];
    const float* mask = (const float*)d_in[1];
    const float* g1   = (const float*)d_in[2];
    const float* b1   = (const float*)d_in[3];
    const float* Wlr  = (const float*)d_in[4];
    const float* blr  = (const float*)d_in[5];
    const float* Wg   = (const float*)d_in[6];
    const float* bg   = (const float*)d_in[7];
    const float* Wog  = (const float*)d_in[8];
    const float* bog  = (const float*)d_in[9];
    const float* g2   = (const float*)d_in[10];
    const float* b2   = (const float*)d_in[11];
    const float* Wop  = (const float*)d_in[12];
    const float* ob   = (const float*)d_in[13];
    float* out = (float*)d_out;

    const size_t sm0 = (size_t)(128*129 + 4*128) * 4;                 // ~68 KB
    const size_t sm1 = (size_t)(2*128*136 + 2*128*72 + 2*128) * 4;    // ~214 KB
    const size_t sm3 = (size_t)(3*128*136 + 5*128) * 4;               // ~212 KB
    cudaFuncSetAttribute(ln1_kernel,   cudaFuncAttributeMaxDynamicSharedMemorySize, (int)sm0);
    cudaFuncSetAttribute(proj_kernel,  cudaFuncAttributeMaxDynamicSharedMemorySize, (int)sm1);
    cudaFuncSetAttribute(final_kernel, cudaFuncAttributeMaxDynamicSharedMemorySize, (int)sm3);

    ln1_kernel<<<2048, 256, sm0>>>(Zr, g1, b1);
    proj_kernel<<<150, 512, sm1>>>(mask, Wlr, blr, Wg, bg, Wog, bog);
    einsum_kernel<<<dim3(4, 4, 128), 256>>>();
    final_kernel<<<148, 512, sm3>>>(Zr, g2, b2, Wop, ob, out);
}

// round 6
// speedup vs baseline: 5.0233x; 1.1477x over previous
#include <cuda_runtime.h>
#include <cuda_bf16.h>
#include <math.h>

#define NNDIM 512
#define DDIM  128
#define MROWS (NNDIM*NNDIM)   // 262144 rows of (i,j)

// Scratch (device globals).
__device__ __nv_bfloat16 g_leftb [(size_t)DDIM*MROWS];  // [c][row] bf16
__device__ __nv_bfloat16 g_rightb[(size_t)DDIM*MROWS];  // [c][row] bf16
__device__ float    g_gate[(size_t)DDIM*MROWS];          // [c][row] f32
__device__ float    g_p   [(size_t)DDIM*MROWS];          // per-c [i][j] f32
__device__ unsigned g_zln [(size_t)DDIM*MROWS];          // LN1(Z) tf32 bits, [c][row]
__device__ unsigned g_wop [DDIM*DDIM];                   // W_op tf32 bits, [c][d]

__device__ __forceinline__ float sigmoidf_(float x) { return 1.0f / (1.0f + expf(-x)); }

__device__ __forceinline__ unsigned f2tf32(float x) {
    unsigned r; asm("cvt.rna.tf32.f32 %0, %1;" : "=r"(r) : "f"(x)); return r;
}

__device__ __forceinline__ void mma_tf32(float c[4],
    unsigned a0, unsigned a1, unsigned a2, unsigned a3, unsigned b0, unsigned b1)
{
    asm volatile(
        "mma.sync.aligned.m16n8k8.row.col.f32.tf32.tf32.f32 "
        "{%0,%1,%2,%3}, {%4,%5,%6,%7}, {%8,%9}, {%0,%1,%2,%3};"
        : "+f"(c[0]), "+f"(c[1]), "+f"(c[2]), "+f"(c[3])
        : "r"(a0), "r"(a1), "r"(a2), "r"(a3), "r"(b0), "r"(b1));
}

__device__ __forceinline__ void mma_bf16(float c[4],
    unsigned a0, unsigned a1, unsigned a2, unsigned a3, unsigned b0, unsigned b1)
{
    asm volatile(
        "mma.sync.aligned.m16n8k16.row.col.f32.bf16.bf16.f32 "
        "{%0,%1,%2,%3}, {%4,%5,%6,%7}, {%8,%9}, {%0,%1,%2,%3};"
        : "+f"(c[0]), "+f"(c[1]), "+f"(c[2]), "+f"(c[3])
        : "r"(a0), "r"(a1), "r"(a2), "r"(a3), "r"(b0), "r"(b1));
}

__device__ __forceinline__ void cp16(void* smem_dst, const void* gsrc) {
    unsigned d = (unsigned)__cvta_generic_to_shared(smem_dst);
    asm volatile("cp.async.ca.shared.global [%0], [%1], 16;" :: "r"(d), "l"(gsrc));
}
__device__ __forceinline__ void cp_commit() { asm volatile("cp.async.commit_group;"); }
template<int N> __device__ __forceinline__ void cp_wait() {
    asm volatile("cp.async.wait_group %0;" :: "n"(N));
}

// ---------------------------------------------------------------------------
// Kernel 0: LN1(Z) -> g_zln (tf32 bits, [c][row]); block 0 also converts W_op.
// ---------------------------------------------------------------------------
extern "C" __global__ void __launch_bounds__(256)
ln1_kernel(const float* __restrict__ Z, const float* __restrict__ g1v,
           const float* __restrict__ b1v, const float* __restrict__ Wop)
{
    extern __shared__ float sf[];
    float* sZ  = sf;                // [128 c][129 r]
    float* mus = sZ + 128*129;
    float* rss = mus + 128;
    float* g1s = rss + 128;
    float* b1s = g1s + 128;

    const int t = threadIdx.x;
    const int rbase = blockIdx.x * 128;

    if (blockIdx.x == 0)
        for (int idx = t; idx < 128*128; idx += 256)
            g_wop[idx] = f2tf32(Wop[idx]);

    for (int idx = t; idx < 128*128; idx += 256) {
        int r = idx >> 7, c = idx & 127;
        sZ[c*129 + r] = Z[(size_t)(rbase + r)*128 + c];
    }
    if (t < 128) { g1s[t] = g1v[t]; b1s[t] = b1v[t]; }
    __syncthreads();

    {
        int r = t >> 1, h = t & 1;
        float s = 0.f, s2 = 0.f;
        #pragma unroll 8
        for (int c = h*64; c < h*64 + 64; ++c) {
            float v = sZ[c*129 + r]; s += v; s2 += v*v;
        }
        s  += __shfl_xor_sync(0xffffffffu, s,  1);
        s2 += __shfl_xor_sync(0xffffffffu, s2, 1);
        if (h == 0) {
            float mu = s * (1.f/128.f);
            float var = s2 * (1.f/128.f) - mu*mu;
            mus[r] = mu; rss[r] = rsqrtf(var + 1e-5f);
        }
    }
    __syncthreads();

    for (int idx = t; idx < 128*128; idx += 256) {
        int c = idx >> 7, r = idx & 127;
        float v = (sZ[c*129 + r] - mus[r]) * rss[r] * g1s[c] + b1s[c];
        g_zln[(size_t)c*MROWS + rbase + r] = f2tf32(v);
    }
}

// ---------------------------------------------------------------------------
// Kernel 1: persistent projections + gating, tf32 tensor cores.
// 150 blocks x 512 thr: bx<60 -> left-dual, <120 -> right-dual, else og.
// left/right stored bf16; gate stored f32.
// ---------------------------------------------------------------------------
extern "C" __global__ void __launch_bounds__(512)
proj_kernel(const float* __restrict__ mask,
            const float* __restrict__ Wlr, const float* __restrict__ blr,
            const float* __restrict__ Wg,  const float* __restrict__ bg,
            const float* __restrict__ Wog, const float* __restrict__ bog)
{
    extern __shared__ unsigned smu[];
    unsigned* W1 = smu;                 // [128 k][136 n]
    unsigned* W2 = W1 + 128*136;        // [128 k][136 n]
    unsigned* As = W2 + 128*136;        // [2][128 k][72 m]
    float* bb1 = (float*)(As + 2*128*72);
    float* bb2 = bb1 + 128;

    const int t = threadIdx.x, bx = blockIdx.x;
    int cg, ms, stride;
    if      (bx < 60)  { cg = 0; ms = bx;       stride = 60; }
    else if (bx < 120) { cg = 1; ms = bx - 60;  stride = 60; }
    else               { cg = 2; ms = bx - 120; stride = 30; }
    const bool dual = (cg < 2);

    if (dual) {
        int cb = cg * 128;
        for (int idx = t; idx < 128*128; idx += 512) {
            int k = idx >> 7, j = idx & 127;
            W1[k*136 + j] = f2tf32(Wlr[k*256 + cb + j]);
            W2[k*136 + j] = f2tf32(Wg [k*256 + cb + j]);
        }
        if (t < 128) { bb1[t] = blr[cg*128 + t]; bb2[t] = bg[cg*128 + t]; }
    } else {
        for (int idx = t; idx < 128*128; idx += 512) {
            int k = idx >> 7, j = idx & 127;
            W1[k*136 + j] = f2tf32(Wog[k*128 + j]);
        }
        if (t < 128) bb1[t] = bog[t];
    }

    const int lane = t & 31, w = t >> 5;
    const int wm = w & 1, wn = w >> 1;      // 2 m-warps x 8 n-warps
    const int tig = lane & 3, grp = lane >> 2;

    __nv_bfloat16* dstb = (cg == 0) ? g_leftb : g_rightb;

    int tile = ms;
    {
        int m0 = tile * 64;
        #pragma unroll
        for (int i = 0; i < 4; ++i) {
            int idx = t + 512*i;
            int c = idx >> 4, seg = idx & 15;
            cp16(As + c*72 + seg*4, g_zln + (size_t)c*MROWS + m0 + seg*4);
        }
        cp_commit();
    }
    int buf = 0;

    for (; tile < 4096; tile += stride) {
        int nxt = tile + stride;
        if (nxt < 4096) {
            int m0 = nxt * 64;
            unsigned* db = As + (buf^1)*128*72;
            #pragma unroll
            for (int i = 0; i < 4; ++i) {
                int idx = t + 512*i;
                int c = idx >> 4, seg = idx & 15;
                cp16(db + c*72 + seg*4, g_zln + (size_t)c*MROWS + m0 + seg*4);
            }
            cp_commit();
            cp_wait<1>();
        } else {
            cp_wait<0>();
        }
        __syncthreads();

        const unsigned* A = As + buf*128*72;

        float acc1[2][2][4], acc2[2][2][4];
        #pragma unroll
        for (int mt = 0; mt < 2; ++mt)
            #pragma unroll
            for (int nt = 0; nt < 2; ++nt)
                #pragma unroll
                for (int q = 0; q < 4; ++q) { acc1[mt][nt][q] = 0.f; acc2[mt][nt][q] = 0.f; }

        if (dual) {
            #pragma unroll
            for (int k0 = 0; k0 < 128; k0 += 8) {
                unsigned af[2][4];
                #pragma unroll
                for (int mt = 0; mt < 2; ++mt) {
                    int ar = wm*32 + mt*16 + grp;
                    af[mt][0] = A[(k0+tig  )*72 + ar];
                    af[mt][1] = A[(k0+tig  )*72 + ar + 8];
                    af[mt][2] = A[(k0+tig+4)*72 + ar];
                    af[mt][3] = A[(k0+tig+4)*72 + ar + 8];
                }
                #pragma unroll
                for (int nt = 0; nt < 2; ++nt) {
                    int bc = wn*16 + nt*8 + grp;
                    unsigned b0 = W1[(k0+tig)*136 + bc], b1 = W1[(k0+tig+4)*136 + bc];
                    mma_tf32(acc1[0][nt], af[0][0], af[0][1], af[0][2], af[0][3], b0, b1);
                    mma_tf32(acc1[1][nt], af[1][0], af[1][1], af[1][2], af[1][3], b0, b1);
                    unsigned c0 = W2[(k0+tig)*136 + bc], c1 = W2[(k0+tig+4)*136 + bc];
                    mma_tf32(acc2[0][nt], af[0][0], af[0][1], af[0][2], af[0][3], c0, c1);
                    mma_tf32(acc2[1][nt], af[1][0], af[1][1], af[1][2], af[1][3], c0, c1);
                }
            }
        } else {
            #pragma unroll
            for (int k0 = 0; k0 < 128; k0 += 8) {
                unsigned af[2][4];
                #pragma unroll
                for (int mt = 0; mt < 2; ++mt) {
                    int ar = wm*32 + mt*16 + grp;
                    af[mt][0] = A[(k0+tig  )*72 + ar];
                    af[mt][1] = A[(k0+tig  )*72 + ar + 8];
                    af[mt][2] = A[(k0+tig+4)*72 + ar];
                    af[mt][3] = A[(k0+tig+4)*72 + ar + 8];
                }
                #pragma unroll
                for (int nt = 0; nt < 2; ++nt) {
                    int bc = wn*16 + nt*8 + grp;
                    unsigned b0 = W1[(k0+tig)*136 + bc], b1 = W1[(k0+tig+4)*136 + bc];
                    mma_tf32(acc1[0][nt], af[0][0], af[0][1], af[0][2], af[0][3], b0, b1);
                    mma_tf32(acc1[1][nt], af[1][0], af[1][1], af[1][2], af[1][3], b0, b1);
                }
            }
        }

        const int rb = tile * 64;
        #pragma unroll
        for (int mt = 0; mt < 2; ++mt) {
            #pragma unroll
            for (int nt = 0; nt < 2; ++nt) {
                #pragma unroll
                for (int q = 0; q < 4; ++q) {
                    int r  = wm*32 + mt*16 + grp + ((q >= 2) ? 8 : 0);
                    int oc = wn*16 + nt*8 + tig*2 + (q & 1);
                    if (dual) {
                        float mv  = __ldg(&mask[rb + r]);
                        float lrv = acc1[mt][nt][q] + bb1[oc];
                        float gtv = acc2[mt][nt][q] + bb2[oc];
                        dstb[(size_t)oc*MROWS + rb + r] =
                            __float2bfloat16(lrv * mv * sigmoidf_(gtv));
                    } else {
                        g_gate[(size_t)oc*MROWS + rb + r] =
                            sigmoidf_(acc1[mt][nt][q] + bb1[oc]);
                    }
                }
            }
        }
        __syncthreads();
        buf ^= 1;
    }
}

// ---------------------------------------------------------------------------
// Kernel 2: p[c] = L_c @ R_c^T via bf16 mma.m16n8k16 (tensor cores).
// grid (4,4,128), block 256 (8 warps 4x2), tile 128x128, 16 k per chunk.
// smem u32 = packed bf16 k-pair, [kp][row] ld=136 (conflict-free).
// ---------------------------------------------------------------------------
extern "C" __global__ void __launch_bounds__(256, 2)
einsum_kernel()
{
    __shared__ unsigned As[2][8][136];
    __shared__ unsigned Bs[2][8][136];

    const int t = threadIdx.x;
    const int lane = t & 31;
    const int w = t >> 5;
    const int wm = w & 3;
    const int wn = w >> 2;
    const int jbase = blockIdx.x * 128;
    const int ibase = blockIdx.y * 128;
    const int c = blockIdx.z;

    const __nv_bfloat16* A = g_leftb  + (size_t)c*MROWS;   // [i][k] 512x512
    const __nv_bfloat16* B = g_rightb + (size_t)c*MROWS;   // [j][k] 512x512

    const int lrow = t >> 1;
    const int lkb  = (t & 1) * 8;     // element offset (8 bf16 = 16B)
    const int lkp  = (t & 1) * 4;     // u32-pair offset

    const __nv_bfloat16* Ap = A + (size_t)(ibase + lrow)*512 + lkb;
    const __nv_bfloat16* Bp = B + (size_t)(jbase + lrow)*512 + lkb;

    const int tig = lane & 3;
    const int grp = lane >> 2;

    float acc[2][8][4];
    #pragma unroll
    for (int mt = 0; mt < 2; ++mt)
        #pragma unroll
        for (int nt = 0; nt < 8; ++nt)
            #pragma unroll
            for (int q = 0; q < 4; ++q) acc[mt][nt][q] = 0.f;

    uint4 av = *(const uint4*)(Ap);
    uint4 bv = *(const uint4*)(Bp);

    int buf = 0;
    {
        As[0][lkp+0][lrow] = av.x; As[0][lkp+1][lrow] = av.y;
        As[0][lkp+2][lrow] = av.z; As[0][lkp+3][lrow] = av.w;
        Bs[0][lkp+0][lrow] = bv.x; Bs[0][lkp+1][lrow] = bv.y;
        Bs[0][lkp+2][lrow] = bv.z; Bs[0][lkp+3][lrow] = bv.w;
    }
    __syncthreads();

    for (int k0 = 0; k0 < 512; k0 += 16) {
        const bool more = (k0 + 16) < 512;
        if (more) {
            av = *(const uint4*)(Ap + k0 + 16);
            bv = *(const uint4*)(Bp + k0 + 16);
        }

        unsigned af[2][4], bf[8][2];
        #pragma unroll
        for (int mt = 0; mt < 2; ++mt) {
            int arow = wm*32 + mt*16 + grp;
            af[mt][0] = As[buf][tig    ][arow    ];
            af[mt][1] = As[buf][tig    ][arow + 8];
            af[mt][2] = As[buf][tig + 4][arow    ];
            af[mt][3] = As[buf][tig + 4][arow + 8];
        }
        #pragma unroll
        for (int nt = 0; nt < 8; ++nt) {
            int bcol = wn*64 + nt*8 + grp;
            bf[nt][0] = Bs[buf][tig    ][bcol];
            bf[nt][1] = Bs[buf][tig + 4][bcol];
        }
        #pragma unroll
        for (int mt = 0; mt < 2; ++mt)
            #pragma unroll
            for (int nt = 0; nt < 8; ++nt)
                mma_bf16(acc[mt][nt], af[mt][0], af[mt][1], af[mt][2], af[mt][3],
                         bf[nt][0], bf[nt][1]);

        if (more) {
            int nb = buf ^ 1;
            As[nb][lkp+0][lrow] = av.x; As[nb][lkp+1][lrow] = av.y;
            As[nb][lkp+2][lrow] = av.z; As[nb][lkp+3][lrow] = av.w;
            Bs[nb][lkp+0][lrow] = bv.x; Bs[nb][lkp+1][lrow] = bv.y;
            Bs[nb][lkp+2][lrow] = bv.z; Bs[nb][lkp+3][lrow] = bv.w;
            __syncthreads();
            buf ^= 1;
        }
    }

    float* P = g_p + (size_t)c*MROWS;
    #pragma unroll
    for (int mt = 0; mt < 2; ++mt) {
        int i0 = ibase + wm*32 + mt*16 + grp;
        #pragma unroll
        for (int nt = 0; nt < 8; ++nt) {
            int j0 = jbase + wn*64 + nt*8 + tig*2;
            float2 v01 = make_float2(acc[mt][nt][0], acc[mt][nt][1]);
            float2 v23 = make_float2(acc[mt][nt][2], acc[mt][nt][3]);
            *(float2*)&P[(size_t)i0*512 + j0]     = v01;
            *(float2*)&P[(size_t)(i0+8)*512 + j0] = v23;
        }
    }
}

// ---------------------------------------------------------------------------
// Kernel 3: LN2 + (pln @ W_op) + gate + residual. Non-persistent 64-row tiles,
// grid 4096, block 256, ~110 KB smem -> 2 blocks/SM.
// ---------------------------------------------------------------------------
extern "C" __global__ void __launch_bounds__(256)
final_kernel(const float* __restrict__ Z,
             const float* __restrict__ g2v, const float* __restrict__ b2v,
             const float* __restrict__ obias, float* __restrict__ out)
{
    extern __shared__ unsigned smu[];
    unsigned* Ws = smu;                   // [128 c][136 d] tf32
    unsigned* Pu = Ws + 128*136;          // [128 c][72 r] (float, then tf32)
    float* Pf  = (float*)Pu;
    float* ps1 = (float*)(Pu + 128*72);   // [4][64] partial sums
    float* ps2 = ps1 + 4*64;
    float* g2s = ps2 + 4*64;              // 128
    float* b2s = g2s + 128;
    float* obs = b2s + 128;
    float* mus = obs + 128;               // 64
    float* rss = mus + 64;                // 64

    const int t  = threadIdx.x;
    const int rb = blockIdx.x * 64;

    // cp.async: W_op tile (tf32, pre-converted) + P tile
    #pragma unroll
    for (int i = 0; i < 16; ++i) {
        int idx = t + 256*i;              // 0..4095
        int c = idx >> 5, seg = idx & 31;
        cp16(Ws + c*136 + seg*4, g_wop + c*128 + seg*4);
    }
    #pragma unroll
    for (int i = 0; i < 8; ++i) {
        int idx = t + 256*i;              // 0..2047
        int c = idx >> 4, seg = idx & 15;
        cp16(Pf + c*72 + seg*4, g_p + (size_t)c*MROWS + rb + seg*4);
    }
    cp_commit();
    if (t < 128) { g2s[t] = g2v[t]; b2s[t] = b2v[t]; obs[t] = obias[t]; }
    cp_wait<0>();
    __syncthreads();

    // LN partials: warp lanes sweep rows (conflict-free)
    {
        int h = t >> 6, r = t & 63;
        float s = 0.f, s2 = 0.f;
        #pragma unroll 8
        for (int cc = 0; cc < 32; ++cc) {
            float v = Pf[(h*32 + cc)*72 + r]; s += v; s2 += v*v;
        }
        ps1[h*64 + r] = s; ps2[h*64 + r] = s2;
    }
    __syncthreads();
    if (t < 64) {
        float s  = ps1[t] + ps1[64+t] + ps1[128+t] + ps1[192+t];
        float s2 = ps2[t] + ps2[64+t] + ps2[128+t] + ps2[192+t];
        float mu = s * (1.f/128.f);
        float var = s2 * (1.f/128.f) - mu*mu;
        mus[t] = mu; rss[t] = rsqrtf(var + 1e-5f);
    }
    __syncthreads();
    for (int idx = t; idx < 64*128; idx += 256) {
        int r = idx & 63, c = idx >> 6;
        Pu[c*72 + r] = f2tf32((Pf[c*72 + r] - mus[r]) * rss[r] * g2s[c] + b2s[c]);
    }
    __syncthreads();

    // GEMM: M=64(r), N=128(d), K=128(c); 8 warps = 2m x 4n
    const int lane = t & 31, w = t >> 5;
    const int wm = w & 1, wn = w >> 1;
    const int tig = lane & 3, grp = lane >> 2;

    float acc[2][4][4];
    #pragma unroll
    for (int mt = 0; mt < 2; ++mt)
        #pragma unroll
        for (int nt = 0; nt < 4; ++nt)
            #pragma unroll
            for (int q = 0; q < 4; ++q) acc[mt][nt][q] = 0.f;

    #pragma unroll
    for (int k0 = 0; k0 < 128; k0 += 8) {
        unsigned af[2][4];
        #pragma unroll
        for (int mt = 0; mt < 2; ++mt) {
            int ar = wm*32 + mt*16 + grp;
            af[mt][0] = Pu[(k0+tig  )*72 + ar];
            af[mt][1] = Pu[(k0+tig  )*72 + ar + 8];
            af[mt][2] = Pu[(k0+tig+4)*72 + ar];
            af[mt][3] = Pu[(k0+tig+4)*72 + ar + 8];
        }
        #pragma unroll
        for (int nt = 0; nt < 4; ++nt) {
            int bc = wn*32 + nt*8 + grp;
            unsigned b0 = Ws[(k0+tig)*136 + bc], b1 = Ws[(k0+tig+4)*136 + bc];
            mma_tf32(acc[0][nt], af[0][0], af[0][1], af[0][2], af[0][3], b0, b1);
            mma_tf32(acc[1][nt], af[1][0], af[1][1], af[1][2], af[1][3], b0, b1);
        }
    }
    __syncthreads();   // done reading Pu; reuse as staging [r][129]

    float* Sout = Pf;
    #pragma unroll
    for (int mt = 0; mt < 2; ++mt) {
        #pragma unroll
        for (int nt = 0; nt < 4; ++nt) {
            #pragma unroll
            for (int q = 0; q < 4; ++q) {
                int r = wm*32 + mt*16 + grp + ((q >= 2) ? 8 : 0);
                int d = wn*32 + nt*8 + tig*2 + (q & 1);
                float gv = __ldg(&g_gate[(size_t)d*MROWS + rb + r]);
                Sout[r*129 + d] = gv * (acc[mt][nt][q] + obs[d]);
            }
        }
    }
    __syncthreads();

    for (int idx = t; idx < 64*128; idx += 256) {
        int r = idx >> 7, d = idx & 127;
        size_t gi = (size_t)(rb + r)*128 + d;
        out[gi] = Z[gi] + Sout[r*129 + d];
    }
}

// ---------------------------------------------------------------------------
extern "C" void kernel_launch(void* const* d_in, const int* in_sizes, int n_in,
                              void* d_out, int out_size)
{
    const float* Zr   = (const float*)d_in[0];
    const float* mask = (const float*)d_in[1];
    const float* g1   = (const float*)d_in[2];
    const float* b1   = (const float*)d_in[3];
    const float* Wlr  = (const float*)d_in[4];
    const float* blr  = (const float*)d_in[5];
    const float* Wg   = (const float*)d_in[6];
    const float* bg   = (const float*)d_in[7];
    const float* Wog  = (const float*)d_in[8];
    const float* bog  = (const float*)d_in[9];
    const float* g2   = (const float*)d_in[10];
    const float* b2   = (const float*)d_in[11];
    const float* Wop  = (const float*)d_in[12];
    const float* ob   = (const float*)d_in[13];
    float* out = (float*)d_out;

    const size_t sm0 = (size_t)(128*129 + 4*128) * 4;                       // ~68 KB
    const size_t sm1 = (size_t)(2*128*136 + 2*128*72 + 2*128) * 4;          // ~214 KB
    const size_t sm3 = (size_t)(128*136 + 128*72 + 8*64 + 3*128 + 2*64)*4;  // ~110 KB
    cudaFuncSetAttribute(ln1_kernel,   cudaFuncAttributeMaxDynamicSharedMemorySize, (int)sm0);
    cudaFuncSetAttribute(proj_kernel,  cudaFuncAttributeMaxDynamicSharedMemorySize, (int)sm1);
    cudaFuncSetAttribute(final_kernel, cudaFuncAttributeMaxDynamicSharedMemorySize, (int)sm3);

    ln1_kernel<<<2048, 256, sm0>>>(Zr, g1, b1, Wop);
    proj_kernel<<<150, 512, sm1>>>(mask, Wlr, blr, Wg, bg, Wog, bog);
    einsum_kernel<<<dim3(4, 4, 128), 256>>>();
    final_kernel<<<4096, 256, sm3>>>(Zr, g2, b2, ob, out);
}

// round 7
// speedup vs baseline: 7.0190x; 1.3973x over previous
#include <cuda_runtime.h>
#include <cuda_bf16.h>
#include <math.h>

#define NNDIM 512
#define DDIM  128
#define MROWS (NNDIM*NNDIM)   // 262144 rows of (i,j)

// Scratch (device globals).
__device__ unsigned g_zln  [(size_t)MROWS*64];           // LN1(Z) bf16-pairs, [row][cp]
__device__ __nv_bfloat16 g_leftb [(size_t)DDIM*MROWS];   // [c][row] bf16
__device__ __nv_bfloat16 g_rightb[(size_t)DDIM*MROWS];   // [c][row] bf16
__device__ float    g_gate[(size_t)DDIM*MROWS];          // [c][row] f32
__device__ float    g_p   [(size_t)DDIM*MROWS];          // per-c [i][j] f32
__device__ unsigned g_wop [DDIM*DDIM];                   // W_op tf32 bits, [c][d]

__device__ __forceinline__ float sigmoidf_(float x) { return 1.0f / (1.0f + expf(-x)); }

__device__ __forceinline__ unsigned f2tf32(float x) {
    unsigned r; asm("cvt.rna.tf32.f32 %0, %1;" : "=r"(r) : "f"(x)); return r;
}
__device__ __forceinline__ unsigned packbf(float lo, float hi) {
    unsigned r; asm("cvt.rn.bf16x2.f32 %0, %1, %2;" : "=r"(r) : "f"(hi), "f"(lo)); return r;
}

__device__ __forceinline__ void mma_tf32(float c[4],
    unsigned a0, unsigned a1, unsigned a2, unsigned a3, unsigned b0, unsigned b1)
{
    asm volatile(
        "mma.sync.aligned.m16n8k8.row.col.f32.tf32.tf32.f32 "
        "{%0,%1,%2,%3}, {%4,%5,%6,%7}, {%8,%9}, {%0,%1,%2,%3};"
        : "+f"(c[0]), "+f"(c[1]), "+f"(c[2]), "+f"(c[3])
        : "r"(a0), "r"(a1), "r"(a2), "r"(a3), "r"(b0), "r"(b1));
}
__device__ __forceinline__ void mma_bf16(float c[4],
    unsigned a0, unsigned a1, unsigned a2, unsigned a3, unsigned b0, unsigned b1)
{
    asm volatile(
        "mma.sync.aligned.m16n8k16.row.col.f32.bf16.bf16.f32 "
        "{%0,%1,%2,%3}, {%4,%5,%6,%7}, {%8,%9}, {%0,%1,%2,%3};"
        : "+f"(c[0]), "+f"(c[1]), "+f"(c[2]), "+f"(c[3])
        : "r"(a0), "r"(a1), "r"(a2), "r"(a3), "r"(b0), "r"(b1));
}

__device__ __forceinline__ void cp16(void* smem_dst, const void* gsrc) {
    unsigned d = (unsigned)__cvta_generic_to_shared(smem_dst);
    asm volatile("cp.async.ca.shared.global [%0], [%1], 16;" :: "r"(d), "l"(gsrc));
}
__device__ __forceinline__ void cp_commit() { asm volatile("cp.async.commit_group;"); }
template<int N> __device__ __forceinline__ void cp_wait() {
    asm volatile("cp.async.wait_group %0;" :: "n"(N));
}

// ---------------------------------------------------------------------------
// Kernel 0: LN1(Z) -> g_zln (bf16 pairs, [row][cp]). Warp-per-row, no smem.
// Block 0 also converts W_op -> g_wop (tf32).
// ---------------------------------------------------------------------------
extern "C" __global__ void __launch_bounds__(256)
ln1_kernel(const float* __restrict__ Z, const float* __restrict__ g1v,
           const float* __restrict__ b1v, const float* __restrict__ Wop)
{
    const int t = threadIdx.x, lane = t & 31, wid = t >> 5;

    if (blockIdx.x == 0) {
        for (int idx = t; idx < 128*128; idx += 256)
            g_wop[idx] = f2tf32(Wop[idx]);
    }

    const size_t row = (size_t)blockIdx.x * 8 + wid;
    const float4 v  = *(const float4*)&Z[row*128 + lane*4];
    const float4 gv = *(const float4*)&g1v[lane*4];
    const float4 bv = *(const float4*)&b1v[lane*4];

    float s  = v.x + v.y + v.z + v.w;
    float s2 = v.x*v.x + v.y*v.y + v.z*v.z + v.w*v.w;
    #pragma unroll
    for (int o = 16; o > 0; o >>= 1) {
        s  += __shfl_xor_sync(0xffffffffu, s,  o);
        s2 += __shfl_xor_sync(0xffffffffu, s2, o);
    }
    float mu = s * (1.f/128.f);
    float rs = rsqrtf(s2 * (1.f/128.f) - mu*mu + 1e-5f);

    float n0 = (v.x - mu) * rs * gv.x + bv.x;
    float n1 = (v.y - mu) * rs * gv.y + bv.y;
    float n2 = (v.z - mu) * rs * gv.z + bv.z;
    float n3 = (v.w - mu) * rs * gv.w + bv.w;

    uint2 o2 = make_uint2(packbf(n0, n1), packbf(n2, n3));
    *(uint2*)&g_zln[row*64 + lane*2] = o2;
}

// ---------------------------------------------------------------------------
// Kernel 1: persistent projections + gating, bf16 tensor cores.
// 300 blocks x 512 thr: bx<120 -> left-dual, <240 -> right-dual, else og.
// Weights resident (bf16 pairs, [kp][136]); 64-row A tiles cp.async
// double-buffered into [row][68] (conflict-free frag loads + 16B stores).
// ---------------------------------------------------------------------------
extern "C" __global__ void __launch_bounds__(512)
proj_kernel(const float* __restrict__ mask,
            const float* __restrict__ Wlr, const float* __restrict__ blr,
            const float* __restrict__ Wg,  const float* __restrict__ bg,
            const float* __restrict__ Wog, const float* __restrict__ bog)
{
    extern __shared__ unsigned smu[];
    unsigned* W1 = smu;                 // [64 kp][136 n]
    unsigned* W2 = W1 + 64*136;         // [64 kp][136 n]
    unsigned* As = W2 + 64*136;         // [2][64 row][68 kp]
    float* bb1 = (float*)(As + 2*64*68);
    float* bb2 = bb1 + 128;

    const int t = threadIdx.x, bx = blockIdx.x;
    int cg, ms, stride;
    if      (bx < 120) { cg = 0; ms = bx;       stride = 120; }
    else if (bx < 240) { cg = 1; ms = bx - 120; stride = 120; }
    else               { cg = 2; ms = bx - 240; stride = 60;  }
    const bool dual = (cg < 2);

    if (dual) {
        int cb = cg * 128;
        for (int idx = t; idx < 64*128; idx += 512) {
            int kp = idx >> 7, j = idx & 127;
            W1[kp*136 + j] = packbf(Wlr[(2*kp)*256 + cb + j], Wlr[(2*kp+1)*256 + cb + j]);
            W2[kp*136 + j] = packbf(Wg [(2*kp)*256 + cb + j], Wg [(2*kp+1)*256 + cb + j]);
        }
        if (t < 128) { bb1[t] = blr[cg*128 + t]; bb2[t] = bg[cg*128 + t]; }
    } else {
        for (int idx = t; idx < 64*128; idx += 512) {
            int kp = idx >> 7, j = idx & 127;
            W1[kp*136 + j] = packbf(Wog[(2*kp)*128 + j], Wog[(2*kp+1)*128 + j]);
        }
        if (t < 128) bb1[t] = bog[t];
    }

    const int lane = t & 31, w = t >> 5;
    const int wm = w & 1, wn = w >> 1;      // 2 m-warps x 8 n-warps
    const int tig = lane & 3, grp = lane >> 2;

    __nv_bfloat16* dstb = (cg == 0) ? g_leftb : g_rightb;

    int tile = ms;
    {   // prefetch first tile (64 rows x 64 kp u32 = contiguous per-row copies)
        int m0 = tile * 64;
        #pragma unroll
        for (int i = 0; i < 2; ++i) {
            int idx = t + 512*i;            // 0..1023
            int r = idx >> 4, kq = idx & 15;
            cp16(As + r*68 + kq*4, g_zln + (size_t)(m0 + r)*64 + kq*4);
        }
        cp_commit();
    }
    int buf = 0;

    for (; tile < 4096; tile += stride) {
        int nxt = tile + stride;
        if (nxt < 4096) {
            int m0 = nxt * 64;
            unsigned* db = As + (buf^1)*64*68;
            #pragma unroll
            for (int i = 0; i < 2; ++i) {
                int idx = t + 512*i;
                int r = idx >> 4, kq = idx & 15;
                cp16(db + r*68 + kq*4, g_zln + (size_t)(m0 + r)*64 + kq*4);
            }
            cp_commit();
            cp_wait<1>();
        } else {
            cp_wait<0>();
        }
        __syncthreads();

        const unsigned* A = As + buf*64*68;

        float acc1[2][2][4], acc2[2][2][4];
        #pragma unroll
        for (int mt = 0; mt < 2; ++mt)
            #pragma unroll
            for (int nt = 0; nt < 2; ++nt)
                #pragma unroll
                for (int q = 0; q < 4; ++q) { acc1[mt][nt][q] = 0.f; acc2[mt][nt][q] = 0.f; }

        if (dual) {
            #pragma unroll
            for (int kp0 = 0; kp0 < 64; kp0 += 8) {
                unsigned af[2][4];
                #pragma unroll
                for (int mt = 0; mt < 2; ++mt) {
                    int ar = wm*32 + mt*16 + grp;
                    af[mt][0] = A[ ar     *68 + kp0 + tig];
                    af[mt][1] = A[(ar + 8)*68 + kp0 + tig];
                    af[mt][2] = A[ ar     *68 + kp0 + tig + 4];
                    af[mt][3] = A[(ar + 8)*68 + kp0 + tig + 4];
                }
                #pragma unroll
                for (int nt = 0; nt < 2; ++nt) {
                    int bc = wn*16 + nt*8 + grp;
                    unsigned b0 = W1[(kp0+tig)*136 + bc], b1 = W1[(kp0+tig+4)*136 + bc];
                    mma_bf16(acc1[0][nt], af[0][0], af[0][1], af[0][2], af[0][3], b0, b1);
                    mma_bf16(acc1[1][nt], af[1][0], af[1][1], af[1][2], af[1][3], b0, b1);
                    unsigned c0 = W2[(kp0+tig)*136 + bc], c1 = W2[(kp0+tig+4)*136 + bc];
                    mma_bf16(acc2[0][nt], af[0][0], af[0][1], af[0][2], af[0][3], c0, c1);
                    mma_bf16(acc2[1][nt], af[1][0], af[1][1], af[1][2], af[1][3], c0, c1);
                }
            }
        } else {
            #pragma unroll
            for (int kp0 = 0; kp0 < 64; kp0 += 8) {
                unsigned af[2][4];
                #pragma unroll
                for (int mt = 0; mt < 2; ++mt) {
                    int ar = wm*32 + mt*16 + grp;
                    af[mt][0] = A[ ar     *68 + kp0 + tig];
                    af[mt][1] = A[(ar + 8)*68 + kp0 + tig];
                    af[mt][2] = A[ ar     *68 + kp0 + tig + 4];
                    af[mt][3] = A[(ar + 8)*68 + kp0 + tig + 4];
                }
                #pragma unroll
                for (int nt = 0; nt < 2; ++nt) {
                    int bc = wn*16 + nt*8 + grp;
                    unsigned b0 = W1[(kp0+tig)*136 + bc], b1 = W1[(kp0+tig+4)*136 + bc];
                    mma_bf16(acc1[0][nt], af[0][0], af[0][1], af[0][2], af[0][3], b0, b1);
                    mma_bf16(acc1[1][nt], af[1][0], af[1][1], af[1][2], af[1][3], b0, b1);
                }
            }
        }

        const int rb = tile * 64;
        #pragma unroll
        for (int mt = 0; mt < 2; ++mt) {
            #pragma unroll
            for (int nt = 0; nt < 2; ++nt) {
                #pragma unroll
                for (int q = 0; q < 4; ++q) {
                    int r  = wm*32 + mt*16 + grp + ((q >= 2) ? 8 : 0);
                    int oc = wn*16 + nt*8 + tig*2 + (q & 1);
                    if (dual) {
                        float mv  = __ldg(&mask[rb + r]);
                        float lrv = acc1[mt][nt][q] + bb1[oc];
                        float gtv = acc2[mt][nt][q] + bb2[oc];
                        dstb[(size_t)oc*MROWS + rb + r] =
                            __float2bfloat16(lrv * mv * sigmoidf_(gtv));
                    } else {
                        g_gate[(size_t)oc*MROWS + rb + r] =
                            sigmoidf_(acc1[mt][nt][q] + bb1[oc]);
                    }
                }
            }
        }
        __syncthreads();
        buf ^= 1;
    }
}

// ---------------------------------------------------------------------------
// Kernel 2: p[c] = L_c @ R_c^T via bf16 mma.m16n8k16 (unchanged from R5).
// ---------------------------------------------------------------------------
extern "C" __global__ void __launch_bounds__(256, 2)
einsum_kernel()
{
    __shared__ unsigned As[2][8][136];
    __shared__ unsigned Bs[2][8][136];

    const int t = threadIdx.x;
    const int lane = t & 31;
    const int w = t >> 5;
    const int wm = w & 3;
    const int wn = w >> 2;
    const int jbase = blockIdx.x * 128;
    const int ibase = blockIdx.y * 128;
    const int c = blockIdx.z;

    const __nv_bfloat16* A = g_leftb  + (size_t)c*MROWS;
    const __nv_bfloat16* B = g_rightb + (size_t)c*MROWS;

    const int lrow = t >> 1;
    const int lkb  = (t & 1) * 8;
    const int lkp  = (t & 1) * 4;

    const __nv_bfloat16* Ap = A + (size_t)(ibase + lrow)*512 + lkb;
    const __nv_bfloat16* Bp = B + (size_t)(jbase + lrow)*512 + lkb;

    const int tig = lane & 3;
    const int grp = lane >> 2;

    float acc[2][8][4];
    #pragma unroll
    for (int mt = 0; mt < 2; ++mt)
        #pragma unroll
        for (int nt = 0; nt < 8; ++nt)
            #pragma unroll
            for (int q = 0; q < 4; ++q) acc[mt][nt][q] = 0.f;

    uint4 av = *(const uint4*)(Ap);
    uint4 bv = *(const uint4*)(Bp);

    int buf = 0;
    {
        As[0][lkp+0][lrow] = av.x; As[0][lkp+1][lrow] = av.y;
        As[0][lkp+2][lrow] = av.z; As[0][lkp+3][lrow] = av.w;
        Bs[0][lkp+0][lrow] = bv.x; Bs[0][lkp+1][lrow] = bv.y;
        Bs[0][lkp+2][lrow] = bv.z; Bs[0][lkp+3][lrow] = bv.w;
    }
    __syncthreads();

    for (int k0 = 0; k0 < 512; k0 += 16) {
        const bool more = (k0 + 16) < 512;
        if (more) {
            av = *(const uint4*)(Ap + k0 + 16);
            bv = *(const uint4*)(Bp + k0 + 16);
        }

        unsigned af[2][4], bf[8][2];
        #pragma unroll
        for (int mt = 0; mt < 2; ++mt) {
            int arow = wm*32 + mt*16 + grp;
            af[mt][0] = As[buf][tig    ][arow    ];
            af[mt][1] = As[buf][tig    ][arow + 8];
            af[mt][2] = As[buf][tig + 4][arow    ];
            af[mt][3] = As[buf][tig + 4][arow + 8];
        }
        #pragma unroll
        for (int nt = 0; nt < 8; ++nt) {
            int bcol = wn*64 + nt*8 + grp;
            bf[nt][0] = Bs[buf][tig    ][bcol];
            bf[nt][1] = Bs[buf][tig + 4][bcol];
        }
        #pragma unroll
        for (int mt = 0; mt < 2; ++mt)
            #pragma unroll
            for (int nt = 0; nt < 8; ++nt)
                mma_bf16(acc[mt][nt], af[mt][0], af[mt][1], af[mt][2], af[mt][3],
                         bf[nt][0], bf[nt][1]);

        if (more) {
            int nb = buf ^ 1;
            As[nb][lkp+0][lrow] = av.x; As[nb][lkp+1][lrow] = av.y;
            As[nb][lkp+2][lrow] = av.z; As[nb][lkp+3][lrow] = av.w;
            Bs[nb][lkp+0][lrow] = bv.x; Bs[nb][lkp+1][lrow] = bv.y;
            Bs[nb][lkp+2][lrow] = bv.z; Bs[nb][lkp+3][lrow] = bv.w;
            __syncthreads();
            buf ^= 1;
        }
    }

    float* P = g_p + (size_t)c*MROWS;
    #pragma unroll
    for (int mt = 0; mt < 2; ++mt) {
        int i0 = ibase + wm*32 + mt*16 + grp;
        #pragma unroll
        for (int nt = 0; nt < 8; ++nt) {
            int j0 = jbase + wn*64 + nt*8 + tig*2;
            float2 v01 = make_float2(acc[mt][nt][0], acc[mt][nt][1]);
            float2 v23 = make_float2(acc[mt][nt][2], acc[mt][nt][3]);
            *(float2*)&P[(size_t)i0*512 + j0]     = v01;
            *(float2*)&P[(size_t)(i0+8)*512 + j0] = v23;
        }
    }
}

// ---------------------------------------------------------------------------
// Kernel 3: LN2 + (pln @ W_op, tf32) + gate + residual.
// 64-row tiles, grid 4096, block 512 (16 warps 4m x 4n), ~113 KB -> 2/SM.
// ---------------------------------------------------------------------------
extern "C" __global__ void __launch_bounds__(512)
final_kernel(const float* __restrict__ Z,
             const float* __restrict__ g2v, const float* __restrict__ b2v,
             const float* __restrict__ obias, float* __restrict__ out)
{
    extern __shared__ unsigned smu[];
    unsigned* Ws = smu;                   // [128 c][136 d] tf32
    unsigned* Pu = Ws + 128*136;          // [128 c][72 r] (float, then tf32)
    float* Pf  = (float*)Pu;
    float* ps1 = (float*)(Pu + 128*72);   // [8][64]
    float* ps2 = ps1 + 8*64;
    float* g2s = ps2 + 8*64;              // 128
    float* b2s = g2s + 128;
    float* obs = b2s + 128;
    float* mus = obs + 128;               // 64
    float* rss = mus + 64;                // 64

    const int t  = threadIdx.x;
    const int rb = blockIdx.x * 64;

    #pragma unroll
    for (int i = 0; i < 8; ++i) {
        int idx = t + 512*i;              // 0..4095
        int c = idx >> 5, seg = idx & 31;
        cp16(Ws + c*136 + seg*4, g_wop + c*128 + seg*4);
    }
    #pragma unroll
    for (int i = 0; i < 4; ++i) {
        int idx = t + 512*i;              // 0..2047
        int c = idx >> 4, seg = idx & 15;
        cp16(Pf + c*72 + seg*4, g_p + (size_t)c*MROWS + rb + seg*4);
    }
    cp_commit();
    if (t < 128) { g2s[t] = g2v[t]; b2s[t] = b2v[t]; obs[t] = obias[t]; }
    cp_wait<0>();
    __syncthreads();

    // LN partials over c (8 groups of 16 c's, lanes sweep rows)
    {
        int h = t >> 6, r = t & 63;
        float s = 0.f, s2 = 0.f;
        #pragma unroll
        for (int cc = 0; cc < 16; ++cc) {
            float v = Pf[(h*16 + cc)*72 + r]; s += v; s2 += v*v;
        }
        ps1[h*64 + r] = s; ps2[h*64 + r] = s2;
    }
    __syncthreads();
    if (t < 64) {
        float s = 0.f, s2 = 0.f;
        #pragma unroll
        for (int h = 0; h < 8; ++h) { s += ps1[h*64 + t]; s2 += ps2[h*64 + t]; }
        float mu = s * (1.f/128.f);
        float var = s2 * (1.f/128.f) - mu*mu;
        mus[t] = mu; rss[t] = rsqrtf(var + 1e-5f);
    }
    __syncthreads();
    for (int idx = t; idx < 64*128; idx += 512) {
        int r = idx & 63, c = idx >> 6;
        Pu[c*72 + r] = f2tf32((Pf[c*72 + r] - mus[r]) * rss[r] * g2s[c] + b2s[c]);
    }
    __syncthreads();

    // GEMM: M=64(r), N=128(d), K=128(c); 16 warps = 4m x 4n
    const int lane = t & 31, w = t >> 5;
    const int wm = w & 3, wn = w >> 2;
    const int tig = lane & 3, grp = lane >> 2;

    float acc[4][4];
    #pragma unroll
    for (int nt = 0; nt < 4; ++nt)
        #pragma unroll
        for (int q = 0; q < 4; ++q) acc[nt][q] = 0.f;

    const int ar = wm*16 + grp;
    #pragma unroll
    for (int k0 = 0; k0 < 128; k0 += 8) {
        unsigned a0 = Pu[(k0+tig  )*72 + ar];
        unsigned a1 = Pu[(k0+tig  )*72 + ar + 8];
        unsigned a2 = Pu[(k0+tig+4)*72 + ar];
        unsigned a3 = Pu[(k0+tig+4)*72 + ar + 8];
        #pragma unroll
        for (int nt = 0; nt < 4; ++nt) {
            int bc = wn*32 + nt*8 + grp;
            unsigned b0 = Ws[(k0+tig)*136 + bc], b1 = Ws[(k0+tig+4)*136 + bc];
            mma_tf32(acc[nt], a0, a1, a2, a3, b0, b1);
        }
    }
    __syncthreads();   // done reading Pu; reuse as staging [r][129]

    float* Sout = Pf;
    #pragma unroll
    for (int nt = 0; nt < 4; ++nt) {
        #pragma unroll
        for (int q = 0; q < 4; ++q) {
            int r = wm*16 + grp + ((q >= 2) ? 8 : 0);
            int d = wn*32 + nt*8 + tig*2 + (q & 1);
            float gv = __ldg(&g_gate[(size_t)d*MROWS + rb + r]);
            Sout[r*129 + d] = gv * (acc[nt][q] + obs[d]);
        }
    }
    __syncthreads();

    for (int idx = t; idx < 64*128; idx += 512) {
        int r = idx >> 7, d = idx & 127;
        size_t gi = (size_t)(rb + r)*128 + d;
        out[gi] = Z[gi] + Sout[r*129 + d];
    }
}

// ---------------------------------------------------------------------------
extern "C" void kernel_launch(void* const* d_in, const int* in_sizes, int n_in,
                              void* d_out, int out_size)
{
    const float* Zr   = (const float*)d_in[0];
    const float* mask = (const float*)d_in[1];
    const float* g1   = (const float*)d_in[2];
    const float* b1   = (const float*)d_in[3];
    const float* Wlr  = (const float*)d_in[4];
    const float* blr  = (const float*)d_in[5];
    const float* Wg   = (const float*)d_in[6];
    const float* bg   = (const float*)d_in[7];
    const float* Wog  = (const float*)d_in[8];
    const float* bog  = (const float*)d_in[9];
    const float* g2   = (const float*)d_in[10];
    const float* b2   = (const float*)d_in[11];
    const float* Wop  = (const float*)d_in[12];
    const float* ob   = (const float*)d_in[13];
    float* out = (float*)d_out;

    const size_t sm1 = (size_t)(2*64*136 + 2*64*68 + 256) * 4;              // ~105.5 KB
    const size_t sm3 = (size_t)(128*136 + 128*72 + 16*64 + 3*128 + 2*64)*4; // ~112.6 KB
    cudaFuncSetAttribute(proj_kernel,  cudaFuncAttributeMaxDynamicSharedMemorySize, (int)sm1);
    cudaFuncSetAttribute(final_kernel, cudaFuncAttributeMaxDynamicSharedMemorySize, (int)sm3);

    ln1_kernel<<<32768, 256>>>(Zr, g1, b1, Wop);
    proj_kernel<<<300, 512, sm1>>>(mask, Wlr, blr, Wg, bg, Wog, bog);
    einsum_kernel<<<dim3(4, 4, 128), 256>>>();
    final_kernel<<<4096, 512, sm3>>>(Zr, g2, b2, ob, out);
}

// round 8
// speedup vs baseline: 7.2038x; 1.0263x over previous
#include <cuda_runtime.h>
#include <cuda_bf16.h>
#include <math.h>

#define NNDIM 512
#define DDIM  128
#define MROWS (NNDIM*NNDIM)   // 262144 rows of (i,j)

// Scratch (device globals).
__device__ unsigned g_zln  [(size_t)MROWS*64];           // LN1(Z) bf16-pairs, [row][cp]
__device__ __nv_bfloat16 g_leftb [(size_t)DDIM*MROWS];   // [c][row] bf16
__device__ __nv_bfloat16 g_rightb[(size_t)DDIM*MROWS];   // [c][row] bf16
__device__ float    g_gate[(size_t)DDIM*MROWS];          // [c][row] f32
__device__ float    g_p   [(size_t)DDIM*MROWS];          // per-c [i][j] f32
__device__ unsigned g_wop [DDIM*DDIM];                   // W_op tf32 bits, [c][d]

__device__ __forceinline__ float sigmoidf_(float x) { return 1.0f / (1.0f + expf(-x)); }

__device__ __forceinline__ unsigned f2tf32(float x) {
    unsigned r; asm("cvt.rna.tf32.f32 %0, %1;" : "=r"(r) : "f"(x)); return r;
}
__device__ __forceinline__ unsigned packbf(float lo, float hi) {
    unsigned r; asm("cvt.rn.bf16x2.f32 %0, %1, %2;" : "=r"(r) : "f"(hi), "f"(lo)); return r;
}

__device__ __forceinline__ void mma_tf32(float c[4],
    unsigned a0, unsigned a1, unsigned a2, unsigned a3, unsigned b0, unsigned b1)
{
    asm volatile(
        "mma.sync.aligned.m16n8k8.row.col.f32.tf32.tf32.f32 "
        "{%0,%1,%2,%3}, {%4,%5,%6,%7}, {%8,%9}, {%0,%1,%2,%3};"
        : "+f"(c[0]), "+f"(c[1]), "+f"(c[2]), "+f"(c[3])
        : "r"(a0), "r"(a1), "r"(a2), "r"(a3), "r"(b0), "r"(b1));
}
__device__ __forceinline__ void mma_bf16(float c[4],
    unsigned a0, unsigned a1, unsigned a2, unsigned a3, unsigned b0, unsigned b1)
{
    asm volatile(
        "mma.sync.aligned.m16n8k16.row.col.f32.bf16.bf16.f32 "
        "{%0,%1,%2,%3}, {%4,%5,%6,%7}, {%8,%9}, {%0,%1,%2,%3};"
        : "+f"(c[0]), "+f"(c[1]), "+f"(c[2]), "+f"(c[3])
        : "r"(a0), "r"(a1), "r"(a2), "r"(a3), "r"(b0), "r"(b1));
}

__device__ __forceinline__ void cp16(void* smem_dst, const void* gsrc) {
    unsigned d = (unsigned)__cvta_generic_to_shared(smem_dst);
    asm volatile("cp.async.ca.shared.global [%0], [%1], 16;" :: "r"(d), "l"(gsrc));
}
__device__ __forceinline__ void cp_commit() { asm volatile("cp.async.commit_group;"); }
template<int N> __device__ __forceinline__ void cp_wait() {
    asm volatile("cp.async.wait_group %0;" :: "n"(N));
}

// ---------------------------------------------------------------------------
// Kernel 0: LN1(Z) -> g_zln (bf16 pairs, [row][cp]). Warp-per-row, no smem.
// Block 0 also converts W_op -> g_wop (tf32).
// ---------------------------------------------------------------------------
extern "C" __global__ void __launch_bounds__(256)
ln1_kernel(const float* __restrict__ Z, const float* __restrict__ g1v,
           const float* __restrict__ b1v, const float* __restrict__ Wop)
{
    const int t = threadIdx.x, lane = t & 31, wid = t >> 5;

    if (blockIdx.x == 0) {
        for (int idx = t; idx < 128*128; idx += 256)
            g_wop[idx] = f2tf32(Wop[idx]);
    }

    const size_t row = (size_t)blockIdx.x * 8 + wid;
    const float4 v  = *(const float4*)&Z[row*128 + lane*4];
    const float4 gv = *(const float4*)&g1v[lane*4];
    const float4 bv = *(const float4*)&b1v[lane*4];

    float s  = v.x + v.y + v.z + v.w;
    float s2 = v.x*v.x + v.y*v.y + v.z*v.z + v.w*v.w;
    #pragma unroll
    for (int o = 16; o > 0; o >>= 1) {
        s  += __shfl_xor_sync(0xffffffffu, s,  o);
        s2 += __shfl_xor_sync(0xffffffffu, s2, o);
    }
    float mu = s * (1.f/128.f);
    float rs = rsqrtf(s2 * (1.f/128.f) - mu*mu + 1e-5f);

    float n0 = (v.x - mu) * rs * gv.x + bv.x;
    float n1 = (v.y - mu) * rs * gv.y + bv.y;
    float n2 = (v.z - mu) * rs * gv.z + bv.z;
    float n3 = (v.w - mu) * rs * gv.w + bv.w;

    uint2 o2 = make_uint2(packbf(n0, n1), packbf(n2, n3));
    *(uint2*)&g_zln[row*64 + lane*2] = o2;
}

// ---------------------------------------------------------------------------
// Kernel 1: persistent projections + gating, bf16 tensor cores.
// 300 blocks x 512 thr: bx<120 -> left-dual, <240 -> right-dual, else og.
// ---------------------------------------------------------------------------
extern "C" __global__ void __launch_bounds__(512)
proj_kernel(const float* __restrict__ mask,
            const float* __restrict__ Wlr, const float* __restrict__ blr,
            const float* __restrict__ Wg,  const float* __restrict__ bg,
            const float* __restrict__ Wog, const float* __restrict__ bog)
{
    extern __shared__ unsigned smu[];
    unsigned* W1 = smu;                 // [64 kp][136 n]
    unsigned* W2 = W1 + 64*136;         // [64 kp][136 n]
    unsigned* As = W2 + 64*136;         // [2][64 row][68 kp]
    float* bb1 = (float*)(As + 2*64*68);
    float* bb2 = bb1 + 128;

    const int t = threadIdx.x, bx = blockIdx.x;
    int cg, ms, stride;
    if      (bx < 120) { cg = 0; ms = bx;       stride = 120; }
    else if (bx < 240) { cg = 1; ms = bx - 120; stride = 120; }
    else               { cg = 2; ms = bx - 240; stride = 60;  }
    const bool dual = (cg < 2);

    if (dual) {
        int cb = cg * 128;
        for (int idx = t; idx < 64*128; idx += 512) {
            int kp = idx >> 7, j = idx & 127;
            W1[kp*136 + j] = packbf(Wlr[(2*kp)*256 + cb + j], Wlr[(2*kp+1)*256 + cb + j]);
            W2[kp*136 + j] = packbf(Wg [(2*kp)*256 + cb + j], Wg [(2*kp+1)*256 + cb + j]);
        }
        if (t < 128) { bb1[t] = blr[cg*128 + t]; bb2[t] = bg[cg*128 + t]; }
    } else {
        for (int idx = t; idx < 64*128; idx += 512) {
            int kp = idx >> 7, j = idx & 127;
            W1[kp*136 + j] = packbf(Wog[(2*kp)*128 + j], Wog[(2*kp+1)*128 + j]);
        }
        if (t < 128) bb1[t] = bog[t];
    }

    const int lane = t & 31, w = t >> 5;
    const int wm = w & 1, wn = w >> 1;      // 2 m-warps x 8 n-warps
    const int tig = lane & 3, grp = lane >> 2;

    __nv_bfloat16* dstb = (cg == 0) ? g_leftb : g_rightb;

    int tile = ms;
    {
        int m0 = tile * 64;
        #pragma unroll
        for (int i = 0; i < 2; ++i) {
            int idx = t + 512*i;
            int r = idx >> 4, kq = idx & 15;
            cp16(As + r*68 + kq*4, g_zln + (size_t)(m0 + r)*64 + kq*4);
        }
        cp_commit();
    }
    int buf = 0;

    for (; tile < 4096; tile += stride) {
        int nxt = tile + stride;
        if (nxt < 4096) {
            int m0 = nxt * 64;
            unsigned* db = As + (buf^1)*64*68;
            #pragma unroll
            for (int i = 0; i < 2; ++i) {
                int idx = t + 512*i;
                int r = idx >> 4, kq = idx & 15;
                cp16(db + r*68 + kq*4, g_zln + (size_t)(m0 + r)*64 + kq*4);
            }
            cp_commit();
            cp_wait<1>();
        } else {
            cp_wait<0>();
        }
        __syncthreads();

        const unsigned* A = As + buf*64*68;
        const int rb = tile * 64;

        // prefetch mask values (hide LDG latency under the MMA loop)
        float mpre[2][2];
        if (dual) {
            #pragma unroll
            for (int mt = 0; mt < 2; ++mt)
                #pragma unroll
                for (int h = 0; h < 2; ++h)
                    mpre[mt][h] = __ldg(&mask[rb + wm*32 + mt*16 + grp + h*8]);
        }

        float acc1[2][2][4], acc2[2][2][4];
        #pragma unroll
        for (int mt = 0; mt < 2; ++mt)
            #pragma unroll
            for (int nt = 0; nt < 2; ++nt)
                #pragma unroll
                for (int q = 0; q < 4; ++q) { acc1[mt][nt][q] = 0.f; acc2[mt][nt][q] = 0.f; }

        if (dual) {
            #pragma unroll
            for (int kp0 = 0; kp0 < 64; kp0 += 8) {
                unsigned af[2][4];
                #pragma unroll
                for (int mt = 0; mt < 2; ++mt) {
                    int ar = wm*32 + mt*16 + grp;
                    af[mt][0] = A[ ar     *68 + kp0 + tig];
                    af[mt][1] = A[(ar + 8)*68 + kp0 + tig];
                    af[mt][2] = A[ ar     *68 + kp0 + tig + 4];
                    af[mt][3] = A[(ar + 8)*68 + kp0 + tig + 4];
                }
                #pragma unroll
                for (int nt = 0; nt < 2; ++nt) {
                    int bc = wn*16 + nt*8 + grp;
                    unsigned b0 = W1[(kp0+tig)*136 + bc], b1 = W1[(kp0+tig+4)*136 + bc];
                    mma_bf16(acc1[0][nt], af[0][0], af[0][1], af[0][2], af[0][3], b0, b1);
                    mma_bf16(acc1[1][nt], af[1][0], af[1][1], af[1][2], af[1][3], b0, b1);
                    unsigned c0 = W2[(kp0+tig)*136 + bc], c1 = W2[(kp0+tig+4)*136 + bc];
                    mma_bf16(acc2[0][nt], af[0][0], af[0][1], af[0][2], af[0][3], c0, c1);
                    mma_bf16(acc2[1][nt], af[1][0], af[1][1], af[1][2], af[1][3], c0, c1);
                }
            }
        } else {
            #pragma unroll
            for (int kp0 = 0; kp0 < 64; kp0 += 8) {
                unsigned af[2][4];
                #pragma unroll
                for (int mt = 0; mt < 2; ++mt) {
                    int ar = wm*32 + mt*16 + grp;
                    af[mt][0] = A[ ar     *68 + kp0 + tig];
                    af[mt][1] = A[(ar + 8)*68 + kp0 + tig];
                    af[mt][2] = A[ ar     *68 + kp0 + tig + 4];
                    af[mt][3] = A[(ar + 8)*68 + kp0 + tig + 4];
                }
                #pragma unroll
                for (int nt = 0; nt < 2; ++nt) {
                    int bc = wn*16 + nt*8 + grp;
                    unsigned b0 = W1[(kp0+tig)*136 + bc], b1 = W1[(kp0+tig+4)*136 + bc];
                    mma_bf16(acc1[0][nt], af[0][0], af[0][1], af[0][2], af[0][3], b0, b1);
                    mma_bf16(acc1[1][nt], af[1][0], af[1][1], af[1][2], af[1][3], b0, b1);
                }
            }
        }

        #pragma unroll
        for (int mt = 0; mt < 2; ++mt) {
            #pragma unroll
            for (int nt = 0; nt < 2; ++nt) {
                #pragma unroll
                for (int q = 0; q < 4; ++q) {
                    int r  = wm*32 + mt*16 + grp + ((q >= 2) ? 8 : 0);
                    int oc = wn*16 + nt*8 + tig*2 + (q & 1);
                    if (dual) {
                        float lrv = acc1[mt][nt][q] + bb1[oc];
                        float gtv = acc2[mt][nt][q] + bb2[oc];
                        dstb[(size_t)oc*MROWS + rb + r] =
                            __float2bfloat16(lrv * mpre[mt][q >= 2] * sigmoidf_(gtv));
                    } else {
                        g_gate[(size_t)oc*MROWS + rb + r] =
                            sigmoidf_(acc1[mt][nt][q] + bb1[oc]);
                    }
                }
            }
        }
        __syncthreads();
        buf ^= 1;
    }
}

// ---------------------------------------------------------------------------
// Kernel 2: p[c] = L_c @ R_c^T via bf16 mma.m16n8k16, cp.async 2-stage BK=32.
// smem [stage][row][20] (ld=20: conflict-free frags, 16B-aligned rows).
// ---------------------------------------------------------------------------
extern "C" __global__ void __launch_bounds__(256, 2)
einsum_kernel()
{
    __shared__ unsigned As[2][128][20];
    __shared__ unsigned Bs[2][128][20];

    const int t = threadIdx.x;
    const int lane = t & 31;
    const int w = t >> 5;
    const int wm = w & 3;
    const int wn = w >> 2;
    const int jbase = blockIdx.x * 128;
    const int ibase = blockIdx.y * 128;
    const int c = blockIdx.z;

    const __nv_bfloat16* A = g_leftb  + (size_t)c*MROWS + (size_t)ibase*512;
    const __nv_bfloat16* B = g_rightb + (size_t)c*MROWS + (size_t)jbase*512;

    const int tig = lane & 3;
    const int grp = lane >> 2;

    // loader mapping: 512 cp16 per matrix per stage; 2 per thread each.
    const int lr0 = t >> 1,        lq0 = (t & 1) * 2;        // rows 0..127, q 0/2... use idx scheme
    // simpler: idx = t + 256*i; row = idx>>2; q = idx&3
    float acc[2][8][4];
    #pragma unroll
    for (int mt = 0; mt < 2; ++mt)
        #pragma unroll
        for (int nt = 0; nt < 8; ++nt)
            #pragma unroll
            for (int q = 0; q < 4; ++q) acc[mt][nt][q] = 0.f;

    (void)lr0; (void)lq0;

    // prefetch stages 0 (k=0) and 1 (k=32)
    #pragma unroll
    for (int st = 0; st < 2; ++st) {
        int k0 = st * 32;
        #pragma unroll
        for (int i = 0; i < 2; ++i) {
            int idx = t + 256*i;
            int row = idx >> 2, q = idx & 3;
            cp16(&As[st][row][q*4], A + row*512 + k0 + q*8);
            cp16(&Bs[st][row][q*4], B + row*512 + k0 + q*8);
        }
        cp_commit();
    }

    int it = 0;
    for (int k0 = 0; k0 < 512; k0 += 32, it ^= 1) {
        if (k0 + 32 >= 512) cp_wait<0>(); else cp_wait<1>();
        __syncthreads();

        #pragma unroll
        for (int kk = 0; kk < 2; ++kk) {
            unsigned af[2][4], bf[8][2];
            #pragma unroll
            for (int mt = 0; mt < 2; ++mt) {
                int ar = wm*32 + mt*16 + grp;
                af[mt][0] = As[it][ar    ][kk*8 + tig];
                af[mt][1] = As[it][ar + 8][kk*8 + tig];
                af[mt][2] = As[it][ar    ][kk*8 + tig + 4];
                af[mt][3] = As[it][ar + 8][kk*8 + tig + 4];
            }
            #pragma unroll
            for (int nt = 0; nt < 8; ++nt) {
                int bc = wn*64 + nt*8 + grp;
                bf[nt][0] = Bs[it][bc][kk*8 + tig];
                bf[nt][1] = Bs[it][bc][kk*8 + tig + 4];
            }
            #pragma unroll
            for (int mt = 0; mt < 2; ++mt)
                #pragma unroll
                for (int nt = 0; nt < 8; ++nt)
                    mma_bf16(acc[mt][nt], af[mt][0], af[mt][1], af[mt][2], af[mt][3],
                             bf[nt][0], bf[nt][1]);
        }

        if (k0 + 64 < 512) {
            __syncthreads();   // done reading stage `it` before overwrite
            int kn = k0 + 64;
            #pragma unroll
            for (int i = 0; i < 2; ++i) {
                int idx = t + 256*i;
                int row = idx >> 2, q = idx & 3;
                cp16(&As[it][row][q*4], A + row*512 + kn + q*8);
                cp16(&Bs[it][row][q*4], B + row*512 + kn + q*8);
            }
            cp_commit();
        }
    }

    float* P = g_p + (size_t)c*MROWS;
    #pragma unroll
    for (int mt = 0; mt < 2; ++mt) {
        int i0 = ibase + wm*32 + mt*16 + grp;
        #pragma unroll
        for (int nt = 0; nt < 8; ++nt) {
            int j0 = jbase + wn*64 + nt*8 + tig*2;
            float2 v01 = make_float2(acc[mt][nt][0], acc[mt][nt][1]);
            float2 v23 = make_float2(acc[mt][nt][2], acc[mt][nt][3]);
            *(float2*)&P[(size_t)i0*512 + j0]     = v01;
            *(float2*)&P[(size_t)(i0+8)*512 + j0] = v23;
        }
    }
}

// ---------------------------------------------------------------------------
// Kernel 3: LN2 + (pln @ W_op, tf32) + gate + residual.
// 64-row tiles, grid 4096, block 512. Split cp groups; gate prefetch.
// ---------------------------------------------------------------------------
extern "C" __global__ void __launch_bounds__(512)
final_kernel(const float* __restrict__ Z,
             const float* __restrict__ g2v, const float* __restrict__ b2v,
             const float* __restrict__ obias, float* __restrict__ out)
{
    extern __shared__ unsigned smu[];
    unsigned* Ws = smu;                   // [128 c][136 d] tf32
    unsigned* Pu = Ws + 128*136;          // [128 c][72 r] (float, then tf32)
    float* Pf  = (float*)Pu;
    float* ps1 = (float*)(Pu + 128*72);   // [8][64]
    float* ps2 = ps1 + 8*64;
    float* g2s = ps2 + 8*64;              // 128
    float* b2s = g2s + 128;
    float* obs = b2s + 128;
    float* mus = obs + 128;               // 64
    float* rss = mus + 64;                // 64

    const int t  = threadIdx.x;
    const int rb = blockIdx.x * 64;

    // group 0: P tile (needed first, for LN)
    #pragma unroll
    for (int i = 0; i < 4; ++i) {
        int idx = t + 512*i;              // 0..2047
        int c = idx >> 4, seg = idx & 15;
        cp16(Pf + c*72 + seg*4, g_p + (size_t)c*MROWS + rb + seg*4);
    }
    cp_commit();
    // group 1: W_op tile (needed only at GEMM)
    #pragma unroll
    for (int i = 0; i < 8; ++i) {
        int idx = t + 512*i;              // 0..4095
        int c = idx >> 5, seg = idx & 31;
        cp16(Ws + c*136 + seg*4, g_wop + c*128 + seg*4);
    }
    cp_commit();
    if (t < 128) { g2s[t] = g2v[t]; b2s[t] = b2v[t]; obs[t] = obias[t]; }
    cp_wait<1>();       // P ready; W still in flight
    __syncthreads();

    // LN partials over c (8 groups of 16 c's, lanes sweep rows)
    {
        int h = t >> 6, r = t & 63;
        float s = 0.f, s2 = 0.f;
        #pragma unroll
        for (int cc = 0; cc < 16; ++cc) {
            float v = Pf[(h*16 + cc)*72 + r]; s += v; s2 += v*v;
        }
        ps1[h*64 + r] = s; ps2[h*64 + r] = s2;
    }
    __syncthreads();
    if (t < 64) {
        float s = 0.f, s2 = 0.f;
        #pragma unroll
        for (int h = 0; h < 8; ++h) { s += ps1[h*64 + t]; s2 += ps2[h*64 + t]; }
        float mu = s * (1.f/128.f);
        float var = s2 * (1.f/128.f) - mu*mu;
        mus[t] = mu; rss[t] = rsqrtf(var + 1e-5f);
    }
    __syncthreads();
    for (int idx = t; idx < 64*128; idx += 512) {
        int r = idx & 63, c = idx >> 6;
        Pu[c*72 + r] = f2tf32((Pf[c*72 + r] - mus[r]) * rss[r] * g2s[c] + b2s[c]);
    }
    cp_wait<0>();       // W ready
    __syncthreads();

    // GEMM: M=64(r), N=128(d), K=128(c); 16 warps = 4m x 4n
    const int lane = t & 31, w = t >> 5;
    const int wm = w & 3, wn = w >> 2;
    const int tig = lane & 3, grp = lane >> 2;

    // prefetch gate values (consumed in epilogue; latency hidden by GEMM)
    float gpre[4][4];
    #pragma unroll
    for (int nt = 0; nt < 4; ++nt)
        #pragma unroll
        for (int q = 0; q < 4; ++q) {
            int r = wm*16 + grp + ((q >= 2) ? 8 : 0);
            int d = wn*32 + nt*8 + tig*2 + (q & 1);
            gpre[nt][q] = __ldg(&g_gate[(size_t)d*MROWS + rb + r]);
        }

    float acc[4][4];
    #pragma unroll
    for (int nt = 0; nt < 4; ++nt)
        #pragma unroll
        for (int q = 0; q < 4; ++q) acc[nt][q] = 0.f;

    const int ar = wm*16 + grp;
    #pragma unroll
    for (int k0 = 0; k0 < 128; k0 += 8) {
        unsigned a0 = Pu[(k0+tig  )*72 + ar];
        unsigned a1 = Pu[(k0+tig  )*72 + ar + 8];
        unsigned a2 = Pu[(k0+tig+4)*72 + ar];
        unsigned a3 = Pu[(k0+tig+4)*72 + ar + 8];
        #pragma unroll
        for (int nt = 0; nt < 4; ++nt) {
            int bc = wn*32 + nt*8 + grp;
            unsigned b0 = Ws[(k0+tig)*136 + bc], b1 = Ws[(k0+tig+4)*136 + bc];
            mma_tf32(acc[nt], a0, a1, a2, a3, b0, b1);
        }
    }
    __syncthreads();   // done reading Pu; reuse as staging [r][129]

    float* Sout = Pf;
    #pragma unroll
    for (int nt = 0; nt < 4; ++nt) {
        #pragma unroll
        for (int q = 0; q < 4; ++q) {
            int r = wm*16 + grp + ((q >= 2) ? 8 : 0);
            int d = wn*32 + nt*8 + tig*2 + (q & 1);
            Sout[r*129 + d] = gpre[nt][q] * (acc[nt][q] + obs[d]);
        }
    }
    __syncthreads();

    for (int idx = t; idx < 64*128; idx += 512) {
        int r = idx >> 7, d = idx & 127;
        size_t gi = (size_t)(rb + r)*128 + d;
        out[gi] = Z[gi] + Sout[r*129 + d];
    }
}

// ---------------------------------------------------------------------------
extern "C" void kernel_launch(void* const* d_in, const int* in_sizes, int n_in,
                              void* d_out, int out_size)
{
    const float* Zr   = (const float*)d_in[0];
    const float* mask = (const float*)d_in[1];
    const float* g1   = (const float*)d_in[2];
    const float* b1   = (const float*)d_in[3];
    const float* Wlr  = (const float*)d_in[4];
    const float* blr  = (const float*)d_in[5];
    const float* Wg   = (const float*)d_in[6];
    const float* bg   = (const float*)d_in[7];
    const float* Wog  = (const float*)d_in[8];
    const float* bog  = (const float*)d_in[9];
    const float* g2   = (const float*)d_in[10];
    const float* b2   = (const float*)d_in[11];
    const float* Wop  = (const float*)d_in[12];
    const float* ob   = (const float*)d_in[13];
    float* out = (float*)d_out;

    const size_t sm1 = (size_t)(2*64*136 + 2*64*68 + 256) * 4;              // ~105.5 KB
    const size_t sm3 = (size_t)(128*136 + 128*72 + 16*64 + 3*128 + 2*64)*4; // ~112.6 KB
    cudaFuncSetAttribute(proj_kernel,  cudaFuncAttributeMaxDynamicSharedMemorySize, (int)sm1);
    cudaFuncSetAttribute(final_kernel, cudaFuncAttributeMaxDynamicSharedMemorySize, (int)sm3);

    ln1_kernel<<<32768, 256>>>(Zr, g1, b1, Wop);
    proj_kernel<<<300, 512, sm1>>>(mask, Wlr, blr, Wg, bg, Wog, bog);
    einsum_kernel<<<dim3(4, 4, 128), 256>>>();
    final_kernel<<<4096, 512, sm3>>>(Zr, g2, b2, ob, out);
}

// round 10
// speedup vs baseline: 8.1709x; 1.1343x over previous
#include <cuda_runtime.h>
#include <cuda_bf16.h>
#include <math.h>

#define NNDIM 512
#define DDIM  128
#define MROWS (NNDIM*NNDIM)   // 262144 rows of (i,j)

// Scratch (device globals).
__device__ unsigned g_zln  [(size_t)MROWS*64];           // LN1(Z) bf16-pairs, [row][cp]
__device__ __nv_bfloat16 g_leftb [(size_t)DDIM*MROWS];   // [c][row] bf16
__device__ __nv_bfloat16 g_rightb[(size_t)DDIM*MROWS];   // [c][row] bf16
__device__ float    g_gate[(size_t)DDIM*MROWS];          // [c][row] f32
__device__ unsigned g_pb  [(size_t)DDIM*MROWS/2];        // p bf16-pairs, per-c [i][j/2]
__device__ unsigned g_wop [DDIM*DDIM];                   // W_op tf32 bits, [c][d]

__device__ __forceinline__ float sigmoidf_(float x) { return 1.0f / (1.0f + expf(-x)); }

__device__ __forceinline__ unsigned f2tf32(float x) {
    unsigned r; asm("cvt.rna.tf32.f32 %0, %1;" : "=r"(r) : "f"(x)); return r;
}
__device__ __forceinline__ unsigned packbf(float lo, float hi) {
    unsigned r; asm("cvt.rn.bf16x2.f32 %0, %1, %2;" : "=r"(r) : "f"(hi), "f"(lo)); return r;
}

__device__ __forceinline__ void mma_tf32(float c[4],
    unsigned a0, unsigned a1, unsigned a2, unsigned a3, unsigned b0, unsigned b1)
{
    asm volatile(
        "mma.sync.aligned.m16n8k8.row.col.f32.tf32.tf32.f32 "
        "{%0,%1,%2,%3}, {%4,%5,%6,%7}, {%8,%9}, {%0,%1,%2,%3};"
        : "+f"(c[0]), "+f"(c[1]), "+f"(c[2]), "+f"(c[3])
        : "r"(a0), "r"(a1), "r"(a2), "r"(a3), "r"(b0), "r"(b1));
}
__device__ __forceinline__ void mma_bf16(float c[4],
    unsigned a0, unsigned a1, unsigned a2, unsigned a3, unsigned b0, unsigned b1)
{
    asm volatile(
        "mma.sync.aligned.m16n8k16.row.col.f32.bf16.bf16.f32 "
        "{%0,%1,%2,%3}, {%4,%5,%6,%7}, {%8,%9}, {%0,%1,%2,%3};"
        : "+f"(c[0]), "+f"(c[1]), "+f"(c[2]), "+f"(c[3])
        : "r"(a0), "r"(a1), "r"(a2), "r"(a3), "r"(b0), "r"(b1));
}
__device__ __forceinline__ void ldsm_x4(unsigned& r0, unsigned& r1, unsigned& r2,
                                        unsigned& r3, unsigned addr)
{
    asm volatile("ldmatrix.sync.aligned.m8n8.x4.shared.b16 {%0,%1,%2,%3}, [%4];"
        : "=r"(r0), "=r"(r1), "=r"(r2), "=r"(r3) : "r"(addr));
}

__device__ __forceinline__ void cp16(void* smem_dst, const void* gsrc) {
    unsigned d = (unsigned)__cvta_generic_to_shared(smem_dst);
    asm volatile("cp.async.ca.shared.global [%0], [%1], 16;" :: "r"(d), "l"(gsrc));
}
__device__ __forceinline__ void cp_commit() { asm volatile("cp.async.commit_group;"); }
template<int N> __device__ __forceinline__ void cp_wait() {
    asm volatile("cp.async.wait_group %0;" :: "n"(N));
}

// ---------------------------------------------------------------------------
// Kernel 0: LN1(Z) -> g_zln (bf16 pairs, [row][cp]). Warp-per-row, no smem.
// Block 0 also converts W_op -> g_wop (tf32).
// ---------------------------------------------------------------------------
extern "C" __global__ void __launch_bounds__(256)
ln1_kernel(const float* __restrict__ Z, const float* __restrict__ g1v,
           const float* __restrict__ b1v, const float* __restrict__ Wop)
{
    const int t = threadIdx.x, lane = t & 31, wid = t >> 5;

    if (blockIdx.x == 0) {
        for (int idx = t; idx < 128*128; idx += 256)
            g_wop[idx] = f2tf32(Wop[idx]);
    }

    const size_t row = (size_t)blockIdx.x * 8 + wid;
    const float4 v  = *(const float4*)&Z[row*128 + lane*4];
    const float4 gv = *(const float4*)&g1v[lane*4];
    const float4 bv = *(const float4*)&b1v[lane*4];

    float s  = v.x + v.y + v.z + v.w;
    float s2 = v.x*v.x + v.y*v.y + v.z*v.z + v.w*v.w;
    #pragma unroll
    for (int o = 16; o > 0; o >>= 1) {
        s  += __shfl_xor_sync(0xffffffffu, s,  o);
        s2 += __shfl_xor_sync(0xffffffffu, s2, o);
    }
    float mu = s * (1.f/128.f);
    float rs = rsqrtf(s2 * (1.f/128.f) - mu*mu + 1e-5f);

    float n0 = (v.x - mu) * rs * gv.x + bv.x;
    float n1 = (v.y - mu) * rs * gv.y + bv.y;
    float n2 = (v.z - mu) * rs * gv.z + bv.z;
    float n3 = (v.w - mu) * rs * gv.w + bv.w;

    uint2 o2 = make_uint2(packbf(n0, n1), packbf(n2, n3));
    *(uint2*)&g_zln[row*64 + lane*2] = o2;
}

// ---------------------------------------------------------------------------
// Kernel 1: persistent projections + gating, bf16 tensor cores.
// 300 blocks x 512 thr: bx<120 -> left-dual, <240 -> right-dual, else og.
// A fragments via ldmatrix.x4 (non-trans).
// ---------------------------------------------------------------------------
extern "C" __global__ void __launch_bounds__(512)
proj_kernel(const float* __restrict__ mask,
            const float* __restrict__ Wlr, const float* __restrict__ blr,
            const float* __restrict__ Wg,  const float* __restrict__ bg,
            const float* __restrict__ Wog, const float* __restrict__ bog)
{
    extern __shared__ unsigned smu[];
    unsigned* W1 = smu;                 // [64 kp][136 n]
    unsigned* W2 = W1 + 64*136;         // [64 kp][136 n]
    unsigned* As = W2 + 64*136;         // [2][64 row][68 kp]
    float* bb1 = (float*)(As + 2*64*68);
    float* bb2 = bb1 + 128;

    const int t = threadIdx.x, bx = blockIdx.x;
    int cg, ms, stride;
    if      (bx < 120) { cg = 0; ms = bx;       stride = 120; }
    else if (bx < 240) { cg = 1; ms = bx - 120; stride = 120; }
    else               { cg = 2; ms = bx - 240; stride = 60;  }
    const bool dual = (cg < 2);

    if (dual) {
        int cb = cg * 128;
        for (int idx = t; idx < 64*128; idx += 512) {
            int kp = idx >> 7, j = idx & 127;
            W1[kp*136 + j] = packbf(Wlr[(2*kp)*256 + cb + j], Wlr[(2*kp+1)*256 + cb + j]);
            W2[kp*136 + j] = packbf(Wg [(2*kp)*256 + cb + j], Wg [(2*kp+1)*256 + cb + j]);
        }
        if (t < 128) { bb1[t] = blr[cg*128 + t]; bb2[t] = bg[cg*128 + t]; }
    } else {
        for (int idx = t; idx < 64*128; idx += 512) {
            int kp = idx >> 7, j = idx & 127;
            W1[kp*136 + j] = packbf(Wog[(2*kp)*128 + j], Wog[(2*kp+1)*128 + j]);
        }
        if (t < 128) bb1[t] = bog[t];
    }

    const int lane = t & 31, w = t >> 5;
    const int wm = w & 1, wn = w >> 1;      // 2 m-warps x 8 n-warps
    const int tig = lane & 3, grp = lane >> 2;

    // ldmatrix lane mapping (A, non-trans): rows lane&15, k-half by lane>=16
    const unsigned sAs = (unsigned)__cvta_generic_to_shared(As);
    const int rla = lane & 15;
    const int kca = (lane >> 4) * 4;
    const unsigned aoff0 = ((wm*32 + 0*16 + rla)*68 + kca) * 4;
    const unsigned aoff1 = ((wm*32 + 1*16 + rla)*68 + kca) * 4;
    const unsigned bufstride = 64*68*4;

    __nv_bfloat16* dstb = (cg == 0) ? g_leftb : g_rightb;

    int tile = ms;
    {
        int m0 = tile * 64;
        #pragma unroll
        for (int i = 0; i < 2; ++i) {
            int idx = t + 512*i;
            int r = idx >> 4, kq = idx & 15;
            cp16(As + r*68 + kq*4, g_zln + (size_t)(m0 + r)*64 + kq*4);
        }
        cp_commit();
    }
    int buf = 0;

    for (; tile < 4096; tile += stride) {
        int nxt = tile + stride;
        if (nxt < 4096) {
            int m0 = nxt * 64;
            unsigned* db = As + (buf^1)*64*68;
            #pragma unroll
            for (int i = 0; i < 2; ++i) {
                int idx = t + 512*i;
                int r = idx >> 4, kq = idx & 15;
                cp16(db + r*68 + kq*4, g_zln + (size_t)(m0 + r)*64 + kq*4);
            }
            cp_commit();
            cp_wait<1>();
        } else {
            cp_wait<0>();
        }
        __syncthreads();

        const unsigned abase = sAs + buf*bufstride;
        const int rb = tile * 64;

        float mpre[2][2];
        if (dual) {
            #pragma unroll
            for (int mt = 0; mt < 2; ++mt)
                #pragma unroll
                for (int h = 0; h < 2; ++h)
                    mpre[mt][h] = __ldg(&mask[rb + wm*32 + mt*16 + grp + h*8]);
        }

        float acc1[2][2][4], acc2[2][2][4];
        #pragma unroll
        for (int mt = 0; mt < 2; ++mt)
            #pragma unroll
            for (int nt = 0; nt < 2; ++nt)
                #pragma unroll
                for (int q = 0; q < 4; ++q) { acc1[mt][nt][q] = 0.f; acc2[mt][nt][q] = 0.f; }

        #pragma unroll
        for (int kp0 = 0; kp0 < 64; kp0 += 8) {
            unsigned af[2][4];
            ldsm_x4(af[0][0], af[0][1], af[0][2], af[0][3], abase + aoff0 + kp0*4);
            ldsm_x4(af[1][0], af[1][1], af[1][2], af[1][3], abase + aoff1 + kp0*4);
            if (dual) {
                #pragma unroll
                for (int nt = 0; nt < 2; ++nt) {
                    int bc = wn*16 + nt*8 + grp;
                    unsigned b0 = W1[(kp0+tig)*136 + bc], b1 = W1[(kp0+tig+4)*136 + bc];
                    mma_bf16(acc1[0][nt], af[0][0], af[0][1], af[0][2], af[0][3], b0, b1);
                    mma_bf16(acc1[1][nt], af[1][0], af[1][1], af[1][2], af[1][3], b0, b1);
                    unsigned c0 = W2[(kp0+tig)*136 + bc], c1 = W2[(kp0+tig+4)*136 + bc];
                    mma_bf16(acc2[0][nt], af[0][0], af[0][1], af[0][2], af[0][3], c0, c1);
                    mma_bf16(acc2[1][nt], af[1][0], af[1][1], af[1][2], af[1][3], c0, c1);
                }
            } else {
                #pragma unroll
                for (int nt = 0; nt < 2; ++nt) {
                    int bc = wn*16 + nt*8 + grp;
                    unsigned b0 = W1[(kp0+tig)*136 + bc], b1 = W1[(kp0+tig+4)*136 + bc];
                    mma_bf16(acc1[0][nt], af[0][0], af[0][1], af[0][2], af[0][3], b0, b1);
                    mma_bf16(acc1[1][nt], af[1][0], af[1][1], af[1][2], af[1][3], b0, b1);
                }
            }
        }

        #pragma unroll
        for (int mt = 0; mt < 2; ++mt) {
            #pragma unroll
            for (int nt = 0; nt < 2; ++nt) {
                #pragma unroll
                for (int q = 0; q < 4; ++q) {
                    int r  = wm*32 + mt*16 + grp + ((q >= 2) ? 8 : 0);
                    int oc = wn*16 + nt*8 + tig*2 + (q & 1);
                    if (dual) {
                        float lrv = acc1[mt][nt][q] + bb1[oc];
                        float gtv = acc2[mt][nt][q] + bb2[oc];
                        dstb[(size_t)oc*MROWS + rb + r] =
                            __float2bfloat16(lrv * mpre[mt][q >= 2] * sigmoidf_(gtv));
                    } else {
                        g_gate[(size_t)oc*MROWS + rb + r] =
                            sigmoidf_(acc1[mt][nt][q] + bb1[oc]);
                    }
                }
            }
        }
        __syncthreads();
        buf ^= 1;
    }
}

// ---------------------------------------------------------------------------
// Kernel 2: p[c] = L_c @ R_c^T via bf16 mma, cp.async 2-stage BK=32, ldmatrix.
// B stored [n][k] = already col-major for mma.row.col -> NON-trans ldmatrix.
// smem [stage][row][20] u32; p written as bf16 pairs to g_pb.
// ---------------------------------------------------------------------------
extern "C" __global__ void __launch_bounds__(256, 2)
einsum_kernel()
{
    __shared__ unsigned As[2][128][20];
    __shared__ unsigned Bs[2][128][20];

    const int t = threadIdx.x;
    const int lane = t & 31;
    const int w = t >> 5;
    const int wm = w & 3;
    const int wn = w >> 2;
    const int jbase = blockIdx.x * 128;
    const int ibase = blockIdx.y * 128;
    const int c = blockIdx.z;

    const __nv_bfloat16* A = g_leftb  + (size_t)c*MROWS + (size_t)ibase*512;
    const __nv_bfloat16* B = g_rightb + (size_t)c*MROWS + (size_t)jbase*512;

    const int tig = lane & 3;
    const int grp = lane >> 2;

    // ldmatrix lane mappings (all non-trans)
    const unsigned sAs = (unsigned)__cvta_generic_to_shared(As);
    const unsigned sBs = (unsigned)__cvta_generic_to_shared(Bs);
    const int rla = lane & 15;                         // A rows
    const int kca = (lane >> 4) * 4;                   // A k-half (u32)
    const int rlb = (lane & 7) + ((lane >> 4) << 3);   // B rows (+8 for lanes>=16)
    const int kcb = ((lane >> 3) & 1) * 4;             // B k-half
    unsigned aoff[2], boff[4];
    #pragma unroll
    for (int mt = 0; mt < 2; ++mt)
        aoff[mt] = ((wm*32 + mt*16 + rla)*20 + kca) * 4;
    #pragma unroll
    for (int ntp = 0; ntp < 4; ++ntp)
        boff[ntp] = ((wn*64 + ntp*16 + rlb)*20 + kcb) * 4;
    const unsigned ststride = 128*20*4;

    float acc[2][8][4];
    #pragma unroll
    for (int mt = 0; mt < 2; ++mt)
        #pragma unroll
        for (int nt = 0; nt < 8; ++nt)
            #pragma unroll
            for (int q = 0; q < 4; ++q) acc[mt][nt][q] = 0.f;

    // prefetch stages 0 (k=0) and 1 (k=32)
    #pragma unroll
    for (int st = 0; st < 2; ++st) {
        int k0 = st * 32;
        #pragma unroll
        for (int i = 0; i < 2; ++i) {
            int idx = t + 256*i;
            int row = idx >> 2, q = idx & 3;
            cp16(&As[st][row][q*4], A + row*512 + k0 + q*8);
            cp16(&Bs[st][row][q*4], B + row*512 + k0 + q*8);
        }
        cp_commit();
    }

    int it = 0;
    for (int k0 = 0; k0 < 512; k0 += 32, it ^= 1) {
        if (k0 + 32 >= 512) cp_wait<0>(); else cp_wait<1>();
        __syncthreads();

        const unsigned ab = sAs + it*ststride;
        const unsigned bb = sBs + it*ststride;

        #pragma unroll
        for (int kk = 0; kk < 2; ++kk) {
            unsigned af[2][4], bf[8][2];
            ldsm_x4(af[0][0], af[0][1], af[0][2], af[0][3], ab + aoff[0] + kk*32);
            ldsm_x4(af[1][0], af[1][1], af[1][2], af[1][3], ab + aoff[1] + kk*32);
            #pragma unroll
            for (int ntp = 0; ntp < 4; ++ntp)
                ldsm_x4(bf[ntp*2][0], bf[ntp*2][1], bf[ntp*2+1][0], bf[ntp*2+1][1],
                        bb + boff[ntp] + kk*32);
            #pragma unroll
            for (int mt = 0; mt < 2; ++mt)
                #pragma unroll
                for (int nt = 0; nt < 8; ++nt)
                    mma_bf16(acc[mt][nt], af[mt][0], af[mt][1], af[mt][2], af[mt][3],
                             bf[nt][0], bf[nt][1]);
        }

        if (k0 + 64 < 512) {
            __syncthreads();
            int kn = k0 + 64;
            #pragma unroll
            for (int i = 0; i < 2; ++i) {
                int idx = t + 256*i;
                int row = idx >> 2, q = idx & 3;
                cp16(&As[it][row][q*4], A + row*512 + kn + q*8);
                cp16(&Bs[it][row][q*4], B + row*512 + kn + q*8);
            }
            cp_commit();
        }
    }

    // store p as bf16 pairs: plane base c*131072 u32, element (i, j/2)
    unsigned* Pb = g_pb + (size_t)c*(MROWS/2);
    #pragma unroll
    for (int mt = 0; mt < 2; ++mt) {
        int i0 = ibase + wm*32 + mt*16 + grp;
        #pragma unroll
        for (int nt = 0; nt < 8; ++nt) {
            int j0 = jbase + wn*64 + nt*8 + tig*2;
            Pb[(size_t)i0*256 + (j0 >> 1)]     = packbf(acc[mt][nt][0], acc[mt][nt][1]);
            Pb[(size_t)(i0+8)*256 + (j0 >> 1)] = packbf(acc[mt][nt][2], acc[mt][nt][3]);
        }
    }
}

// ---------------------------------------------------------------------------
// Kernel 3: LN2 + (pln @ W_op, tf32) + gate + residual.
// 64-row tiles, grid 4096, block 512. p loaded as bf16 pairs into Pu row tails,
// expanded in place (register-staged) to tf32.
// ---------------------------------------------------------------------------
extern "C" __global__ void __launch_bounds__(512)
final_kernel(const float* __restrict__ Z,
             const float* __restrict__ g2v, const float* __restrict__ b2v,
             const float* __restrict__ obias, float* __restrict__ out)
{
    extern __shared__ unsigned smu[];
    unsigned* Ws = smu;                   // [128 c][136 d] tf32
    unsigned* Pu = Ws + 128*136;          // [128 c][72]: cols 0..63 tf32; 32..63 packed bf16 on load
    float* Pf  = (float*)Pu;
    float* ps1 = (float*)(Pu + 128*72);   // [8][64]
    float* ps2 = ps1 + 8*64;
    float* g2s = ps2 + 8*64;              // 128
    float* b2s = g2s + 128;
    float* obs = b2s + 128;
    float* mus = obs + 128;               // 64
    float* rss = mus + 64;                // 64

    const int t  = threadIdx.x;
    const int rb = blockIdx.x * 64;

    // group 0: P tile (bf16 pairs -> Pu[c][32..63])
    #pragma unroll
    for (int i = 0; i < 2; ++i) {
        int idx = t + 512*i;              // 0..1023
        int c = idx >> 3, seg = idx & 7;
        cp16(Pu + c*72 + 32 + seg*4, g_pb + (size_t)c*(MROWS/2) + (rb >> 1) + seg*4);
    }
    cp_commit();
    // group 1: W_op tile
    #pragma unroll
    for (int i = 0; i < 8; ++i) {
        int idx = t + 512*i;              // 0..4095
        int c = idx >> 5, seg = idx & 31;
        cp16(Ws + c*136 + seg*4, g_wop + c*128 + seg*4);
    }
    cp_commit();
    if (t < 128) { g2s[t] = g2v[t]; b2s[t] = b2v[t]; obs[t] = obias[t]; }
    cp_wait<1>();       // P ready; W still in flight
    __syncthreads();

    // LN partials over c (8 groups of 16 c's, lanes sweep rows)
    {
        int h = t >> 6, r = t & 63;
        int r2 = r >> 1, hi = r & 1;
        float s = 0.f, s2 = 0.f;
        #pragma unroll
        for (int cc = 0; cc < 16; ++cc) {
            unsigned pk = Pu[(h*16 + cc)*72 + 32 + r2];
            __nv_bfloat162 h2 = *reinterpret_cast<const __nv_bfloat162*>(&pk);
            float v = hi ? __bfloat162float(h2.y) : __bfloat162float(h2.x);
            s += v; s2 += v*v;
        }
        ps1[h*64 + r] = s; ps2[h*64 + r] = s2;
    }
    __syncthreads();
    if (t < 64) {
        float s = 0.f, s2 = 0.f;
        #pragma unroll
        for (int h = 0; h < 8; ++h) { s += ps1[h*64 + t]; s2 += ps2[h*64 + t]; }
        float mu = s * (1.f/128.f);
        float var = s2 * (1.f/128.f) - mu*mu;
        mus[t] = mu; rss[t] = rsqrtf(var + 1e-5f);
    }
    __syncthreads();

    // expand packed bf16 -> tf32 in place (register-staged to avoid races)
    {
        unsigned pk[8];
        #pragma unroll
        for (int i = 0; i < 8; ++i) {
            int idx = t + 512*i;          // 0..4095 pairs
            int c = idx >> 5, r2 = idx & 31;
            pk[i] = Pu[c*72 + 32 + r2];
        }
        __syncthreads();                  // all reads done before writes
        #pragma unroll
        for (int i = 0; i < 8; ++i) {
            int idx = t + 512*i;
            int c = idx >> 5, r2 = idx & 31, r = r2*2;
            __nv_bfloat162 h2 = *reinterpret_cast<const __nv_bfloat162*>(&pk[i]);
            float vx = __bfloat162float(h2.x), vy = __bfloat162float(h2.y);
            Pu[c*72 + r    ] = f2tf32((vx - mus[r  ]) * rss[r  ] * g2s[c] + b2s[c]);
            Pu[c*72 + r + 1] = f2tf32((vy - mus[r+1]) * rss[r+1] * g2s[c] + b2s[c]);
        }
    }
    cp_wait<0>();       // W ready
    __syncthreads();

    // GEMM: M=64(r), N=128(d), K=128(c); 16 warps = 4m x 4n
    const int lane = t & 31, w = t >> 5;
    const int wm = w & 3, wn = w >> 2;
    const int tig = lane & 3, grp = lane >> 2;

    float gpre[4][4];
    #pragma unroll
    for (int nt = 0; nt < 4; ++nt)
        #pragma unroll
        for (int q = 0; q < 4; ++q) {
            int r = wm*16 + grp + ((q >= 2) ? 8 : 0);
            int d = wn*32 + nt*8 + tig*2 + (q & 1);
            gpre[nt][q] = __ldg(&g_gate[(size_t)d*MROWS + rb + r]);
        }

    float acc[4][4];
    #pragma unroll
    for (int nt = 0; nt < 4; ++nt)
        #pragma unroll
        for (int q = 0; q < 4; ++q) acc[nt][q] = 0.f;

    const int ar = wm*16 + grp;
    #pragma unroll
    for (int k0 = 0; k0 < 128; k0 += 8) {
        unsigned a0 = Pu[(k0+tig  )*72 + ar];
        unsigned a1 = Pu[(k0+tig  )*72 + ar + 8];
        unsigned a2 = Pu[(k0+tig+4)*72 + ar];
        unsigned a3 = Pu[(k0+tig+4)*72 + ar + 8];
        #pragma unroll
        for (int nt = 0; nt < 4; ++nt) {
            int bc = wn*32 + nt*8 + grp;
            unsigned b0 = Ws[(k0+tig)*136 + bc], b1 = Ws[(k0+tig+4)*136 + bc];
            mma_tf32(acc[nt], a0, a1, a2, a3, b0, b1);
        }
    }
    __syncthreads();   // done reading Pu; reuse as staging [r][129]

    float* Sout = Pf;
    #pragma unroll
    for (int nt = 0; nt < 4; ++nt) {
        #pragma unroll
        for (int q = 0; q < 4; ++q) {
            int r = wm*16 + grp + ((q >= 2) ? 8 : 0);
            int d = wn*32 + nt*8 + tig*2 + (q & 1);
            Sout[r*129 + d] = gpre[nt][q] * (acc[nt][q] + obs[d]);
        }
    }
    __syncthreads();

    for (int idx = t; idx < 64*128; idx += 512) {
        int r = idx >> 7, d = idx & 127;
        size_t gi = (size_t)(rb + r)*128 + d;
        out[gi] = Z[gi] + Sout[r*129 + d];
    }
}

// ---------------------------------------------------------------------------
extern "C" void kernel_launch(void* const* d_in, const int* in_sizes, int n_in,
                              void* d_out, int out_size)
{
    const float* Zr   = (const float*)d_in[0];
    const float* mask = (const float*)d_in[1];
    const float* g1   = (const float*)d_in[2];
    const float* b1   = (const float*)d_in[3];
    const float* Wlr  = (const float*)d_in[4];
    const float* blr  = (const float*)d_in[5];
    const float* Wg   = (const float*)d_in[6];
    const float* bg   = (const float*)d_in[7];
    const float* Wog  = (const float*)d_in[8];
    const float* bog  = (const float*)d_in[9];
    const float* g2   = (const float*)d_in[10];
    const float* b2   = (const float*)d_in[11];
    const float* Wop  = (const float*)d_in[12];
    const float* ob   = (const float*)d_in[13];
    float* out = (float*)d_out;

    const size_t sm1 = (size_t)(2*64*136 + 2*64*68 + 256) * 4;              // ~105.5 KB
    const size_t sm3 = (size_t)(128*136 + 128*72 + 16*64 + 3*128 + 2*64)*4; // ~112.6 KB
    cudaFuncSetAttribute(proj_kernel,  cudaFuncAttributeMaxDynamicSharedMemorySize, (int)sm1);
    cudaFuncSetAttribute(final_kernel, cudaFuncAttributeMaxDynamicSharedMemorySize, (int)sm3);

    ln1_kernel<<<32768, 256>>>(Zr, g1, b1, Wop);
    proj_kernel<<<300, 512, sm1>>>(mask, Wlr, blr, Wg, bg, Wog, bog);
    einsum_kernel<<<dim3(4, 4, 128), 256>>>();
    final_kernel<<<4096, 512, sm3>>>(Zr, g2, b2, ob, out);
}

// round 11
// speedup vs baseline: 8.7453x; 1.0703x over previous
#include <cuda_runtime.h>
#include <cuda_bf16.h>
#include <math.h>

#define NNDIM 512
#define DDIM  128
#define MROWS (NNDIM*NNDIM)   // 262144 rows of (i,j)

// Scratch (device globals).
__device__ unsigned g_zln  [(size_t)MROWS*64];           // LN1(Z) bf16-pairs, [row][cp]
__device__ __nv_bfloat16 g_leftb [(size_t)DDIM*MROWS];   // [c][row] bf16
__device__ __nv_bfloat16 g_rightb[(size_t)DDIM*MROWS];   // [c][row] bf16
__device__ float    g_gate[(size_t)DDIM*MROWS];          // [c][row] f32
__device__ unsigned g_pb  [(size_t)DDIM*MROWS/2];        // p bf16-pairs, per-c [i][j/2]
__device__ unsigned g_wop [DDIM*DDIM];                   // W_op tf32 bits, [c][d]

__device__ __forceinline__ float sigmoidf_(float x) { return 1.0f / (1.0f + expf(-x)); }

__device__ __forceinline__ unsigned f2tf32(float x) {
    unsigned r; asm("cvt.rna.tf32.f32 %0, %1;" : "=r"(r) : "f"(x)); return r;
}
__device__ __forceinline__ unsigned packbf(float lo, float hi) {
    unsigned r; asm("cvt.rn.bf16x2.f32 %0, %1, %2;" : "=r"(r) : "f"(hi), "f"(lo)); return r;
}

__device__ __forceinline__ void mma_tf32(float c[4],
    unsigned a0, unsigned a1, unsigned a2, unsigned a3, unsigned b0, unsigned b1)
{
    asm volatile(
        "mma.sync.aligned.m16n8k8.row.col.f32.tf32.tf32.f32 "
        "{%0,%1,%2,%3}, {%4,%5,%6,%7}, {%8,%9}, {%0,%1,%2,%3};"
        : "+f"(c[0]), "+f"(c[1]), "+f"(c[2]), "+f"(c[3])
        : "r"(a0), "r"(a1), "r"(a2), "r"(a3), "r"(b0), "r"(b1));
}
__device__ __forceinline__ void mma_bf16(float c[4],
    unsigned a0, unsigned a1, unsigned a2, unsigned a3, unsigned b0, unsigned b1)
{
    asm volatile(
        "mma.sync.aligned.m16n8k16.row.col.f32.bf16.bf16.f32 "
        "{%0,%1,%2,%3}, {%4,%5,%6,%7}, {%8,%9}, {%0,%1,%2,%3};"
        : "+f"(c[0]), "+f"(c[1]), "+f"(c[2]), "+f"(c[3])
        : "r"(a0), "r"(a1), "r"(a2), "r"(a3), "r"(b0), "r"(b1));
}
__device__ __forceinline__ void ldsm_x4(unsigned& r0, unsigned& r1, unsigned& r2,
                                        unsigned& r3, unsigned addr)
{
    asm volatile("ldmatrix.sync.aligned.m8n8.x4.shared.b16 {%0,%1,%2,%3}, [%4];"
        : "=r"(r0), "=r"(r1), "=r"(r2), "=r"(r3) : "r"(addr));
}

__device__ __forceinline__ void cp16(void* smem_dst, const void* gsrc) {
    unsigned d = (unsigned)__cvta_generic_to_shared(smem_dst);
    asm volatile("cp.async.ca.shared.global [%0], [%1], 16;" :: "r"(d), "l"(gsrc));
}
__device__ __forceinline__ void cp_commit() { asm volatile("cp.async.commit_group;"); }
template<int N> __device__ __forceinline__ void cp_wait() {
    asm volatile("cp.async.wait_group %0;" :: "n"(N));
}

// ---------------------------------------------------------------------------
// Kernel 0: LN1(Z) -> g_zln (bf16 pairs, [row][cp]). Warp-per-row, no smem.
// Block 0 also converts W_op -> g_wop (tf32).
// ---------------------------------------------------------------------------
extern "C" __global__ void __launch_bounds__(256)
ln1_kernel(const float* __restrict__ Z, const float* __restrict__ g1v,
           const float* __restrict__ b1v, const float* __restrict__ Wop)
{
    const int t = threadIdx.x, lane = t & 31, wid = t >> 5;

    if (blockIdx.x == 0) {
        for (int idx = t; idx < 128*128; idx += 256)
            g_wop[idx] = f2tf32(Wop[idx]);
    }

    const size_t row = (size_t)blockIdx.x * 8 + wid;
    const float4 v  = *(const float4*)&Z[row*128 + lane*4];
    const float4 gv = *(const float4*)&g1v[lane*4];
    const float4 bv = *(const float4*)&b1v[lane*4];

    float s  = v.x + v.y + v.z + v.w;
    float s2 = v.x*v.x + v.y*v.y + v.z*v.z + v.w*v.w;
    #pragma unroll
    for (int o = 16; o > 0; o >>= 1) {
        s  += __shfl_xor_sync(0xffffffffu, s,  o);
        s2 += __shfl_xor_sync(0xffffffffu, s2, o);
    }
    float mu = s * (1.f/128.f);
    float rs = rsqrtf(s2 * (1.f/128.f) - mu*mu + 1e-5f);

    float n0 = (v.x - mu) * rs * gv.x + bv.x;
    float n1 = (v.y - mu) * rs * gv.y + bv.y;
    float n2 = (v.z - mu) * rs * gv.z + bv.z;
    float n3 = (v.w - mu) * rs * gv.w + bv.w;

    uint2 o2 = make_uint2(packbf(n0, n1), packbf(n2, n3));
    *(uint2*)&g_zln[row*64 + lane*2] = o2;
}

// ---------------------------------------------------------------------------
// Kernel 1: persistent projections + gating, bf16 tensor cores.
// 300 blocks x 512 thr: bx<120 -> left-dual, <240 -> right-dual, else og.
// A fragments via ldmatrix.x4 (non-trans). (Unchanged from R9 pass.)
// ---------------------------------------------------------------------------
extern "C" __global__ void __launch_bounds__(512)
proj_kernel(const float* __restrict__ mask,
            const float* __restrict__ Wlr, const float* __restrict__ blr,
            const float* __restrict__ Wg,  const float* __restrict__ bg,
            const float* __restrict__ Wog, const float* __restrict__ bog)
{
    extern __shared__ unsigned smu[];
    unsigned* W1 = smu;                 // [64 kp][136 n]
    unsigned* W2 = W1 + 64*136;         // [64 kp][136 n]
    unsigned* As = W2 + 64*136;         // [2][64 row][68 kp]
    float* bb1 = (float*)(As + 2*64*68);
    float* bb2 = bb1 + 128;

    const int t = threadIdx.x, bx = blockIdx.x;
    int cg, ms, stride;
    if      (bx < 120) { cg = 0; ms = bx;       stride = 120; }
    else if (bx < 240) { cg = 1; ms = bx - 120; stride = 120; }
    else               { cg = 2; ms = bx - 240; stride = 60;  }
    const bool dual = (cg < 2);

    if (dual) {
        int cb = cg * 128;
        for (int idx = t; idx < 64*128; idx += 512) {
            int kp = idx >> 7, j = idx & 127;
            W1[kp*136 + j] = packbf(Wlr[(2*kp)*256 + cb + j], Wlr[(2*kp+1)*256 + cb + j]);
            W2[kp*136 + j] = packbf(Wg [(2*kp)*256 + cb + j], Wg [(2*kp+1)*256 + cb + j]);
        }
        if (t < 128) { bb1[t] = blr[cg*128 + t]; bb2[t] = bg[cg*128 + t]; }
    } else {
        for (int idx = t; idx < 64*128; idx += 512) {
            int kp = idx >> 7, j = idx & 127;
            W1[kp*136 + j] = packbf(Wog[(2*kp)*128 + j], Wog[(2*kp+1)*128 + j]);
        }
        if (t < 128) bb1[t] = bog[t];
    }

    const int lane = t & 31, w = t >> 5;
    const int wm = w & 1, wn = w >> 1;      // 2 m-warps x 8 n-warps
    const int tig = lane & 3, grp = lane >> 2;

    const unsigned sAs = (unsigned)__cvta_generic_to_shared(As);
    const int rla = lane & 15;
    const int kca = (lane >> 4) * 4;
    const unsigned aoff0 = ((wm*32 + 0*16 + rla)*68 + kca) * 4;
    const unsigned aoff1 = ((wm*32 + 1*16 + rla)*68 + kca) * 4;
    const unsigned bufstride = 64*68*4;

    __nv_bfloat16* dstb = (cg == 0) ? g_leftb : g_rightb;

    int tile = ms;
    {
        int m0 = tile * 64;
        #pragma unroll
        for (int i = 0; i < 2; ++i) {
            int idx = t + 512*i;
            int r = idx >> 4, kq = idx & 15;
            cp16(As + r*68 + kq*4, g_zln + (size_t)(m0 + r)*64 + kq*4);
        }
        cp_commit();
    }
    int buf = 0;

    for (; tile < 4096; tile += stride) {
        int nxt = tile + stride;
        if (nxt < 4096) {
            int m0 = nxt * 64;
            unsigned* db = As + (buf^1)*64*68;
            #pragma unroll
            for (int i = 0; i < 2; ++i) {
                int idx = t + 512*i;
                int r = idx >> 4, kq = idx & 15;
                cp16(db + r*68 + kq*4, g_zln + (size_t)(m0 + r)*64 + kq*4);
            }
            cp_commit();
            cp_wait<1>();
        } else {
            cp_wait<0>();
        }
        __syncthreads();

        const unsigned abase = sAs + buf*bufstride;
        const int rb = tile * 64;

        float mpre[2][2];
        if (dual) {
            #pragma unroll
            for (int mt = 0; mt < 2; ++mt)
                #pragma unroll
                for (int h = 0; h < 2; ++h)
                    mpre[mt][h] = __ldg(&mask[rb + wm*32 + mt*16 + grp + h*8]);
        }

        float acc1[2][2][4], acc2[2][2][4];
        #pragma unroll
        for (int mt = 0; mt < 2; ++mt)
            #pragma unroll
            for (int nt = 0; nt < 2; ++nt)
                #pragma unroll
                for (int q = 0; q < 4; ++q) { acc1[mt][nt][q] = 0.f; acc2[mt][nt][q] = 0.f; }

        #pragma unroll
        for (int kp0 = 0; kp0 < 64; kp0 += 8) {
            unsigned af[2][4];
            ldsm_x4(af[0][0], af[0][1], af[0][2], af[0][3], abase + aoff0 + kp0*4);
            ldsm_x4(af[1][0], af[1][1], af[1][2], af[1][3], abase + aoff1 + kp0*4);
            if (dual) {
                #pragma unroll
                for (int nt = 0; nt < 2; ++nt) {
                    int bc = wn*16 + nt*8 + grp;
                    unsigned b0 = W1[(kp0+tig)*136 + bc], b1 = W1[(kp0+tig+4)*136 + bc];
                    mma_bf16(acc1[0][nt], af[0][0], af[0][1], af[0][2], af[0][3], b0, b1);
                    mma_bf16(acc1[1][nt], af[1][0], af[1][1], af[1][2], af[1][3], b0, b1);
                    unsigned c0 = W2[(kp0+tig)*136 + bc], c1 = W2[(kp0+tig+4)*136 + bc];
                    mma_bf16(acc2[0][nt], af[0][0], af[0][1], af[0][2], af[0][3], c0, c1);
                    mma_bf16(acc2[1][nt], af[1][0], af[1][1], af[1][2], af[1][3], c0, c1);
                }
            } else {
                #pragma unroll
                for (int nt = 0; nt < 2; ++nt) {
                    int bc = wn*16 + nt*8 + grp;
                    unsigned b0 = W1[(kp0+tig)*136 + bc], b1 = W1[(kp0+tig+4)*136 + bc];
                    mma_bf16(acc1[0][nt], af[0][0], af[0][1], af[0][2], af[0][3], b0, b1);
                    mma_bf16(acc1[1][nt], af[1][0], af[1][1], af[1][2], af[1][3], b0, b1);
                }
            }
        }

        #pragma unroll
        for (int mt = 0; mt < 2; ++mt) {
            #pragma unroll
            for (int nt = 0; nt < 2; ++nt) {
                #pragma unroll
                for (int q = 0; q < 4; ++q) {
                    int r  = wm*32 + mt*16 + grp + ((q >= 2) ? 8 : 0);
                    int oc = wn*16 + nt*8 + tig*2 + (q & 1);
                    if (dual) {
                        float lrv = acc1[mt][nt][q] + bb1[oc];
                        float gtv = acc2[mt][nt][q] + bb2[oc];
                        dstb[(size_t)oc*MROWS + rb + r] =
                            __float2bfloat16(lrv * mpre[mt][q >= 2] * sigmoidf_(gtv));
                    } else {
                        g_gate[(size_t)oc*MROWS + rb + r] =
                            sigmoidf_(acc1[mt][nt][q] + bb1[oc]);
                    }
                }
            }
        }
        __syncthreads();
        buf ^= 1;
    }
}

// ---------------------------------------------------------------------------
// Kernel 2: p[c] = L_c @ R_c^T via bf16 mma, cp.async 2-stage BK=32, ldmatrix.
// (Unchanged from R9 pass.)
// ---------------------------------------------------------------------------
extern "C" __global__ void __launch_bounds__(256, 2)
einsum_kernel()
{
    __shared__ unsigned As[2][128][20];
    __shared__ unsigned Bs[2][128][20];

    const int t = threadIdx.x;
    const int lane = t & 31;
    const int w = t >> 5;
    const int wm = w & 3;
    const int wn = w >> 2;
    const int jbase = blockIdx.x * 128;
    const int ibase = blockIdx.y * 128;
    const int c = blockIdx.z;

    const __nv_bfloat16* A = g_leftb  + (size_t)c*MROWS + (size_t)ibase*512;
    const __nv_bfloat16* B = g_rightb + (size_t)c*MROWS + (size_t)jbase*512;

    const int tig = lane & 3;
    const int grp = lane >> 2;

    const unsigned sAs = (unsigned)__cvta_generic_to_shared(As);
    const unsigned sBs = (unsigned)__cvta_generic_to_shared(Bs);
    const int rla = lane & 15;
    const int kca = (lane >> 4) * 4;
    const int rlb = (lane & 7) + ((lane >> 4) << 3);
    const int kcb = ((lane >> 3) & 1) * 4;
    unsigned aoff[2], boff[4];
    #pragma unroll
    for (int mt = 0; mt < 2; ++mt)
        aoff[mt] = ((wm*32 + mt*16 + rla)*20 + kca) * 4;
    #pragma unroll
    for (int ntp = 0; ntp < 4; ++ntp)
        boff[ntp] = ((wn*64 + ntp*16 + rlb)*20 + kcb) * 4;
    const unsigned ststride = 128*20*4;

    float acc[2][8][4];
    #pragma unroll
    for (int mt = 0; mt < 2; ++mt)
        #pragma unroll
        for (int nt = 0; nt < 8; ++nt)
            #pragma unroll
            for (int q = 0; q < 4; ++q) acc[mt][nt][q] = 0.f;

    #pragma unroll
    for (int st = 0; st < 2; ++st) {
        int k0 = st * 32;
        #pragma unroll
        for (int i = 0; i < 2; ++i) {
            int idx = t + 256*i;
            int row = idx >> 2, q = idx & 3;
            cp16(&As[st][row][q*4], A + row*512 + k0 + q*8);
            cp16(&Bs[st][row][q*4], B + row*512 + k0 + q*8);
        }
        cp_commit();
    }

    int it = 0;
    for (int k0 = 0; k0 < 512; k0 += 32, it ^= 1) {
        if (k0 + 32 >= 512) cp_wait<0>(); else cp_wait<1>();
        __syncthreads();

        const unsigned ab = sAs + it*ststride;
        const unsigned bb = sBs + it*ststride;

        #pragma unroll
        for (int kk = 0; kk < 2; ++kk) {
            unsigned af[2][4], bf[8][2];
            ldsm_x4(af[0][0], af[0][1], af[0][2], af[0][3], ab + aoff[0] + kk*32);
            ldsm_x4(af[1][0], af[1][1], af[1][2], af[1][3], ab + aoff[1] + kk*32);
            #pragma unroll
            for (int ntp = 0; ntp < 4; ++ntp)
                ldsm_x4(bf[ntp*2][0], bf[ntp*2][1], bf[ntp*2+1][0], bf[ntp*2+1][1],
                        bb + boff[ntp] + kk*32);
            #pragma unroll
            for (int mt = 0; mt < 2; ++mt)
                #pragma unroll
                for (int nt = 0; nt < 8; ++nt)
                    mma_bf16(acc[mt][nt], af[mt][0], af[mt][1], af[mt][2], af[mt][3],
                             bf[nt][0], bf[nt][1]);
        }

        if (k0 + 64 < 512) {
            __syncthreads();
            int kn = k0 + 64;
            #pragma unroll
            for (int i = 0; i < 2; ++i) {
                int idx = t + 256*i;
                int row = idx >> 2, q = idx & 3;
                cp16(&As[it][row][q*4], A + row*512 + kn + q*8);
                cp16(&Bs[it][row][q*4], B + row*512 + kn + q*8);
            }
            cp_commit();
        }
    }

    unsigned* Pb = g_pb + (size_t)c*(MROWS/2);
    #pragma unroll
    for (int mt = 0; mt < 2; ++mt) {
        int i0 = ibase + wm*32 + mt*16 + grp;
        #pragma unroll
        for (int nt = 0; nt < 8; ++nt) {
            int j0 = jbase + wn*64 + nt*8 + tig*2;
            Pb[(size_t)i0*256 + (j0 >> 1)]     = packbf(acc[mt][nt][0], acc[mt][nt][1]);
            Pb[(size_t)(i0+8)*256 + (j0 >> 1)] = packbf(acc[mt][nt][2], acc[mt][nt][3]);
        }
    }
}

// ---------------------------------------------------------------------------
// Kernel 3: PERSISTENT LN2 + (pln @ W_op, tf32) + gate + residual.
// Grid 152 x 512. W_op resident; P tiles double-buffered via cp.async; Z/gate
// prefetched into registers before GEMM; direct float2 gated-residual stores.
// ---------------------------------------------------------------------------
extern "C" __global__ void __launch_bounds__(512)
final_kernel(const float* __restrict__ Z,
             const float* __restrict__ g2v, const float* __restrict__ b2v,
             const float* __restrict__ obias, float* __restrict__ out)
{
    extern __shared__ unsigned smu[];
    unsigned* Ws  = smu;                  // [128 c][136 d] tf32
    unsigned* Pu0 = Ws + 128*136;         // [128 c][72]: cols 32..63 packed on load
    unsigned* Pu1 = Pu0 + 128*72;
    float* ps1 = (float*)(Pu1 + 128*72);  // [8][64]
    float* ps2 = ps1 + 8*64;
    float* g2s = ps2 + 8*64;              // 128
    float* b2s = g2s + 128;
    float* obs = b2s + 128;
    float* mus = obs + 128;               // 64
    float* rss = mus + 64;                // 64

    const int t = threadIdx.x;

    // prologue: W_op + first P tile in one group
    #pragma unroll
    for (int i = 0; i < 8; ++i) {
        int idx = t + 512*i;
        int c = idx >> 5, seg = idx & 31;
        cp16(Ws + c*136 + seg*4, g_wop + c*128 + seg*4);
    }
    {
        int rb0 = blockIdx.x * 64;
        #pragma unroll
        for (int i = 0; i < 2; ++i) {
            int idx = t + 512*i;
            int c = idx >> 3, seg = idx & 7;
            cp16(Pu0 + c*72 + 32 + seg*4, g_pb + (size_t)c*(MROWS/2) + (rb0 >> 1) + seg*4);
        }
    }
    cp_commit();
    if (t < 128) { g2s[t] = g2v[t]; b2s[t] = b2v[t]; obs[t] = obias[t]; }

    const int lane = t & 31, w = t >> 5;
    const int wm = w & 3, wn = w >> 2;
    const int tig = lane & 3, grp = lane >> 2;

    int st = 0;
    for (int tile = blockIdx.x; tile < 4096; tile += 152, st ^= 1) {
        unsigned* Pu = st ? Pu1 : Pu0;
        float* Pf = (float*)Pu;
        const int rb = tile * 64;

        cp_wait<0>();          // current tile's P (and, first iter, Ws) ready
        __syncthreads();       // also: all warps done with prior tile

        // prefetch NEXT tile's packed P into the other stage (overlaps LN+GEMM)
        int ntile = tile + 152;
        if (ntile < 4096) {
            unsigned* D = st ? Pu0 : Pu1;
            int rbn = ntile * 64;
            #pragma unroll
            for (int i = 0; i < 2; ++i) {
                int idx = t + 512*i;
                int c = idx >> 3, seg = idx & 7;
                cp16(D + c*72 + 32 + seg*4, g_pb + (size_t)c*(MROWS/2) + (rbn >> 1) + seg*4);
            }
            cp_commit();
        }

        // LN partials over c (8 groups of 16 c's)
        {
            int h = t >> 6, r = t & 63;
            int r2 = r >> 1, hi = r & 1;
            float s = 0.f, s2 = 0.f;
            #pragma unroll
            for (int cc = 0; cc < 16; ++cc) {
                unsigned pk = Pu[(h*16 + cc)*72 + 32 + r2];
                __nv_bfloat162 h2 = *reinterpret_cast<const __nv_bfloat162*>(&pk);
                float v = hi ? __bfloat162float(h2.y) : __bfloat162float(h2.x);
                s += v; s2 += v*v;
            }
            ps1[h*64 + r] = s; ps2[h*64 + r] = s2;
        }
        __syncthreads();
        if (t < 64) {
            float s = 0.f, s2 = 0.f;
            #pragma unroll
            for (int h = 0; h < 8; ++h) { s += ps1[h*64 + t]; s2 += ps2[h*64 + t]; }
            float mu = s * (1.f/128.f);
            float var = s2 * (1.f/128.f) - mu*mu;
            mus[t] = mu; rss[t] = rsqrtf(var + 1e-5f);
        }
        __syncthreads();

        // expand packed bf16 -> tf32 in place (register-staged)
        {
            unsigned pk[8];
            #pragma unroll
            for (int i = 0; i < 8; ++i) {
                int idx = t + 512*i;
                int c = idx >> 5, r2 = idx & 31;
                pk[i] = Pu[c*72 + 32 + r2];
            }
            __syncthreads();
            #pragma unroll
            for (int i = 0; i < 8; ++i) {
                int idx = t + 512*i;
                int c = idx >> 5, r2 = idx & 31, r = r2*2;
                __nv_bfloat162 h2 = *reinterpret_cast<const __nv_bfloat162*>(&pk[i]);
                float vx = __bfloat162float(h2.x), vy = __bfloat162float(h2.y);
                Pu[c*72 + r    ] = f2tf32((vx - mus[r  ]) * rss[r  ] * g2s[c] + b2s[c]);
                Pu[c*72 + r + 1] = f2tf32((vy - mus[r+1]) * rss[r+1] * g2s[c] + b2s[c]);
            }
        }
        __syncthreads();

        // prefetch gate + Z (latency hidden under GEMM)
        float  gpre[4][4];
        float2 zpre[4][2];
        #pragma unroll
        for (int nt = 0; nt < 4; ++nt) {
            int d0 = wn*32 + nt*8 + tig*2;
            int r0 = wm*16 + grp;
            #pragma unroll
            for (int q = 0; q < 4; ++q) {
                int r = r0 + ((q >= 2) ? 8 : 0);
                gpre[nt][q] = __ldg(&g_gate[(size_t)(d0 + (q & 1))*MROWS + rb + r]);
            }
            zpre[nt][0] = *(const float2*)&Z[(size_t)(rb + r0    )*128 + d0];
            zpre[nt][1] = *(const float2*)&Z[(size_t)(rb + r0 + 8)*128 + d0];
        }

        // GEMM: M=64(r), N=128(d), K=128(c)
        float acc[4][4];
        #pragma unroll
        for (int nt = 0; nt < 4; ++nt)
            #pragma unroll
            for (int q = 0; q < 4; ++q) acc[nt][q] = 0.f;

        const int ar = wm*16 + grp;
        #pragma unroll
        for (int k0 = 0; k0 < 128; k0 += 8) {
            unsigned a0 = Pu[(k0+tig  )*72 + ar];
            unsigned a1 = Pu[(k0+tig  )*72 + ar + 8];
            unsigned a2 = Pu[(k0+tig+4)*72 + ar];
            unsigned a3 = Pu[(k0+tig+4)*72 + ar + 8];
            #pragma unroll
            for (int nt = 0; nt < 4; ++nt) {
                int bc = wn*32 + nt*8 + grp;
                unsigned b0 = Ws[(k0+tig)*136 + bc], b1 = Ws[(k0+tig+4)*136 + bc];
                mma_tf32(acc[nt], a0, a1, a2, a3, b0, b1);
            }
        }

        // epilogue: direct gated-residual float2 stores (sector-aligned)
        #pragma unroll
        for (int nt = 0; nt < 4; ++nt) {
            int d0 = wn*32 + nt*8 + tig*2;
            int r0 = wm*16 + grp;
            float ob0 = obs[d0], ob1 = obs[d0 + 1];
            float2 o0, o1;
            o0.x = zpre[nt][0].x + gpre[nt][0] * (acc[nt][0] + ob0);
            o0.y = zpre[nt][0].y + gpre[nt][1] * (acc[nt][1] + ob1);
            o1.x = zpre[nt][1].x + gpre[nt][2] * (acc[nt][2] + ob0);
            o1.y = zpre[nt][1].y + gpre[nt][3] * (acc[nt][3] + ob1);
            *(float2*)&out[(size_t)(rb + r0    )*128 + d0] = o0;
            *(float2*)&out[(size_t)(rb + r0 + 8)*128 + d0] = o1;
        }
        // next iteration's cp_wait + __syncthreads protects buffer reuse
    }
}

// ---------------------------------------------------------------------------
extern "C" void kernel_launch(void* const* d_in, const int* in_sizes, int n_in,
                              void* d_out, int out_size)
{
    const float* Zr   = (const float*)d_in[0];
    const float* mask = (const float*)d_in[1];
    const float* g1   = (const float*)d_in[2];
    const float* b1   = (const float*)d_in[3];
    const float* Wlr  = (const float*)d_in[4];
    const float* blr  = (const float*)d_in[5];
    const float* Wg   = (const float*)d_in[6];
    const float* bg   = (const float*)d_in[7];
    const float* Wog  = (const float*)d_in[8];
    const float* bog  = (const float*)d_in[9];
    const float* g2   = (const float*)d_in[10];
    const float* b2   = (const float*)d_in[11];
    const float* Wop  = (const float*)d_in[12];
    const float* ob   = (const float*)d_in[13];
    float* out = (float*)d_out;

    const size_t sm1 = (size_t)(2*64*136 + 2*64*68 + 256) * 4;                   // ~105.5 KB
    const size_t sm3 = (size_t)(128*136 + 2*128*72 + 16*64 + 3*128 + 2*64) * 4;  // ~149.5 KB
    cudaFuncSetAttribute(proj_kernel,  cudaFuncAttributeMaxDynamicSharedMemorySize, (int)sm1);
    cudaFuncSetAttribute(final_kernel, cudaFuncAttributeMaxDynamicSharedMemorySize, (int)sm3);

    ln1_kernel<<<32768, 256>>>(Zr, g1, b1, Wop);
    proj_kernel<<<300, 512, sm1>>>(mask, Wlr, blr, Wg, bg, Wog, bog);
    einsum_kernel<<<dim3(4, 4, 128), 256>>>();
    final_kernel<<<152, 512, sm3>>>(Zr, g2, b2, ob, out);
}